// round 13
// baseline (speedup 1.0000x reference)
#include <cuda_runtime.h>
#include <cuda_bf16.h>
#include <cstdint>

// ---------------- problem constants ----------------
#define BN     4
#define CCH    288
#define HWSZ   4096
#define SN     (CCH*HWSZ)
#define DD     1152
#define SIXC   1728
#define STOK   1024
#define SSEQ   1026
#define NHEADS 36
#define HFF    4608
#define HF2    9216
#define LNB    144

typedef __nv_bfloat16 bf16;

// ---------------- scratch (static device memory) ----------------
__device__ bf16  g_ss   [BN*SIXC*HWSZ];
__device__ bf16  g_condT[BN*HWSZ*SIXC];
__device__ bf16  g_tok  [BN*SSEQ*DD];
__device__ bf16  g_qkv  [BN*SSEQ*3*DD];
__device__ bf16  g_attn [BN*STOK*DD];
__device__ float g_aproj[BN*STOK*DD];
__device__ float g_x1   [BN*SN];
__device__ bf16  g_t2   [BN*STOK*DD];
__device__ bf16  g_hexp [BN*STOK*HF2];
__device__ bf16  g_hglu [BN*STOK*HFF];
__device__ bf16  g_m    [BN*STOK*DD];
__device__ float g_psum [BN*LNB];
__device__ float g_psumsq[BN*LNB];
__device__ float g_stats[BN*2];
__device__ bf16  g_ssw  [SIXC*SIXC];
__device__ bf16  g_qkvw [3*DD*DD];
__device__ bf16  g_projw[DD*DD];
__device__ bf16  g_invw [HF2*DD];
__device__ bf16  g_pww  [DD*HFF];

__device__ __forceinline__ float siluf(float v) { return v / (1.0f + __expf(-v)); }

__device__ __forceinline__ unsigned pk2(float x, float y) {
    __nv_bfloat162 h = __floats2bfloat162_rn(x, y);
    return *reinterpret_cast<unsigned*>(&h);
}

// ---------------- common async-copy primitives ----------------
__device__ __forceinline__ void cpasync16(unsigned dst, const void* src, bool valid) {
    int sz = valid ? 16 : 0;
    asm volatile("cp.async.cg.shared.global [%0], [%1], 16, %2;" :: "r"(dst), "l"(src), "r"(sz));
}
__device__ __forceinline__ void cp_commit() { asm volatile("cp.async.commit_group;"); }
template<int N> __device__ __forceinline__ void cp_wait() {
    asm volatile("cp.async.wait_group %0;" :: "n"(N));
}

// ---------------- legacy mma.sync primitives (fallback path) ----------------
__device__ __forceinline__ void ldsm4(unsigned r[4], unsigned addr) {
    asm volatile("ldmatrix.sync.aligned.m8n8.x4.shared.b16 {%0,%1,%2,%3}, [%4];"
                 : "=r"(r[0]), "=r"(r[1]), "=r"(r[2]), "=r"(r[3]) : "r"(addr));
}
__device__ __forceinline__ void mma_bf16(float c[4], const unsigned a[4], unsigned b0, unsigned b1) {
    asm volatile(
        "mma.sync.aligned.m16n8k16.row.col.f32.bf16.bf16.f32 "
        "{%0,%1,%2,%3}, {%4,%5,%6,%7}, {%8,%9}, {%0,%1,%2,%3};"
        : "+f"(c[0]), "+f"(c[1]), "+f"(c[2]), "+f"(c[3])
        : "r"(a[0]), "r"(a[1]), "r"(a[2]), "r"(a[3]), "r"(b0), "r"(b1));
}

// ---------------- tcgen05 primitives (sm_103a-only path; call sites guarded) ----
__device__ __forceinline__ uint32_t elect1() {
    uint32_t pred;
    asm volatile("{\n\t.reg .pred p;\n\telect.sync _|p, 0xFFFFFFFF;\n\tselp.b32 %0, 1, 0, p;\n\t}"
                 : "=r"(pred));
    return pred;
}
__device__ __forceinline__ void mbar_init(uint32_t a, uint32_t cnt) {
    asm volatile("mbarrier.init.shared.b64 [%0], %1;" :: "r"(a), "r"(cnt) : "memory");
}
__device__ __forceinline__ void mbar_inval(uint32_t a) {
    asm volatile("mbarrier.inval.shared.b64 [%0];" :: "r"(a) : "memory");
}
__device__ __forceinline__ void mbar_wait(uint32_t a, uint32_t parity) {
    asm volatile(
        "{\n\t.reg .pred P;\n\t"
        "W%=:\n\t"
        "mbarrier.try_wait.parity.acquire.cta.shared::cta.b64 P, [%0], %1, 0x989680;\n\t"
        "@P bra.uni D%=;\n\t"
        "bra.uni W%=;\n\t"
        "D%=:\n\t}"
        :: "r"(a), "r"(parity) : "memory");
}
__device__ __forceinline__ void t5_alloc(uint32_t dst, uint32_t n) {
    asm volatile("tcgen05.alloc.cta_group::1.sync.aligned.shared::cta.b32 [%0], %1;"
                 :: "r"(dst), "r"(n) : "memory");
}
__device__ __forceinline__ void t5_relinquish() {
    asm volatile("tcgen05.relinquish_alloc_permit.cta_group::1.sync.aligned;");
}
__device__ __forceinline__ void t5_dealloc(uint32_t t, uint32_t n) {
    asm volatile("tcgen05.dealloc.cta_group::1.sync.aligned.b32 %0, %1;" :: "r"(t), "r"(n));
}
__device__ __forceinline__ void t5_commit(uint32_t mbar) {
    asm volatile("tcgen05.commit.cta_group::1.mbarrier::arrive::one.shared::cluster.b64 [%0];"
                 :: "r"(mbar) : "memory");
}
__device__ __forceinline__ void t5_fence_after() {
    asm volatile("tcgen05.fence::after_thread_sync;" ::: "memory");
}
__device__ __forceinline__ void t5_waitld() {
    asm volatile("tcgen05.wait::ld.sync.aligned;" ::: "memory");
}
__device__ __forceinline__ void fence_async_shared() {
    asm volatile("fence.proxy.async.shared::cta;" ::: "memory");
}
__device__ __forceinline__ void t5_mma(uint32_t d, uint64_t ad, uint64_t bd,
                                       uint32_t idesc, bool acc) {
    uint32_t en = acc ? 1u : 0u;
    asm volatile(
        "{\n\t.reg .pred p;\n\tsetp.ne.u32 p, %5, 0;\n\t"
        "tcgen05.mma.cta_group::1.kind::f16 [%0], %1, %2, %3, {%4, %4, %4, %4}, p;\n\t}"
        :: "r"(d), "l"(ad), "l"(bd), "r"(idesc), "r"(0u), "r"(en) : "memory");
}
__device__ __forceinline__ void t5_ld32(uint32_t* r, uint32_t taddr) {
    asm volatile(
        "tcgen05.ld.sync.aligned.32x32b.x32.b32 "
        "{%0,%1,%2,%3,%4,%5,%6,%7,%8,%9,%10,%11,%12,%13,%14,%15,"
        "%16,%17,%18,%19,%20,%21,%22,%23,%24,%25,%26,%27,%28,%29,%30,%31}, [%32];"
        : "=r"(r[0]), "=r"(r[1]), "=r"(r[2]), "=r"(r[3]), "=r"(r[4]), "=r"(r[5]),
          "=r"(r[6]), "=r"(r[7]), "=r"(r[8]), "=r"(r[9]), "=r"(r[10]), "=r"(r[11]),
          "=r"(r[12]), "=r"(r[13]), "=r"(r[14]), "=r"(r[15]), "=r"(r[16]), "=r"(r[17]),
          "=r"(r[18]), "=r"(r[19]), "=r"(r[20]), "=r"(r[21]), "=r"(r[22]), "=r"(r[23]),
          "=r"(r[24]), "=r"(r[25]), "=r"(r[26]), "=r"(r[27]), "=r"(r[28]), "=r"(r[29]),
          "=r"(r[30]), "=r"(r[31])
        : "r"(taddr));
}

// idesc kind::f16: dtype=F32, a=BF16 K-major, b=BF16 K-major, N=128, M=128
static constexpr uint32_t T5_IDESC = (1u << 4) | (1u << 7) | (1u << 10) |
                                     ((128u / 8) << 17) | ((128u / 16) << 24);
// SW128 K-major smem descriptor: layout=2, version=1, SBO=64, LBO=1
static constexpr unsigned long long T5_DESC_BASE =
    (2ull << 61) | (1ull << 46) | (64ull << 32) | (1ull << 16);
__device__ __forceinline__ uint64_t make_desc(uint32_t addr) {
    return T5_DESC_BASE | ((uint64_t)(addr >> 4) & 0x3FFFull);
}

#define GSMEM 149504   // tcgen05: ctrl + 3 x 48KB stages; fallback uses 64KB of it

// ---------------- unified bf16 NT GEMM: C[M,N] = A[M,K] * B[N,K]^T ----------------
// grid (N/128, ceil(M/256), z); 256 threads. N%128==0; K%64==0; M guarded.
// BIASMODE: 0 none, 1 bias[row], 2 bias[col]. ACT_SILU on C. OUTBF: bf16 out.
template<int BIASMODE, bool ACT_SILU, bool OUTBF>
__global__ __launch_bounds__(256, 1)
void gemm_nt(const bf16* __restrict__ A, const bf16* __restrict__ B,
             void* __restrict__ Cv, const float* __restrict__ bias,
             int M, int N, int K, long long sA_, long long sB_, long long sC_)
{
    extern __shared__ __align__(16) unsigned char smem[];
    const bf16* Az = A + (long long)blockIdx.z * sA_;
    const bf16* Bz = B + (long long)blockIdx.z * sB_;
    const int tid  = threadIdx.x;
    const int row0 = blockIdx.y * 256;
    const int col0 = blockIdx.x * 128;

#if defined(__CUDA_ARCH__) && defined(__CUDA_ARCH_FEAT_SM103_ALL)
    // ====== tcgen05: 256x128 split-M tile, 3x48KB stages, re-phased pipeline ======
    const unsigned u    = (unsigned)__cvta_generic_to_shared(smem);
    const unsigned ctrl = u;                           // [0]=tmem ptr; mbars +16,+24,+32
    const unsigned stg  = (u + 2047u) & ~1023u;
    const int warp = tid >> 5, lane = tid & 31;
    const unsigned STG = 49152u;                       // A 32KB + B 16KB

    if (warp == 0) { t5_alloc(ctrl, 256); t5_relinquish(); }
    if (tid == 0) { mbar_init(ctrl + 16, 1); mbar_init(ctrl + 24, 1); mbar_init(ctrl + 32, 1); }
    __syncthreads();
    uint32_t tmem;
    asm volatile("ld.shared.b32 %0, [%1];" : "=r"(tmem) : "r"(ctrl));

    const int nk = K >> 6;

    auto copyStage = [&](int it) {
        int st = it % 3;
        int k0 = it << 6;
        unsigned sA = stg + (unsigned)st * STG;
        unsigned sB = sA + 32768u;
        int c = tid & 7, rb = tid >> 3;
#pragma unroll
        for (int i = 0; i < 8; i++) {                  // A: 256 rows x 128B
            int r = i * 32 + rb;
            unsigned sw = (unsigned)((c ^ (r & 7)) << 4);
            cpasync16(sA + (unsigned)r * 128u + sw,
                      Az + (long long)(row0 + r) * K + k0 + c * 8, row0 + r < M);
        }
#pragma unroll
        for (int i = 0; i < 4; i++) {                  // B: 128 rows x 128B
            int r = i * 32 + rb;
            unsigned sw = (unsigned)((c ^ (r & 7)) << 4);
            cpasync16(sB + (unsigned)r * 128u + sw,
                      Bz + (long long)(col0 + r) * K + k0 + c * 8, true);
        }
    };

    // prologue: exactly 2 committed groups (tiles 0, 1)
    copyStage(0); cp_commit();
    if (nk > 1) copyStage(1);
    cp_commit();

    for (int it = 0; it < nk; it++) {
        int st = it % 3;
        cp_wait<1>();                  // outstanding = {it, it+1}; completes tile it
        fence_async_shared();
        __syncthreads();

        if (tid < 32 && elect1()) {
            t5_fence_after();
            unsigned sA = stg + (unsigned)st * STG;
            uint64_t ad0 = make_desc(sA);
            uint64_t ad1 = make_desc(sA + 16384u);     // rows 128..255
            uint64_t bd  = make_desc(sA + 32768u);
#pragma unroll
            for (int sub = 0; sub < 4; sub++) {
                t5_mma(tmem,        ad0 + 2 * sub, bd + 2 * sub, T5_IDESC, (it | sub) != 0);
                t5_mma(tmem + 128u, ad1 + 2 * sub, bd + 2 * sub, T5_IDESC, (it | sub) != 0);
            }
            t5_commit(ctrl + 16 + st * 8);
        }
        // copy tile it+2 into stage (it+2)%3 == (it-1)%3; for it>=1 that stage was
        // read by MMA(it-1) -> gate on its commit (one full iteration old).
        if (it + 2 < nk) {
            if (it >= 1) {
                int prev = it - 1;
                mbar_wait(ctrl + 16 + (prev % 3) * 8, (uint32_t)((prev / 3) & 1));
            }
            copyStage(it + 2);
        }
        cp_commit();                   // unconditional: keeps group accounting exact
    }
    {   // drain: MMAs complete in-order; last stage's commit suffices
        int lastst = (nk - 1) % 3;
        mbar_wait(ctrl + 16 + lastst * 8, (uint32_t)(((nk - 1) / 3) & 1));
    }
    t5_fence_after();
    cp_wait<0>();
    __syncthreads();

    // epilogue: two 128-row halves through one padded smem buffer
    float* tb = (float*)(smem + (stg - u));            // [128][129]
#pragma unroll
    for (int half = 0; half < 2; half++) {
        if (warp < 4) {
            int rloc = warp * 32 + lane;
            int grow = row0 + half * 128 + rloc;
            float bm = (BIASMODE == 1 && grow < M) ? bias[grow] : 0.f;
#pragma unroll
            for (int g = 0; g < 4; g++) {
                uint32_t d[32];
                t5_ld32(d, tmem + (unsigned)(half * 128 + g * 32));
                t5_waitld();
#pragma unroll
                for (int c2 = 0; c2 < 32; c2++) {
                    float v = __uint_as_float(d[c2]);
                    if (BIASMODE == 1) v += bm;
                    if (BIASMODE == 2) v += bias[col0 + g * 32 + c2];
                    if (ACT_SILU) v = siluf(v);
                    tb[rloc * 129 + g * 32 + c2] = v;
                }
            }
        }
        __syncthreads();
        {
            int colx = tid & 127;
            int hq = tid >> 7;
            for (int rr = hq * 64; rr < hq * 64 + 64; rr++) {
                int r = row0 + half * 128 + rr;
                if (r >= M) break;
                float v = tb[rr * 129 + colx];
                if (OUTBF) {
                    bf16* Cz = (bf16*)Cv + (long long)blockIdx.z * sC_;
                    Cz[(long long)r * N + col0 + colx] = __float2bfloat16(v);
                } else {
                    float* Cz = (float*)Cv + (long long)blockIdx.z * sC_;
                    Cz[(long long)r * N + col0 + colx] = v;
                }
            }
        }
        __syncthreads();
    }
    if (tid == 0) { mbar_inval(ctrl + 16); mbar_inval(ctrl + 24); mbar_inval(ctrl + 32); }
    __syncthreads();
    if (warp == 0) t5_dealloc(tmem, 256);

#else
    // ============ legacy mma.sync fallback: two 128-row halves per CTA ============
    const unsigned sbase = (unsigned)__cvta_generic_to_shared(smem);
    const int lane = tid & 31;
    const int warp = tid >> 5;
    const int wm   = (warp & 3) * 32;
    const int wn   = (warp >> 2) * 64;
    const int nk = K / 32;
    const unsigned STG = 16384u;

    for (int sub2 = 0; sub2 < 2; sub2++) {
        const int r0 = row0 + sub2 * 128;
        if (r0 >= M) break;

        float acc[2][8][4];
#pragma unroll
        for (int i = 0; i < 2; i++)
#pragma unroll
            for (int j = 0; j < 8; j++)
#pragma unroll
                for (int r = 0; r < 4; r++) acc[i][j][r] = 0.f;

        auto copyStage = [&](int kt, int st) {
            int k0 = kt * 32;
            unsigned sA = sbase + (unsigned)st * STG;
            unsigned sB = sA + 8192u;
#pragma unroll
            for (int i = 0; i < 2; i++) {
                int f = tid + (i << 8);
                int row = f >> 2, ch = f & 3;
                unsigned dst = sA + row * 64u + (unsigned)((ch ^ ((row >> 1) & 3)) << 4);
                cpasync16(dst, Az + (long long)(r0 + row) * K + k0 + ch * 8, r0 + row < M);
            }
#pragma unroll
            for (int i = 0; i < 2; i++) {
                int f = tid + (i << 8);
                int n = f >> 2, ch = f & 3;
                unsigned dst = sB + n * 64u + (unsigned)((ch ^ ((n >> 1) & 3)) << 4);
                cpasync16(dst, Bz + (long long)(col0 + n) * K + k0 + ch * 8, true);
            }
        };

        copyStage(0, 0); cp_commit();
        if (nk > 1) copyStage(1, 1);
        cp_commit();
        if (nk > 2) copyStage(2, 2);
        cp_commit();

        for (int kt = 0; kt < nk; kt++) {
            cp_wait<2>();
            __syncthreads();

            int st = kt & 3;
            unsigned sA = sbase + (unsigned)st * STG;
            unsigned sB = sA + 8192u;

#pragma unroll
            for (int kk = 0; kk < 32; kk += 16) {
                unsigned a_fr[2][4];
#pragma unroll
                for (int i = 0; i < 2; i++) {
                    int row = wm + 16 * i + (lane & 15);
                    int ch  = (kk >> 3) + (lane >> 4);
                    ldsm4(a_fr[i], sA + row * 64u + (unsigned)((ch ^ ((row >> 1) & 3)) << 4));
                }
                unsigned b_fr[4][4];
#pragma unroll
                for (int j = 0; j < 4; j++) {
                    int row = wn + 16 * j + ((lane >> 4) << 3) + (lane & 7);
                    int ch  = (kk >> 3) + ((lane >> 3) & 1);
                    ldsm4(b_fr[j], sB + row * 64u + (unsigned)((ch ^ ((row >> 1) & 3)) << 4));
                }
#pragma unroll
                for (int i = 0; i < 2; i++)
#pragma unroll
                    for (int j = 0; j < 4; j++) {
                        mma_bf16(acc[i][2 * j],     a_fr[i], b_fr[j][0], b_fr[j][1]);
                        mma_bf16(acc[i][2 * j + 1], a_fr[i], b_fr[j][2], b_fr[j][3]);
                    }
            }

            if (kt + 3 < nk) copyStage(kt + 3, (kt + 3) & 3);
            cp_commit();
        }
        __syncthreads();

        const int gid = lane >> 2, tig = lane & 3;
#pragma unroll
        for (int i = 0; i < 2; i++) {
#pragma unroll
            for (int rr = 0; rr < 2; rr++) {
                int r = r0 + wm + i * 16 + gid + rr * 8;
                if (r >= M) continue;
                float bm = (BIASMODE == 1) ? bias[r] : 0.f;
#pragma unroll
                for (int j = 0; j < 8; j++) {
                    int cc = col0 + wn + j * 8 + 2 * tig;
                    float x0 = acc[i][j][2 * rr + 0];
                    float x1 = acc[i][j][2 * rr + 1];
                    if (BIASMODE == 1) { x0 += bm; x1 += bm; }
                    if (BIASMODE == 2) { x0 += bias[cc]; x1 += bias[cc + 1]; }
                    if (ACT_SILU) { x0 = siluf(x0); x1 = siluf(x1); }
                    if (OUTBF) {
                        bf16* Cz = (bf16*)Cv + (long long)blockIdx.z * sC_;
                        unsigned p = pk2(x0, x1);
                        *(unsigned*)(Cz + (long long)r * N + cc) = p;
                    } else {
                        float* Cz = (float*)Cv + (long long)blockIdx.z * sC_;
                        *(float2*)(Cz + (long long)r * N + cc) = make_float2(x0, x1);
                    }
                }
            }
        }
    }
#endif
}

// ---------------- weight conversion (vectorized) ----------------
__global__ void convw4_k(const float* __restrict__ src, bf16* __restrict__ dst, long long n4)
{
    long long i = (long long)blockIdx.x * blockDim.x + threadIdx.x;
    long long stride = (long long)gridDim.x * blockDim.x;
    for (; i < n4; i += stride) {
        float4 v = ((const float4*)src)[i];
        uint2 o;
        o.x = pk2(v.x, v.y);
        o.y = pk2(v.z, v.w);
        ((uint2*)dst)[i] = o;
    }
}

// ---------------- silu + transpose ----------------
__global__ void tsil_k(const float* __restrict__ cond, bf16* __restrict__ condT)
{
    __shared__ float t[32][33];
    int b = blockIdx.z;
    int c0 = blockIdx.x * 32, h0 = blockIdx.y * 32;
#pragma unroll
    for (int i = 0; i < 4; i++) {
        int c = c0 + threadIdx.y + i * 8;
        t[threadIdx.y + i * 8][threadIdx.x] =
            cond[((long long)b * SIXC + c) * HWSZ + h0 + threadIdx.x];
    }
    __syncthreads();
#pragma unroll
    for (int i = 0; i < 4; i++) {
        int h = h0 + threadIdx.y + i * 8;
        condT[((long long)b * HWSZ + h) * SIXC + c0 + threadIdx.x] =
            __float2bfloat16(siluf(t[threadIdx.x][threadIdx.y + i * 8]));
    }
}

// ---------------- LayerNorm partial ----------------
__global__ void ln_partial_k(const float* __restrict__ x,
                             float* __restrict__ psum, float* __restrict__ psumsq)
{
    int b = blockIdx.y;
    const float* xb = x + (long long)b * SN;
    const int chunk = SN / LNB;
    int base = blockIdx.x * chunk;
    float s = 0.f, sq = 0.f;
    for (int i = base + threadIdx.x; i < base + chunk; i += 256) {
        float v = xb[i]; s += v; sq += v * v;
    }
    __shared__ float sh1[256], sh2[256];
    sh1[threadIdx.x] = s; sh2[threadIdx.x] = sq;
    __syncthreads();
    for (int o = 128; o > 0; o >>= 1) {
        if (threadIdx.x < o) {
            sh1[threadIdx.x] += sh1[threadIdx.x + o];
            sh2[threadIdx.x] += sh2[threadIdx.x + o];
        }
        __syncthreads();
    }
    if (threadIdx.x == 0) {
        psum[b * LNB + blockIdx.x] = sh1[0];
        psumsq[b * LNB + blockIdx.x] = sh2[0];
    }
}

__global__ void ln_final_k(const float* __restrict__ psum, const float* __restrict__ psumsq,
                           float* __restrict__ stats)
{
    int b = blockIdx.x;
    float s = 0.f, sq = 0.f;
    for (int i = threadIdx.x; i < LNB; i += 256) { s += psum[b * LNB + i]; sq += psumsq[b * LNB + i]; }
    __shared__ float sh1[256], sh2[256];
    sh1[threadIdx.x] = s; sh2[threadIdx.x] = sq;
    __syncthreads();
    for (int o = 128; o > 0; o >>= 1) {
        if (threadIdx.x < o) {
            sh1[threadIdx.x] += sh1[threadIdx.x + o];
            sh2[threadIdx.x] += sh2[threadIdx.x + o];
        }
        __syncthreads();
    }
    if (threadIdx.x == 0) {
        float mu = sh1[0] / (float)SN;
        float var = sh2[0] / (float)SN - mu * mu;
        stats[b * 2 + 0] = mu;
        stats[b * 2 + 1] = rsqrtf(var + 1e-6f);
    }
}

// ---------------- token init ----------------
__global__ void tokinit_k(const float* __restrict__ gt, const float* __restrict__ tt,
                          bf16* __restrict__ tok)
{
    int gid = blockIdx.x * blockDim.x + threadIdx.x;
    if (gid >= BN * DD) return;
    int b = gid / DD, j = gid % DD;
    tok[((long long)b * SSEQ + 0) * DD + j] = __float2bfloat16(gt[b * DD + j]);
    tok[((long long)b * SSEQ + 1) * DD + j] = __float2bfloat16(tt[b * DD + j]);
}

// ---------------- MSA modulate + segment ----------------
__global__ void msa_seg_k(const float* __restrict__ x, const bf16* __restrict__ ss,
                          const float* __restrict__ stats, bf16* __restrict__ tok)
{
    long long gid = (long long)blockIdx.x * blockDim.x + threadIdx.x;
    if (gid >= (long long)BN * STOK * DD) return;
    int j = (int)(gid % DD);
    int t = (int)((gid / DD) % STOK);
    int b = (int)(gid / ((long long)STOK * DD));
    int c = j >> 2, p1 = (j >> 1) & 1, p2 = j & 1;
    int n1 = t >> 5, n2 = t & 31;
    int hw = ((2 * n1 + p1) << 6) + 2 * n2 + p2;
    float mu = stats[b * 2], rsig = stats[b * 2 + 1];
    float xv = x[((long long)b * CCH + c) * HWSZ + hw];
    float sc = __bfloat162float(ss[((long long)b * SIXC + 288 + c) * HWSZ + hw]);
    float sh = __bfloat162float(ss[((long long)b * SIXC + c) * HWSZ + hw]);
    tok[((long long)b * SSEQ + 2 + t) * DD + j] =
        __float2bfloat16((xv - mu) * rsig * (1.f + sc) + sh);
}

// ---------------- linear attention (bf16 qkv) ----------------
__global__ void attn_k(const bf16* __restrict__ qkv, bf16* __restrict__ attn)
{
    int h = blockIdx.x, b = blockIdx.y;
    int tid = threadIdx.x;
    __shared__ float vk[33 * 32];
    __shared__ float ks[8][32];
    __shared__ float vs[8][33];
    float acc[5] = {0.f, 0.f, 0.f, 0.f, 0.f};
    const bf16* qkvb = qkv + (long long)b * SSEQ * (3 * DD);

    for (int s0 = 0; s0 < SSEQ; s0 += 8) {
        {
            int si = tid >> 5, d = tid & 31;
            int s = s0 + si;
            ks[si][d] = (s < SSEQ)
                ? fmaxf(__bfloat162float(qkvb[(long long)s * (3 * DD) + DD + h * 32 + d]), 0.f) : 0.f;
        }
        for (int idx = tid; idx < 8 * 33; idx += 256) {
            int si = idx / 33, e = idx % 33;
            int s = s0 + si;
            float vv = 0.f;
            if (s < SSEQ)
                vv = (e < 32) ? __bfloat162float(qkvb[(long long)s * (3 * DD) + 2 * DD + h * 32 + e]) : 1.f;
            vs[si][e] = vv;
        }
        __syncthreads();
#pragma unroll
        for (int si = 0; si < 8; si++) {
#pragma unroll
            for (int r = 0; r < 5; r++) {
                int f = tid + (r << 8);
                if (f < 1056) acc[r] += vs[si][f >> 5] * ks[si][f & 31];
            }
        }
        __syncthreads();
    }
#pragma unroll
    for (int r = 0; r < 5; r++) {
        int f = tid + (r << 8);
        if (f < 1056) vk[f] = acc[r];
    }
    __syncthreads();

    for (int s = tid; s < SSEQ; s += 256) {
        float q[32];
        const __nv_bfloat162* qp2 = reinterpret_cast<const __nv_bfloat162*>(
            qkvb + (long long)s * (3 * DD) + h * 32);
#pragma unroll
        for (int d2 = 0; d2 < 16; d2++) {
            float2 f = __bfloat1622float2(qp2[d2]);
            q[2 * d2]     = fmaxf(f.x, 0.f);
            q[2 * d2 + 1] = fmaxf(f.y, 0.f);
        }
        float den = 0.f;
#pragma unroll
        for (int d = 0; d < 32; d++) den += vk[32 * 32 + d] * q[d];
        float inv = 1.0f / (den + 1e-8f);
        if (s >= 2) {
            bf16* op = attn + ((long long)(b * STOK + s - 2)) * DD + h * 32;
            for (int e = 0; e < 32; e++) {
                float num = 0.f;
#pragma unroll
                for (int d = 0; d < 32; d++) num += vk[e * 32 + d] * q[d];
                op[e] = __float2bfloat16(num * inv);
            }
        }
    }
}

// ---------------- fused: x1 = x + comb(a)*g_msa, + LN partials ----------
__global__ void comb1_ln_k(const float* __restrict__ x, const float* __restrict__ a,
                           const bf16* __restrict__ ss, float* __restrict__ x1,
                           float* __restrict__ psum, float* __restrict__ psumsq)
{
    int b = blockIdx.y;
    const int chunk = SN / LNB;
    int base = blockIdx.x * chunk;
    float s = 0.f, sq = 0.f;
    for (int i = threadIdx.x; i < chunk; i += 256) {
        int loc = base + i;
        int hw = loc & (HWSZ - 1);
        int c  = loc >> 12;
        int hh = hw >> 6, ww = hw & 63;
        int t = ((hh >> 1) << 5) + (ww >> 1);
        int j = (c << 2) + ((hh & 1) << 1) + (ww & 1);
        float g = __bfloat162float(ss[((long long)b * SIXC + 576 + c) * HWSZ + hw]);
        long long gid = (long long)b * SN + loc;
        float v = x[gid] + a[((long long)(b * STOK + t)) * DD + j] * g;
        x1[gid] = v;
        s += v; sq += v * v;
    }
    __shared__ float sh1[256], sh2[256];
    sh1[threadIdx.x] = s; sh2[threadIdx.x] = sq;
    __syncthreads();
    for (int o = 128; o > 0; o >>= 1) {
        if (threadIdx.x < o) {
            sh1[threadIdx.x] += sh1[threadIdx.x + o];
            sh2[threadIdx.x] += sh2[threadIdx.x + o];
        }
        __syncthreads();
    }
    if (threadIdx.x == 0) {
        psum[b * LNB + blockIdx.x] = sh1[0];
        psumsq[b * LNB + blockIdx.x] = sh2[0];
    }
}

// ---------------- MLP modulate + segment ----------------
__global__ void mlp_seg_k(const float* __restrict__ x1, const bf16* __restrict__ ss,
                          const float* __restrict__ stats, bf16* __restrict__ t2)
{
    long long gid = (long long)blockIdx.x * blockDim.x + threadIdx.x;
    if (gid >= (long long)BN * STOK * DD) return;
    int j = (int)(gid % DD);
    int t = (int)((gid / DD) % STOK);
    int b = (int)(gid / ((long long)STOK * DD));
    int c = j >> 2, p1 = (j >> 1) & 1, p2 = j & 1;
    int n1 = t >> 5, n2 = t & 31;
    int hw = ((2 * n1 + p1) << 6) + 2 * n2 + p2;
    float mu = stats[b * 2], rsig = stats[b * 2 + 1];
    float xv = x1[((long long)b * CCH + c) * HWSZ + hw];
    float sc = __bfloat162float(ss[((long long)b * SIXC + 1152 + c) * HWSZ + hw]);
    float sh = __bfloat162float(ss[((long long)b * SIXC + 864 + c) * HWSZ + hw]);
    t2[gid] = __float2bfloat16((xv - mu) * rsig * (1.f + sc) + sh);
}

// ---------------- tiled depthwise 3x3 + GLU ----------------
#define DW_CH 64
__global__ __launch_bounds__(256)
void dwglu_t_k(const bf16* __restrict__ hexp, const float* __restrict__ dw_w,
               const float* __restrict__ dw_b, bf16* __restrict__ hglu)
{
    __shared__ bf16 sm[6][32][2 * DW_CH];
    const int cb = blockIdx.x * DW_CH;
    const int y0 = blockIdx.y * 4;
    const int b  = blockIdx.z;
    const bf16* base = hexp + (long long)b * STOK * HF2;

    for (int idx = threadIdx.x; idx < 6 * 32 * 2; idx += 256) {
        int grp = idx & 1;
        int xx  = (idx >> 1) & 31;
        int yr  = idx >> 6;
        int y   = y0 - 1 + yr;
        uint4* dst = (uint4*)&sm[yr][xx][grp * DW_CH];
        if ((unsigned)y < 32u) {
            const uint4* src = (const uint4*)(base + (long long)((y << 5) + xx) * HF2
                                              + cb + grp * HFF);
#pragma unroll
            for (int q = 0; q < 8; q++) dst[q] = src[q];
        } else {
#pragma unroll
            for (int q = 0; q < 8; q++) dst[q] = make_uint4(0, 0, 0, 0);
        }
    }
    __syncthreads();

    const int chp = threadIdx.x & 31;
    const int ch  = chp * 2;
    float2 wa[9], wg[9];
#pragma unroll
    for (int i = 0; i < 9; i++) {
        wa[i] = make_float2(dw_w[(cb + ch) * 9 + i],      dw_w[(cb + ch + 1) * 9 + i]);
        wg[i] = make_float2(dw_w[(cb + ch + HFF) * 9 + i], dw_w[(cb + ch + 1 + HFF) * 9 + i]);
    }
    float2 ba = make_float2(dw_b[cb + ch], dw_b[cb + ch + 1]);
    float2 bg = make_float2(dw_b[cb + ch + HFF], dw_b[cb + ch + 1 + HFF]);

    for (int pos = threadIdx.x >> 5; pos < 128; pos += 8) {
        int xx = pos & 31, yo = pos >> 5;
        float2 va = ba, vg = bg;
#pragma unroll
        for (int ky = 0; ky < 3; ky++) {
            int yr = yo + ky;
#pragma unroll
            for (int kx = -1; kx <= 1; kx++) {
                int xc = xx + kx;
                if ((unsigned)xc >= 32u) continue;
                int wi = ky * 3 + (kx + 1);
                float2 av = __bfloat1622float2(*(const __nv_bfloat162*)&sm[yr][xc][ch]);
                float2 gv = __bfloat1622float2(*(const __nv_bfloat162*)&sm[yr][xc][ch + DW_CH]);
                va.x += wa[wi].x * av.x; va.y += wa[wi].y * av.y;
                vg.x += wg[wi].x * gv.x; vg.y += wg[wi].y * gv.y;
            }
        }
        int n = ((y0 + yo) << 5) + xx;
        float o0 = va.x * siluf(vg.x);
        float o1 = va.y * siluf(vg.y);
        *(unsigned*)&hglu[((long long)(b * STOK + n)) * HFF + cb + ch] = pk2(o0, o1);
    }
}

// ---------------- comb(m)*g_mlp + residual -> out (m bf16) ----------------
__global__ void comb2_k(const float* __restrict__ x1, const bf16* __restrict__ m,
                        const bf16* __restrict__ ss, float* __restrict__ out)
{
    long long gid = (long long)blockIdx.x * blockDim.x + threadIdx.x;
    if (gid >= (long long)BN * SN) return;
    int hw = (int)(gid % HWSZ);
    int c = (int)((gid / HWSZ) % CCH);
    int b = (int)(gid / SN);
    int hh = hw >> 6, ww = hw & 63;
    int t = ((hh >> 1) << 5) + (ww >> 1);
    int j = (c << 2) + ((hh & 1) << 1) + (ww & 1);
    float g = __bfloat162float(ss[((long long)b * SIXC + 1440 + c) * HWSZ + hw]);
    out[gid] = x1[gid] + __bfloat162float(m[((long long)(b * STOK + t)) * DD + j]) * g;
}

// ---------------- launch ----------------
extern "C" void kernel_launch(void* const* d_in, const int* in_sizes, int n_in,
                              void* d_out, int out_size)
{
    const float* x      = (const float*)d_in[0];
    const float* cond   = (const float*)d_in[1];
    const float* gtok   = (const float*)d_in[2];
    const float* ttok   = (const float*)d_in[3];
    const float* ss_w   = (const float*)d_in[4];
    const float* ss_b   = (const float*)d_in[5];
    const float* qkv_w  = (const float*)d_in[6];
    const float* proj_w = (const float*)d_in[7];
    const float* proj_b = (const float*)d_in[8];
    const float* inv_w  = (const float*)d_in[9];
    const float* inv_b  = (const float*)d_in[10];
    const float* dw_w   = (const float*)d_in[11];
    const float* dw_b   = (const float*)d_in[12];
    const float* pw_w   = (const float*)d_in[13];
    float* out = (float*)d_out;

    float *p_aproj, *p_x1, *p_psum, *p_psumsq, *p_stats;
    bf16 *p_ss, *p_condT, *p_tok, *p_qkv, *p_attn, *p_t2, *p_hexp, *p_hglu, *p_m;
    bf16 *p_ssw, *p_qkvw, *p_projw, *p_invw, *p_pww;
    cudaGetSymbolAddress((void**)&p_ss, g_ss);
    cudaGetSymbolAddress((void**)&p_condT, g_condT);
    cudaGetSymbolAddress((void**)&p_tok, g_tok);
    cudaGetSymbolAddress((void**)&p_qkv, g_qkv);
    cudaGetSymbolAddress((void**)&p_attn, g_attn);
    cudaGetSymbolAddress((void**)&p_aproj, g_aproj);
    cudaGetSymbolAddress((void**)&p_x1, g_x1);
    cudaGetSymbolAddress((void**)&p_t2, g_t2);
    cudaGetSymbolAddress((void**)&p_hexp, g_hexp);
    cudaGetSymbolAddress((void**)&p_hglu, g_hglu);
    cudaGetSymbolAddress((void**)&p_m, g_m);
    cudaGetSymbolAddress((void**)&p_psum, g_psum);
    cudaGetSymbolAddress((void**)&p_psumsq, g_psumsq);
    cudaGetSymbolAddress((void**)&p_stats, g_stats);
    cudaGetSymbolAddress((void**)&p_ssw, g_ssw);
    cudaGetSymbolAddress((void**)&p_qkvw, g_qkvw);
    cudaGetSymbolAddress((void**)&p_projw, g_projw);
    cudaGetSymbolAddress((void**)&p_invw, g_invw);
    cudaGetSymbolAddress((void**)&p_pww, g_pww);

    cudaFuncSetAttribute(gemm_nt<1, false, true>,  cudaFuncAttributeMaxDynamicSharedMemorySize, GSMEM);
    cudaFuncSetAttribute(gemm_nt<0, false, true>,  cudaFuncAttributeMaxDynamicSharedMemorySize, GSMEM);
    cudaFuncSetAttribute(gemm_nt<2, false, false>, cudaFuncAttributeMaxDynamicSharedMemorySize, GSMEM);
    cudaFuncSetAttribute(gemm_nt<2, true, true>,   cudaFuncAttributeMaxDynamicSharedMemorySize, GSMEM);

    // 0) weight conversion + cond silu-transpose
    convw4_k<<<1024, 256>>>(ss_w, p_ssw, (long long)SIXC * SIXC / 4);
    convw4_k<<<1024, 256>>>(qkv_w, p_qkvw, (long long)3 * DD * DD / 4);
    convw4_k<<<1024, 256>>>(proj_w, p_projw, (long long)DD * DD / 4);
    convw4_k<<<2048, 256>>>(inv_w, p_invw, (long long)HF2 * DD / 4);
    convw4_k<<<1024, 256>>>(pw_w, p_pww, (long long)DD * HFF / 4);
    tsil_k<<<dim3(SIXC / 32, HWSZ / 32, BN), dim3(32, 8)>>>(cond, p_condT);

    // 1) scale_shift (bf16 out): M=1728 -> 7 row tiles of 256
    gemm_nt<1, false, true><<<dim3(HWSZ / 128, 7, BN), 256, GSMEM>>>(
        p_ssw, p_condT, p_ss, ss_b, SIXC, HWSZ, SIXC,
        0LL, (long long)HWSZ * SIXC, (long long)SIXC * HWSZ);

    // 2) LayerNorm(x)
    ln_partial_k<<<dim3(LNB, BN), 256>>>(x, p_psum, p_psumsq);
    ln_final_k<<<BN, 256>>>(p_psum, p_psumsq, p_stats);

    // 3) tokens (bf16)
    tokinit_k<<<(BN * DD + 255) / 256, 256>>>(gtok, ttok, p_tok);
    msa_seg_k<<<(int)(((long long)BN * STOK * DD + 255) / 256), 256>>>(x, p_ss, p_stats, p_tok);

    // 4) qkv (bf16 out): M=4104 -> 17 row tiles of 256
    gemm_nt<0, false, true><<<dim3((3 * DD) / 128, 17, 1), 256, GSMEM>>>(
        p_tok, p_qkvw, p_qkv, nullptr, BN * SSEQ, 3 * DD, DD, 0LL, 0LL, 0LL);

    // 5) linear attention (bf16 in/out)
    attn_k<<<dim3(NHEADS, BN), 256>>>(p_qkv, p_attn);

    // 6) proj (fp32 out): M=4096 -> 16 row tiles
    gemm_nt<2, false, false><<<dim3(DD / 128, 16, 1), 256, GSMEM>>>(
        p_attn, p_projw, p_aproj, proj_b, BN * STOK, DD, DD, 0LL, 0LL, 0LL);

    // 7+8a) x1 = x + comb(a)*g_msa, fused with LN(x1) partials
    comb1_ln_k<<<dim3(LNB, BN), 256>>>(x, p_aproj, p_ss, p_x1, p_psum, p_psumsq);

    // 8b) LN(x1) finalize
    ln_final_k<<<BN, 256>>>(p_psum, p_psumsq, p_stats);

    // 9) MLP modulate+segment (token-major bf16)
    mlp_seg_k<<<(int)(((long long)BN * STOK * DD + 255) / 256), 256>>>(p_x1, p_ss, p_stats, p_t2);

    // 10) expand (bf16 out): M=1024 -> 4 row tiles per batch
    gemm_nt<2, true, true><<<dim3(HF2 / 128, STOK / 256, BN), 256, GSMEM>>>(
        p_t2, p_invw, p_hexp, inv_b, STOK, HF2, DD,
        (long long)STOK * DD, 0LL, (long long)STOK * HF2);

    // 11) tiled depthwise 3x3 + GLU
    dwglu_t_k<<<dim3(HFF / DW_CH, 8, BN), 256>>>(p_hexp, dw_w, dw_b, p_hglu);

    // 12) project (bf16 out): M=1024 -> 4 row tiles per batch
    gemm_nt<0, false, true><<<dim3(DD / 128, STOK / 256, BN), 256, GSMEM>>>(
        p_hglu, p_pww, p_m, nullptr, STOK, DD, HFF,
        (long long)STOK * HFF, 0LL, (long long)STOK * DD);

    // 13) out = x1 + comb(m)*g_mlp
    comb2_k<<<(int)(((long long)BN * SN + 255) / 256), 256>>>(p_x1, p_m, p_ss, out);
}

// round 14
// speedup vs baseline: 1.1200x; 1.1200x over previous
#include <cuda_runtime.h>
#include <cuda_bf16.h>
#include <cstdint>

// ---------------- problem constants ----------------
#define BN     4
#define CCH    288
#define HWSZ   4096
#define SN     (CCH*HWSZ)
#define DD     1152
#define SIXC   1728
#define STOK   1024
#define SSEQ   1026
#define NHEADS 36
#define HFF    4608
#define HF2    9216
#define LNB    144
#define LNB2   256     // comb1_ln partial count per batch

typedef __nv_bfloat16 bf16;

// ---------------- scratch (static device memory) ----------------
__device__ bf16  g_ss   [BN*SIXC*HWSZ];
__device__ bf16  g_condT[BN*HWSZ*SIXC];
__device__ bf16  g_tok  [BN*SSEQ*DD];
__device__ bf16  g_qkv  [BN*SSEQ*3*DD];
__device__ bf16  g_attn [BN*STOK*DD];
__device__ float g_aproj[BN*STOK*DD];
__device__ float g_x1   [BN*SN];
__device__ bf16  g_t2   [BN*STOK*DD];
__device__ bf16  g_hexp [BN*STOK*HF2];
__device__ bf16  g_hglu [BN*STOK*HFF];
__device__ bf16  g_m    [BN*STOK*DD];
__device__ float g_psum [BN*LNB2];
__device__ float g_psumsq[BN*LNB2];
__device__ float g_stats[BN*2];
__device__ bf16  g_ssw  [SIXC*SIXC];
__device__ bf16  g_qkvw [3*DD*DD];
__device__ bf16  g_projw[DD*DD];
__device__ bf16  g_invw [HF2*DD];
__device__ bf16  g_pww  [DD*HFF];

__device__ __forceinline__ float siluf(float v) { return v / (1.0f + __expf(-v)); }

__device__ __forceinline__ unsigned pk2(float x, float y) {
    __nv_bfloat162 h = __floats2bfloat162_rn(x, y);
    return *reinterpret_cast<unsigned*>(&h);
}

// ---------------- common async-copy primitives ----------------
__device__ __forceinline__ void cpasync16(unsigned dst, const void* src, bool valid) {
    int sz = valid ? 16 : 0;
    asm volatile("cp.async.cg.shared.global [%0], [%1], 16, %2;" :: "r"(dst), "l"(src), "r"(sz));
}
__device__ __forceinline__ void cp_commit() { asm volatile("cp.async.commit_group;"); }
template<int N> __device__ __forceinline__ void cp_wait() {
    asm volatile("cp.async.wait_group %0;" :: "n"(N));
}

// ---------------- legacy mma.sync primitives (fallback path) ----------------
__device__ __forceinline__ void ldsm4(unsigned r[4], unsigned addr) {
    asm volatile("ldmatrix.sync.aligned.m8n8.x4.shared.b16 {%0,%1,%2,%3}, [%4];"
                 : "=r"(r[0]), "=r"(r[1]), "=r"(r[2]), "=r"(r[3]) : "r"(addr));
}
__device__ __forceinline__ void mma_bf16(float c[4], const unsigned a[4], unsigned b0, unsigned b1) {
    asm volatile(
        "mma.sync.aligned.m16n8k16.row.col.f32.bf16.bf16.f32 "
        "{%0,%1,%2,%3}, {%4,%5,%6,%7}, {%8,%9}, {%0,%1,%2,%3};"
        : "+f"(c[0]), "+f"(c[1]), "+f"(c[2]), "+f"(c[3])
        : "r"(a[0]), "r"(a[1]), "r"(a[2]), "r"(a[3]), "r"(b0), "r"(b1));
}

// ---------------- tcgen05 primitives (sm_103a-only path; call sites guarded) ----
__device__ __forceinline__ uint32_t elect1() {
    uint32_t pred;
    asm volatile("{\n\t.reg .pred p;\n\telect.sync _|p, 0xFFFFFFFF;\n\tselp.b32 %0, 1, 0, p;\n\t}"
                 : "=r"(pred));
    return pred;
}
__device__ __forceinline__ void mbar_init(uint32_t a, uint32_t cnt) {
    asm volatile("mbarrier.init.shared.b64 [%0], %1;" :: "r"(a), "r"(cnt) : "memory");
}
__device__ __forceinline__ void mbar_inval(uint32_t a) {
    asm volatile("mbarrier.inval.shared.b64 [%0];" :: "r"(a) : "memory");
}
__device__ __forceinline__ void mbar_wait(uint32_t a, uint32_t parity) {
    asm volatile(
        "{\n\t.reg .pred P;\n\t"
        "W%=:\n\t"
        "mbarrier.try_wait.parity.acquire.cta.shared::cta.b64 P, [%0], %1, 0x989680;\n\t"
        "@P bra.uni D%=;\n\t"
        "bra.uni W%=;\n\t"
        "D%=:\n\t}"
        :: "r"(a), "r"(parity) : "memory");
}
__device__ __forceinline__ void t5_alloc(uint32_t dst, uint32_t n) {
    asm volatile("tcgen05.alloc.cta_group::1.sync.aligned.shared::cta.b32 [%0], %1;"
                 :: "r"(dst), "r"(n) : "memory");
}
__device__ __forceinline__ void t5_relinquish() {
    asm volatile("tcgen05.relinquish_alloc_permit.cta_group::1.sync.aligned;");
}
__device__ __forceinline__ void t5_dealloc(uint32_t t, uint32_t n) {
    asm volatile("tcgen05.dealloc.cta_group::1.sync.aligned.b32 %0, %1;" :: "r"(t), "r"(n));
}
__device__ __forceinline__ void t5_commit(uint32_t mbar) {
    asm volatile("tcgen05.commit.cta_group::1.mbarrier::arrive::one.shared::cluster.b64 [%0];"
                 :: "r"(mbar) : "memory");
}
__device__ __forceinline__ void t5_fence_after() {
    asm volatile("tcgen05.fence::after_thread_sync;" ::: "memory");
}
__device__ __forceinline__ void t5_waitld() {
    asm volatile("tcgen05.wait::ld.sync.aligned;" ::: "memory");
}
__device__ __forceinline__ void fence_async_shared() {
    asm volatile("fence.proxy.async.shared::cta;" ::: "memory");
}
__device__ __forceinline__ void t5_mma(uint32_t d, uint64_t ad, uint64_t bd,
                                       uint32_t idesc, bool acc) {
    uint32_t en = acc ? 1u : 0u;
    asm volatile(
        "{\n\t.reg .pred p;\n\tsetp.ne.u32 p, %5, 0;\n\t"
        "tcgen05.mma.cta_group::1.kind::f16 [%0], %1, %2, %3, {%4, %4, %4, %4}, p;\n\t}"
        :: "r"(d), "l"(ad), "l"(bd), "r"(idesc), "r"(0u), "r"(en) : "memory");
}
__device__ __forceinline__ void t5_ld32(uint32_t* r, uint32_t taddr) {
    asm volatile(
        "tcgen05.ld.sync.aligned.32x32b.x32.b32 "
        "{%0,%1,%2,%3,%4,%5,%6,%7,%8,%9,%10,%11,%12,%13,%14,%15,"
        "%16,%17,%18,%19,%20,%21,%22,%23,%24,%25,%26,%27,%28,%29,%30,%31}, [%32];"
        : "=r"(r[0]), "=r"(r[1]), "=r"(r[2]), "=r"(r[3]), "=r"(r[4]), "=r"(r[5]),
          "=r"(r[6]), "=r"(r[7]), "=r"(r[8]), "=r"(r[9]), "=r"(r[10]), "=r"(r[11]),
          "=r"(r[12]), "=r"(r[13]), "=r"(r[14]), "=r"(r[15]), "=r"(r[16]), "=r"(r[17]),
          "=r"(r[18]), "=r"(r[19]), "=r"(r[20]), "=r"(r[21]), "=r"(r[22]), "=r"(r[23]),
          "=r"(r[24]), "=r"(r[25]), "=r"(r[26]), "=r"(r[27]), "=r"(r[28]), "=r"(r[29]),
          "=r"(r[30]), "=r"(r[31])
        : "r"(taddr));
}

// idesc kind::f16: dtype=F32, a=BF16 K-major, b=BF16 K-major, N=128, M=128
static constexpr uint32_t T5_IDESC = (1u << 4) | (1u << 7) | (1u << 10) |
                                     ((128u / 8) << 17) | ((128u / 16) << 24);
// SW128 K-major smem descriptor: layout=2, version=1, SBO=64, LBO=1
static constexpr unsigned long long T5_DESC_BASE =
    (2ull << 61) | (1ull << 46) | (64ull << 32) | (1ull << 16);
__device__ __forceinline__ uint64_t make_desc(uint32_t addr) {
    return T5_DESC_BASE | ((uint64_t)(addr >> 4) & 0x3FFFull);
}

#define GSMEM 100352   // tcgen05: ctrl + 3x32KB; fallback: 4x16KB

// ---------------- unified bf16 NT GEMM: C[M,N] = A[M,K] * B[N,K]^T (R12 frozen) ----
template<int BIASMODE, bool ACT_SILU, bool OUTBF>
__global__ __launch_bounds__(256, 2)
void gemm_nt(const bf16* __restrict__ A, const bf16* __restrict__ B,
             void* __restrict__ Cv, const float* __restrict__ bias,
             int M, int N, int K, long long sA_, long long sB_, long long sC_)
{
    extern __shared__ __align__(16) unsigned char smem[];
    const bf16* Az = A + (long long)blockIdx.z * sA_;
    const bf16* Bz = B + (long long)blockIdx.z * sB_;
    const int tid  = threadIdx.x;
    const int row0 = blockIdx.y * 128;
    const int col0 = blockIdx.x * 128;

#if defined(__CUDA_ARCH__) && defined(__CUDA_ARCH_FEAT_SM103_ALL)
    const unsigned u    = (unsigned)__cvta_generic_to_shared(smem);
    const unsigned ctrl = u;
    const unsigned stg  = (u + 2047u) & ~1023u;
    const int warp = tid >> 5, lane = tid & 31;

    if (warp == 0) { t5_alloc(ctrl, 128); t5_relinquish(); }
    if (tid == 0) { mbar_init(ctrl + 16, 1); mbar_init(ctrl + 24, 1); mbar_init(ctrl + 32, 1); }
    __syncthreads();
    uint32_t tmem;
    asm volatile("ld.shared.b32 %0, [%1];" : "=r"(tmem) : "r"(ctrl));

    const int nk = K >> 6;

    auto copyStage = [&](int it, int st) {
        int k0 = it << 6;
        unsigned sA = stg + (unsigned)st * 32768u;
        unsigned sB = sA + 16384u;
        int c = tid & 7, rb = tid >> 3;
#pragma unroll
        for (int i = 0; i < 4; i++) {
            int r = i * 32 + rb;
            unsigned sw = (unsigned)((c ^ (r & 7)) << 4);
            cpasync16(sA + (unsigned)r * 128u + sw,
                      Az + (long long)(row0 + r) * K + k0 + c * 8, row0 + r < M);
            cpasync16(sB + (unsigned)r * 128u + sw,
                      Bz + (long long)(col0 + r) * K + k0 + c * 8, true);
        }
    };

    copyStage(0, 0); cp_commit();
    if (nk > 1) copyStage(1, 1);
    cp_commit();
    if (nk > 2) copyStage(2, 2);
    cp_commit();

    for (int it = 0; it < nk; it++) {
        int st = it % 3;
        cp_wait<1>();
        fence_async_shared();
        __syncthreads();

        if (tid < 32 && elect1()) {
            t5_fence_after();
            unsigned sA = stg + (unsigned)st * 32768u;
            uint64_t ad = make_desc(sA);
            uint64_t bd = make_desc(sA + 16384u);
#pragma unroll
            for (int sub = 0; sub < 4; sub++)
                t5_mma(tmem, ad + 2 * sub, bd + 2 * sub, T5_IDESC, (it | sub) != 0);
            t5_commit(ctrl + 16 + st * 8);
        }
        int prev = it - 1;
        if (prev >= 0 && it + 2 < nk) {
            int pst = prev % 3;
            mbar_wait(ctrl + 16 + pst * 8, (uint32_t)((prev / 3) & 1));
            copyStage(it + 2, pst);
        }
        cp_commit();
    }
    {
        int lastst = (nk - 1) % 3;
        mbar_wait(ctrl + 16 + lastst * 8, (uint32_t)(((nk - 1) / 3) & 1));
    }
    t5_fence_after();
    cp_wait<0>();
    __syncthreads();

    float* tb = (float*)(smem + (stg - u));      // [128][129]
    if (warp < 4) {
        int rloc = warp * 32 + lane;
        float bm = (BIASMODE == 1 && row0 + rloc < M) ? bias[row0 + rloc] : 0.f;
#pragma unroll
        for (int g = 0; g < 4; g++) {
            uint32_t d[32];
            t5_ld32(d, tmem + g * 32);
            t5_waitld();
#pragma unroll
            for (int c2 = 0; c2 < 32; c2++) {
                float v = __uint_as_float(d[c2]);
                if (BIASMODE == 1) v += bm;
                if (BIASMODE == 2) v += bias[col0 + g * 32 + c2];
                if (ACT_SILU) v = siluf(v);
                tb[rloc * 129 + g * 32 + c2] = v;
            }
        }
    }
    __syncthreads();
    {
        int colx = tid & 127;
        int half = tid >> 7;
        for (int rr = half * 64; rr < half * 64 + 64; rr++) {
            int r = row0 + rr;
            if (r >= M) break;
            float v = tb[rr * 129 + colx];
            if (OUTBF) {
                bf16* Cz = (bf16*)Cv + (long long)blockIdx.z * sC_;
                Cz[(long long)r * N + col0 + colx] = __float2bfloat16(v);
            } else {
                float* Cz = (float*)Cv + (long long)blockIdx.z * sC_;
                Cz[(long long)r * N + col0 + colx] = v;
            }
        }
    }
    __syncthreads();
    if (tid == 0) { mbar_inval(ctrl + 16); mbar_inval(ctrl + 24); mbar_inval(ctrl + 32); }
    __syncthreads();
    if (warp == 0) t5_dealloc(tmem, 128);

#else
    const unsigned sbase = (unsigned)__cvta_generic_to_shared(smem);
    const int lane = tid & 31;
    const int warp = tid >> 5;
    const int wm   = (warp & 3) * 32;
    const int wn   = (warp >> 2) * 64;

    float acc[2][8][4];
#pragma unroll
    for (int i = 0; i < 2; i++)
#pragma unroll
        for (int j = 0; j < 8; j++)
#pragma unroll
            for (int r = 0; r < 4; r++) acc[i][j][r] = 0.f;

    const int nk = K / 32;
    const unsigned STG = 16384u;

    auto copyStage = [&](int kt, int st) {
        int k0 = kt * 32;
        unsigned sA = sbase + (unsigned)st * STG;
        unsigned sB = sA + 8192u;
#pragma unroll
        for (int i = 0; i < 2; i++) {
            int f = tid + (i << 8);
            int row = f >> 2, ch = f & 3;
            unsigned dst = sA + row * 64u + (unsigned)((ch ^ ((row >> 1) & 3)) << 4);
            cpasync16(dst, Az + (long long)(row0 + row) * K + k0 + ch * 8, row0 + row < M);
        }
#pragma unroll
        for (int i = 0; i < 2; i++) {
            int f = tid + (i << 8);
            int n = f >> 2, ch = f & 3;
            unsigned dst = sB + n * 64u + (unsigned)((ch ^ ((n >> 1) & 3)) << 4);
            cpasync16(dst, Bz + (long long)(col0 + n) * K + k0 + ch * 8, true);
        }
    };

    copyStage(0, 0); cp_commit();
    if (nk > 1) copyStage(1, 1);
    cp_commit();
    if (nk > 2) copyStage(2, 2);
    cp_commit();

    for (int kt = 0; kt < nk; kt++) {
        cp_wait<2>();
        __syncthreads();

        int st = kt & 3;
        unsigned sA = sbase + (unsigned)st * STG;
        unsigned sB = sA + 8192u;

#pragma unroll
        for (int kk = 0; kk < 32; kk += 16) {
            unsigned a_fr[2][4];
#pragma unroll
            for (int i = 0; i < 2; i++) {
                int row = wm + 16 * i + (lane & 15);
                int ch  = (kk >> 3) + (lane >> 4);
                ldsm4(a_fr[i], sA + row * 64u + (unsigned)((ch ^ ((row >> 1) & 3)) << 4));
            }
            unsigned b_fr[4][4];
#pragma unroll
            for (int j = 0; j < 4; j++) {
                int row = wn + 16 * j + ((lane >> 4) << 3) + (lane & 7);
                int ch  = (kk >> 3) + ((lane >> 3) & 1);
                ldsm4(b_fr[j], sB + row * 64u + (unsigned)((ch ^ ((row >> 1) & 3)) << 4));
            }
#pragma unroll
            for (int i = 0; i < 2; i++)
#pragma unroll
                for (int j = 0; j < 4; j++) {
                    mma_bf16(acc[i][2 * j],     a_fr[i], b_fr[j][0], b_fr[j][1]);
                    mma_bf16(acc[i][2 * j + 1], a_fr[i], b_fr[j][2], b_fr[j][3]);
                }
        }

        if (kt + 3 < nk) copyStage(kt + 3, (kt + 3) & 3);
        cp_commit();
    }

    const int gid = lane >> 2, tig = lane & 3;
#pragma unroll
    for (int i = 0; i < 2; i++) {
#pragma unroll
        for (int rr = 0; rr < 2; rr++) {
            int r = row0 + wm + i * 16 + gid + rr * 8;
            if (r >= M) continue;
            float bm = (BIASMODE == 1) ? bias[r] : 0.f;
#pragma unroll
            for (int j = 0; j < 8; j++) {
                int cc = col0 + wn + j * 8 + 2 * tig;
                float x0 = acc[i][j][2 * rr + 0];
                float x1 = acc[i][j][2 * rr + 1];
                if (BIASMODE == 1) { x0 += bm; x1 += bm; }
                if (BIASMODE == 2) { x0 += bias[cc]; x1 += bias[cc + 1]; }
                if (ACT_SILU) { x0 = siluf(x0); x1 = siluf(x1); }
                if (OUTBF) {
                    bf16* Cz = (bf16*)Cv + (long long)blockIdx.z * sC_;
                    unsigned p = pk2(x0, x1);
                    *(unsigned*)(Cz + (long long)r * N + cc) = p;
                } else {
                    float* Cz = (float*)Cv + (long long)blockIdx.z * sC_;
                    *(float2*)(Cz + (long long)r * N + cc) = make_float2(x0, x1);
                }
            }
        }
    }
#endif
}

// ---------------- weight conversion (vectorized) ----------------
__global__ void convw4_k(const float* __restrict__ src, bf16* __restrict__ dst, long long n4)
{
    long long i = (long long)blockIdx.x * blockDim.x + threadIdx.x;
    long long stride = (long long)gridDim.x * blockDim.x;
    for (; i < n4; i += stride) {
        float4 v = ((const float4*)src)[i];
        uint2 o;
        o.x = pk2(v.x, v.y);
        o.y = pk2(v.z, v.w);
        ((uint2*)dst)[i] = o;
    }
}

// ---------------- silu + transpose ----------------
__global__ void tsil_k(const float* __restrict__ cond, bf16* __restrict__ condT)
{
    __shared__ float t[32][33];
    int b = blockIdx.z;
    int c0 = blockIdx.x * 32, h0 = blockIdx.y * 32;
#pragma unroll
    for (int i = 0; i < 4; i++) {
        int c = c0 + threadIdx.y + i * 8;
        t[threadIdx.y + i * 8][threadIdx.x] =
            cond[((long long)b * SIXC + c) * HWSZ + h0 + threadIdx.x];
    }
    __syncthreads();
#pragma unroll
    for (int i = 0; i < 4; i++) {
        int h = h0 + threadIdx.y + i * 8;
        condT[((long long)b * HWSZ + h) * SIXC + c0 + threadIdx.x] =
            __float2bfloat16(siluf(t[threadIdx.x][threadIdx.y + i * 8]));
    }
}

// ---------------- LayerNorm partial (contiguous input) ----------------
__global__ void ln_partial_k(const float* __restrict__ x,
                             float* __restrict__ psum, float* __restrict__ psumsq)
{
    int b = blockIdx.y;
    const float* xb = x + (long long)b * SN;
    const int chunk = SN / LNB;
    int base = blockIdx.x * chunk;
    float s = 0.f, sq = 0.f;
    for (int i = base + threadIdx.x; i < base + chunk; i += 256) {
        float v = xb[i]; s += v; sq += v * v;
    }
    __shared__ float sh1[256], sh2[256];
    sh1[threadIdx.x] = s; sh2[threadIdx.x] = sq;
    __syncthreads();
    for (int o = 128; o > 0; o >>= 1) {
        if (threadIdx.x < o) {
            sh1[threadIdx.x] += sh1[threadIdx.x + o];
            sh2[threadIdx.x] += sh2[threadIdx.x + o];
        }
        __syncthreads();
    }
    if (threadIdx.x == 0) {
        psum[b * LNB2 + blockIdx.x] = sh1[0];
        psumsq[b * LNB2 + blockIdx.x] = sh2[0];
    }
}

__global__ void ln_final_k(const float* __restrict__ psum, const float* __restrict__ psumsq,
                           float* __restrict__ stats, int cnt)
{
    int b = blockIdx.x;
    float s = 0.f, sq = 0.f;
    for (int i = threadIdx.x; i < cnt; i += 256) { s += psum[b * LNB2 + i]; sq += psumsq[b * LNB2 + i]; }
    __shared__ float sh1[256], sh2[256];
    sh1[threadIdx.x] = s; sh2[threadIdx.x] = sq;
    __syncthreads();
    for (int o = 128; o > 0; o >>= 1) {
        if (threadIdx.x < o) {
            sh1[threadIdx.x] += sh1[threadIdx.x + o];
            sh2[threadIdx.x] += sh2[threadIdx.x + o];
        }
        __syncthreads();
    }
    if (threadIdx.x == 0) {
        float mu = sh1[0] / (float)SN;
        float var = sh2[0] / (float)SN - mu * mu;
        stats[b * 2 + 0] = mu;
        stats[b * 2 + 1] = rsqrtf(var + 1e-6f);
    }
}

// ---------------- token init ----------------
__global__ void tokinit_k(const float* __restrict__ gt, const float* __restrict__ tt,
                          bf16* __restrict__ tok)
{
    int gid = blockIdx.x * blockDim.x + threadIdx.x;
    if (gid >= BN * DD) return;
    int b = gid / DD, j = gid % DD;
    tok[((long long)b * SSEQ + 0) * DD + j] = __float2bfloat16(gt[b * DD + j]);
    tok[((long long)b * SSEQ + 1) * DD + j] = __float2bfloat16(tt[b * DD + j]);
}

// ======= tiled modulate+segment: grid (8 cblk, 32 n1, BN), block 256 =======
// CTA: c in [36*cb, 36*cb+36), rows hh = 2*n1, 2*n1+1 (hl in [0,128)).
// Writes TOKOUT[b][toff + n1*32+n2][4*c0 + jl], jl in [0,144).
template<int TOKSEQ, int TOFF, int SHIFT_CH, int SCALE_CH>
__global__ __launch_bounds__(256)
void seg_t_k(const float* __restrict__ x, const bf16* __restrict__ ss,
             const float* __restrict__ stats, bf16* __restrict__ tokout)
{
    __shared__ float sx[36][128];
    __shared__ bf16  ssc[36][128];
    __shared__ bf16  ssh[36][128];
    const int cb = blockIdx.x, n1 = blockIdx.y, b = blockIdx.z;
    const int c0 = cb * 36;
    const long long hwb = (long long)(n1 << 7);   // 128*n1

    for (int idx = threadIdx.x; idx < 36 * 128; idx += 256) {
        int cl = idx >> 7, hl = idx & 127;
        long long off = ((long long)b * SIXC) * HWSZ + hwb + hl;
        sx[cl][hl]  = x[((long long)b * CCH + c0 + cl) * HWSZ + hwb + hl];
        ssc[cl][hl] = ss[off + (long long)(SCALE_CH + c0 + cl) * HWSZ];
        ssh[cl][hl] = ss[off + (long long)(SHIFT_CH + c0 + cl) * HWSZ];
    }
    __syncthreads();

    float mu = stats[b * 2], rsig = stats[b * 2 + 1];
    for (int idx = threadIdx.x; idx < 32 * 144; idx += 256) {
        int n2 = idx / 144, jl = idx - n2 * 144;
        int cl = jl >> 2;
        int hl = ((jl >> 1) & 1) * 64 + 2 * n2 + (jl & 1);
        float sc = __bfloat162float(ssc[cl][hl]);
        float sh = __bfloat162float(ssh[cl][hl]);
        float v = (sx[cl][hl] - mu) * rsig * (1.f + sc) + sh;
        tokout[((long long)b * TOKSEQ + TOFF + n1 * 32 + n2) * DD + 4 * c0 + jl] =
            __float2bfloat16(v);
    }
}

// ---------------- linear attention (bf16 qkv) ----------------
__global__ void attn_k(const bf16* __restrict__ qkv, bf16* __restrict__ attn)
{
    int h = blockIdx.x, b = blockIdx.y;
    int tid = threadIdx.x;
    __shared__ float vk[33 * 32];
    __shared__ float ks[8][32];
    __shared__ float vs[8][33];
    float acc[5] = {0.f, 0.f, 0.f, 0.f, 0.f};
    const bf16* qkvb = qkv + (long long)b * SSEQ * (3 * DD);

    for (int s0 = 0; s0 < SSEQ; s0 += 8) {
        {
            int si = tid >> 5, d = tid & 31;
            int s = s0 + si;
            ks[si][d] = (s < SSEQ)
                ? fmaxf(__bfloat162float(qkvb[(long long)s * (3 * DD) + DD + h * 32 + d]), 0.f) : 0.f;
        }
        for (int idx = tid; idx < 8 * 33; idx += 256) {
            int si = idx / 33, e = idx % 33;
            int s = s0 + si;
            float vv = 0.f;
            if (s < SSEQ)
                vv = (e < 32) ? __bfloat162float(qkvb[(long long)s * (3 * DD) + 2 * DD + h * 32 + e]) : 1.f;
            vs[si][e] = vv;
        }
        __syncthreads();
#pragma unroll
        for (int si = 0; si < 8; si++) {
#pragma unroll
            for (int r = 0; r < 5; r++) {
                int f = tid + (r << 8);
                if (f < 1056) acc[r] += vs[si][f >> 5] * ks[si][f & 31];
            }
        }
        __syncthreads();
    }
#pragma unroll
    for (int r = 0; r < 5; r++) {
        int f = tid + (r << 8);
        if (f < 1056) vk[f] = acc[r];
    }
    __syncthreads();

    for (int s = tid; s < SSEQ; s += 256) {
        float q[32];
        const __nv_bfloat162* qp2 = reinterpret_cast<const __nv_bfloat162*>(
            qkvb + (long long)s * (3 * DD) + h * 32);
#pragma unroll
        for (int d2 = 0; d2 < 16; d2++) {
            float2 f = __bfloat1622float2(qp2[d2]);
            q[2 * d2]     = fmaxf(f.x, 0.f);
            q[2 * d2 + 1] = fmaxf(f.y, 0.f);
        }
        float den = 0.f;
#pragma unroll
        for (int d = 0; d < 32; d++) den += vk[32 * 32 + d] * q[d];
        float inv = 1.0f / (den + 1e-8f);
        if (s >= 2) {
            bf16* op = attn + ((long long)(b * STOK + s - 2)) * DD + h * 32;
            for (int e = 0; e < 32; e++) {
                float num = 0.f;
#pragma unroll
                for (int d = 0; d < 32; d++) num += vk[e * 32 + d] * q[d];
                op[e] = __float2bfloat16(num * inv);
            }
        }
    }
}

// ======= tiled comb1 + LN partials: grid (8 cblk, 32 n1, BN), block 256 =======
__global__ __launch_bounds__(256)
void comb1_ln_t_k(const float* __restrict__ x, const float* __restrict__ a,
                  const bf16* __restrict__ ss, float* __restrict__ x1,
                  float* __restrict__ psum, float* __restrict__ psumsq)
{
    __shared__ float sa[32][144];
    const int cb = blockIdx.x, n1 = blockIdx.y, b = blockIdx.z;
    const int c0 = cb * 36;
    const long long hwb = (long long)(n1 << 7);

    for (int idx = threadIdx.x; idx < 32 * 144; idx += 256) {
        int n2 = idx / 144, jl = idx - n2 * 144;
        sa[n2][jl] = a[((long long)(b * STOK + n1 * 32 + n2)) * DD + 4 * c0 + jl];
    }
    __syncthreads();

    float s = 0.f, sq = 0.f;
    for (int idx = threadIdx.x; idx < 36 * 128; idx += 256) {
        int cl = idx >> 7, hl = idx & 127;
        int n2 = (hl & 63) >> 1;
        int jl = cl * 4 + ((hl >> 6) << 1) + (hl & 1);
        long long gidx = ((long long)b * CCH + c0 + cl) * HWSZ + hwb + hl;
        float g = __bfloat162float(ss[((long long)b * SIXC + 576 + c0 + cl) * HWSZ + hwb + hl]);
        float v = x[gidx] + sa[n2][jl] * g;
        x1[gidx] = v;
        s += v; sq += v * v;
    }
    __shared__ float sh1[256], sh2[256];
    sh1[threadIdx.x] = s; sh2[threadIdx.x] = sq;
    __syncthreads();
    for (int o = 128; o > 0; o >>= 1) {
        if (threadIdx.x < o) {
            sh1[threadIdx.x] += sh1[threadIdx.x + o];
            sh2[threadIdx.x] += sh2[threadIdx.x + o];
        }
        __syncthreads();
    }
    if (threadIdx.x == 0) {
        int cta = n1 * 8 + cb;                    // 0..255
        psum[b * LNB2 + cta] = sh1[0];
        psumsq[b * LNB2 + cta] = sh2[0];
    }
}

// ---------------- tiled depthwise 3x3 + GLU (proven R12) ----------------
#define DW_CH 64
__global__ __launch_bounds__(256)
void dwglu_t_k(const bf16* __restrict__ hexp, const float* __restrict__ dw_w,
               const float* __restrict__ dw_b, bf16* __restrict__ hglu)
{
    __shared__ bf16 sm[6][32][2 * DW_CH];
    const int cb = blockIdx.x * DW_CH;
    const int y0 = blockIdx.y * 4;
    const int b  = blockIdx.z;
    const bf16* base = hexp + (long long)b * STOK * HF2;

    for (int idx = threadIdx.x; idx < 6 * 32 * 2; idx += 256) {
        int grp = idx & 1;
        int xx  = (idx >> 1) & 31;
        int yr  = idx >> 6;
        int y   = y0 - 1 + yr;
        uint4* dst = (uint4*)&sm[yr][xx][grp * DW_CH];
        if ((unsigned)y < 32u) {
            const uint4* src = (const uint4*)(base + (long long)((y << 5) + xx) * HF2
                                              + cb + grp * HFF);
#pragma unroll
            for (int q = 0; q < 8; q++) dst[q] = src[q];
        } else {
#pragma unroll
            for (int q = 0; q < 8; q++) dst[q] = make_uint4(0, 0, 0, 0);
        }
    }
    __syncthreads();

    const int chp = threadIdx.x & 31;
    const int ch  = chp * 2;
    float2 wa[9], wg[9];
#pragma unroll
    for (int i = 0; i < 9; i++) {
        wa[i] = make_float2(dw_w[(cb + ch) * 9 + i],      dw_w[(cb + ch + 1) * 9 + i]);
        wg[i] = make_float2(dw_w[(cb + ch + HFF) * 9 + i], dw_w[(cb + ch + 1 + HFF) * 9 + i]);
    }
    float2 ba = make_float2(dw_b[cb + ch], dw_b[cb + ch + 1]);
    float2 bg = make_float2(dw_b[cb + ch + HFF], dw_b[cb + ch + 1 + HFF]);

    for (int pos = threadIdx.x >> 5; pos < 128; pos += 8) {
        int xx = pos & 31, yo = pos >> 5;
        float2 va = ba, vg = bg;
#pragma unroll
        for (int ky = 0; ky < 3; ky++) {
            int yr = yo + ky;
#pragma unroll
            for (int kx = -1; kx <= 1; kx++) {
                int xc = xx + kx;
                if ((unsigned)xc >= 32u) continue;
                int wi = ky * 3 + (kx + 1);
                float2 av = __bfloat1622float2(*(const __nv_bfloat162*)&sm[yr][xc][ch]);
                float2 gv = __bfloat1622float2(*(const __nv_bfloat162*)&sm[yr][xc][ch + DW_CH]);
                va.x += wa[wi].x * av.x; va.y += wa[wi].y * av.y;
                vg.x += wg[wi].x * gv.x; vg.y += wg[wi].y * gv.y;
            }
        }
        int n = ((y0 + yo) << 5) + xx;
        float o0 = va.x * siluf(vg.x);
        float o1 = va.y * siluf(vg.y);
        *(unsigned*)&hglu[((long long)(b * STOK + n)) * HFF + cb + ch] = pk2(o0, o1);
    }
}

// ======= tiled comb2: grid (8 cblk, 32 n1, BN), block 256 =======
__global__ __launch_bounds__(256)
void comb2_t_k(const float* __restrict__ x1, const bf16* __restrict__ m,
               const bf16* __restrict__ ss, float* __restrict__ out)
{
    __shared__ bf16 sm_[32][144];
    const int cb = blockIdx.x, n1 = blockIdx.y, b = blockIdx.z;
    const int c0 = cb * 36;
    const long long hwb = (long long)(n1 << 7);

    for (int idx = threadIdx.x; idx < 32 * 144; idx += 256) {
        int n2 = idx / 144, jl = idx - n2 * 144;
        sm_[n2][jl] = m[((long long)(b * STOK + n1 * 32 + n2)) * DD + 4 * c0 + jl];
    }
    __syncthreads();

    for (int idx = threadIdx.x; idx < 36 * 128; idx += 256) {
        int cl = idx >> 7, hl = idx & 127;
        int n2 = (hl & 63) >> 1;
        int jl = cl * 4 + ((hl >> 6) << 1) + (hl & 1);
        long long gidx = ((long long)b * CCH + c0 + cl) * HWSZ + hwb + hl;
        float g = __bfloat162float(ss[((long long)b * SIXC + 1440 + c0 + cl) * HWSZ + hwb + hl]);
        out[gidx] = x1[gidx] + __bfloat162float(sm_[n2][jl]) * g;
    }
}

// ---------------- launch ----------------
extern "C" void kernel_launch(void* const* d_in, const int* in_sizes, int n_in,
                              void* d_out, int out_size)
{
    const float* x      = (const float*)d_in[0];
    const float* cond   = (const float*)d_in[1];
    const float* gtok   = (const float*)d_in[2];
    const float* ttok   = (const float*)d_in[3];
    const float* ss_w   = (const float*)d_in[4];
    const float* ss_b   = (const float*)d_in[5];
    const float* qkv_w  = (const float*)d_in[6];
    const float* proj_w = (const float*)d_in[7];
    const float* proj_b = (const float*)d_in[8];
    const float* inv_w  = (const float*)d_in[9];
    const float* inv_b  = (const float*)d_in[10];
    const float* dw_w   = (const float*)d_in[11];
    const float* dw_b   = (const float*)d_in[12];
    const float* pw_w   = (const float*)d_in[13];
    float* out = (float*)d_out;

    float *p_aproj, *p_x1, *p_psum, *p_psumsq, *p_stats;
    bf16 *p_ss, *p_condT, *p_tok, *p_qkv, *p_attn, *p_t2, *p_hexp, *p_hglu, *p_m;
    bf16 *p_ssw, *p_qkvw, *p_projw, *p_invw, *p_pww;
    cudaGetSymbolAddress((void**)&p_ss, g_ss);
    cudaGetSymbolAddress((void**)&p_condT, g_condT);
    cudaGetSymbolAddress((void**)&p_tok, g_tok);
    cudaGetSymbolAddress((void**)&p_qkv, g_qkv);
    cudaGetSymbolAddress((void**)&p_attn, g_attn);
    cudaGetSymbolAddress((void**)&p_aproj, g_aproj);
    cudaGetSymbolAddress((void**)&p_x1, g_x1);
    cudaGetSymbolAddress((void**)&p_t2, g_t2);
    cudaGetSymbolAddress((void**)&p_hexp, g_hexp);
    cudaGetSymbolAddress((void**)&p_hglu, g_hglu);
    cudaGetSymbolAddress((void**)&p_m, g_m);
    cudaGetSymbolAddress((void**)&p_psum, g_psum);
    cudaGetSymbolAddress((void**)&p_psumsq, g_psumsq);
    cudaGetSymbolAddress((void**)&p_stats, g_stats);
    cudaGetSymbolAddress((void**)&p_ssw, g_ssw);
    cudaGetSymbolAddress((void**)&p_qkvw, g_qkvw);
    cudaGetSymbolAddress((void**)&p_projw, g_projw);
    cudaGetSymbolAddress((void**)&p_invw, g_invw);
    cudaGetSymbolAddress((void**)&p_pww, g_pww);

    cudaFuncSetAttribute(gemm_nt<1, false, true>,  cudaFuncAttributeMaxDynamicSharedMemorySize, GSMEM);
    cudaFuncSetAttribute(gemm_nt<0, false, true>,  cudaFuncAttributeMaxDynamicSharedMemorySize, GSMEM);
    cudaFuncSetAttribute(gemm_nt<2, false, false>, cudaFuncAttributeMaxDynamicSharedMemorySize, GSMEM);
    cudaFuncSetAttribute(gemm_nt<2, true, true>,   cudaFuncAttributeMaxDynamicSharedMemorySize, GSMEM);

    // 0) weight conversion + cond silu-transpose
    convw4_k<<<1024, 256>>>(ss_w, p_ssw, (long long)SIXC * SIXC / 4);
    convw4_k<<<1024, 256>>>(qkv_w, p_qkvw, (long long)3 * DD * DD / 4);
    convw4_k<<<1024, 256>>>(proj_w, p_projw, (long long)DD * DD / 4);
    convw4_k<<<2048, 256>>>(inv_w, p_invw, (long long)HF2 * DD / 4);
    convw4_k<<<1024, 256>>>(pw_w, p_pww, (long long)DD * HFF / 4);
    tsil_k<<<dim3(SIXC / 32, HWSZ / 32, BN), dim3(32, 8)>>>(cond, p_condT);

    // 1) scale_shift (bf16 out)
    gemm_nt<1, false, true><<<dim3(HWSZ / 128, 14, BN), 256, GSMEM>>>(
        p_ssw, p_condT, p_ss, ss_b, SIXC, HWSZ, SIXC,
        0LL, (long long)HWSZ * SIXC, (long long)SIXC * HWSZ);

    // 2) LayerNorm(x)
    ln_partial_k<<<dim3(LNB, BN), 256>>>(x, p_psum, p_psumsq);
    ln_final_k<<<BN, 256>>>(p_psum, p_psumsq, p_stats, LNB);

    // 3) tokens (bf16): global/time + tiled MSA modulate+segment
    tokinit_k<<<(BN * DD + 255) / 256, 256>>>(gtok, ttok, p_tok);
    seg_t_k<SSEQ, 2, 0, 288><<<dim3(8, 32, BN), 256>>>(x, p_ss, p_stats, p_tok);

    // 4) qkv (bf16 out)
    gemm_nt<0, false, true><<<dim3((3 * DD) / 128, 33, 1), 256, GSMEM>>>(
        p_tok, p_qkvw, p_qkv, nullptr, BN * SSEQ, 3 * DD, DD, 0LL, 0LL, 0LL);

    // 5) linear attention (bf16 in/out)
    attn_k<<<dim3(NHEADS, BN), 256>>>(p_qkv, p_attn);

    // 6) proj (fp32 out)
    gemm_nt<2, false, false><<<dim3(DD / 128, 32, 1), 256, GSMEM>>>(
        p_attn, p_projw, p_aproj, proj_b, BN * STOK, DD, DD, 0LL, 0LL, 0LL);

    // 7+8a) tiled comb1 + LN(x1) partials
    comb1_ln_t_k<<<dim3(8, 32, BN), 256>>>(x, p_aproj, p_ss, p_x1, p_psum, p_psumsq);

    // 8b) LN(x1) finalize
    ln_final_k<<<BN, 256>>>(p_psum, p_psumsq, p_stats, LNB2);

    // 9) tiled MLP modulate+segment (token-major bf16)
    seg_t_k<STOK, 0, 864, 1152><<<dim3(8, 32, BN), 256>>>(p_x1, p_ss, p_stats, p_t2);

    // 10) expand (bf16 out)
    gemm_nt<2, true, true><<<dim3(HF2 / 128, STOK / 128, BN), 256, GSMEM>>>(
        p_t2, p_invw, p_hexp, inv_b, STOK, HF2, DD,
        (long long)STOK * DD, 0LL, (long long)STOK * HF2);

    // 11) tiled depthwise 3x3 + GLU
    dwglu_t_k<<<dim3(HFF / DW_CH, 8, BN), 256>>>(p_hexp, dw_w, dw_b, p_hglu);

    // 12) project (bf16 out)
    gemm_nt<0, false, true><<<dim3(DD / 128, STOK / 128, BN), 256, GSMEM>>>(
        p_hglu, p_pww, p_m, nullptr, STOK, DD, HFF,
        (long long)STOK * HFF, 0LL, (long long)STOK * DD);

    // 13) tiled comb2
    comb2_t_k<<<dim3(8, 32, BN), 256>>>(p_x1, p_m, p_ss, out);
}

// round 15
// speedup vs baseline: 1.1958x; 1.0676x over previous
#include <cuda_runtime.h>
#include <cuda_bf16.h>
#include <cstdint>

// ---------------- problem constants ----------------
#define BN     4
#define CCH    288
#define HWSZ   4096
#define SN     (CCH*HWSZ)
#define DD     1152
#define SIXC   1728
#define STOK   1024
#define SSEQ   1026
#define NHEADS 36
#define HFF    4608
#define HF2    9216
#define LNB    144

typedef __nv_bfloat16 bf16;

// ---------------- scratch (static device memory) ----------------
__device__ bf16  g_ss   [BN*SIXC*HWSZ];
__device__ bf16  g_condT[BN*HWSZ*SIXC];
__device__ bf16  g_tok  [BN*SSEQ*DD];
__device__ bf16  g_qkv  [BN*SSEQ*3*DD];
__device__ bf16  g_attn [BN*STOK*DD];
__device__ bf16  g_aproj[BN*STOK*DD];
__device__ float g_x1   [BN*SN];
__device__ bf16  g_t2   [BN*STOK*DD];
__device__ bf16  g_hexp [BN*STOK*HF2];
__device__ bf16  g_hglu [BN*STOK*HFF];
__device__ bf16  g_m    [BN*STOK*DD];
__device__ float g_psum [BN*LNB];
__device__ float g_psumsq[BN*LNB];
__device__ float g_stats[BN*2];
__device__ bf16  g_ssw  [SIXC*SIXC];
__device__ bf16  g_qkvw [3*DD*DD];
__device__ bf16  g_projw[DD*DD];
__device__ bf16  g_invw [HF2*DD];
__device__ bf16  g_pww  [DD*HFF];

__device__ __forceinline__ float siluf(float v) { return v / (1.0f + __expf(-v)); }

__device__ __forceinline__ unsigned pk2(float x, float y) {
    __nv_bfloat162 h = __floats2bfloat162_rn(x, y);
    return *reinterpret_cast<unsigned*>(&h);
}

// ---------------- common async-copy primitives ----------------
__device__ __forceinline__ void cpasync16(unsigned dst, const void* src, bool valid) {
    int sz = valid ? 16 : 0;
    asm volatile("cp.async.cg.shared.global [%0], [%1], 16, %2;" :: "r"(dst), "l"(src), "r"(sz));
}
__device__ __forceinline__ void cp_commit() { asm volatile("cp.async.commit_group;"); }
template<int N> __device__ __forceinline__ void cp_wait() {
    asm volatile("cp.async.wait_group %0;" :: "n"(N));
}

// ---------------- legacy mma.sync primitives (fallback path) ----------------
__device__ __forceinline__ void ldsm4(unsigned r[4], unsigned addr) {
    asm volatile("ldmatrix.sync.aligned.m8n8.x4.shared.b16 {%0,%1,%2,%3}, [%4];"
                 : "=r"(r[0]), "=r"(r[1]), "=r"(r[2]), "=r"(r[3]) : "r"(addr));
}
__device__ __forceinline__ void mma_bf16(float c[4], const unsigned a[4], unsigned b0, unsigned b1) {
    asm volatile(
        "mma.sync.aligned.m16n8k16.row.col.f32.bf16.bf16.f32 "
        "{%0,%1,%2,%3}, {%4,%5,%6,%7}, {%8,%9}, {%0,%1,%2,%3};"
        : "+f"(c[0]), "+f"(c[1]), "+f"(c[2]), "+f"(c[3])
        : "r"(a[0]), "r"(a[1]), "r"(a[2]), "r"(a[3]), "r"(b0), "r"(b1));
}

// ---------------- tcgen05 primitives (sm_103a-only path; call sites guarded) ----
__device__ __forceinline__ uint32_t elect1() {
    uint32_t pred;
    asm volatile("{\n\t.reg .pred p;\n\telect.sync _|p, 0xFFFFFFFF;\n\tselp.b32 %0, 1, 0, p;\n\t}"
                 : "=r"(pred));
    return pred;
}
__device__ __forceinline__ void mbar_init(uint32_t a, uint32_t cnt) {
    asm volatile("mbarrier.init.shared.b64 [%0], %1;" :: "r"(a), "r"(cnt) : "memory");
}
__device__ __forceinline__ void mbar_inval(uint32_t a) {
    asm volatile("mbarrier.inval.shared.b64 [%0];" :: "r"(a) : "memory");
}
__device__ __forceinline__ void mbar_wait(uint32_t a, uint32_t parity) {
    asm volatile(
        "{\n\t.reg .pred P;\n\t"
        "W%=:\n\t"
        "mbarrier.try_wait.parity.acquire.cta.shared::cta.b64 P, [%0], %1, 0x989680;\n\t"
        "@P bra.uni D%=;\n\t"
        "bra.uni W%=;\n\t"
        "D%=:\n\t}"
        :: "r"(a), "r"(parity) : "memory");
}
__device__ __forceinline__ void t5_alloc(uint32_t dst, uint32_t n) {
    asm volatile("tcgen05.alloc.cta_group::1.sync.aligned.shared::cta.b32 [%0], %1;"
                 :: "r"(dst), "r"(n) : "memory");
}
__device__ __forceinline__ void t5_relinquish() {
    asm volatile("tcgen05.relinquish_alloc_permit.cta_group::1.sync.aligned;");
}
__device__ __forceinline__ void t5_dealloc(uint32_t t, uint32_t n) {
    asm volatile("tcgen05.dealloc.cta_group::1.sync.aligned.b32 %0, %1;" :: "r"(t), "r"(n));
}
__device__ __forceinline__ void t5_commit(uint32_t mbar) {
    asm volatile("tcgen05.commit.cta_group::1.mbarrier::arrive::one.shared::cluster.b64 [%0];"
                 :: "r"(mbar) : "memory");
}
__device__ __forceinline__ void t5_fence_after() {
    asm volatile("tcgen05.fence::after_thread_sync;" ::: "memory");
}
__device__ __forceinline__ void t5_waitld() {
    asm volatile("tcgen05.wait::ld.sync.aligned;" ::: "memory");
}
__device__ __forceinline__ void fence_async_shared() {
    asm volatile("fence.proxy.async.shared::cta;" ::: "memory");
}
__device__ __forceinline__ void t5_mma(uint32_t d, uint64_t ad, uint64_t bd,
                                       uint32_t idesc, bool acc) {
    uint32_t en = acc ? 1u : 0u;
    asm volatile(
        "{\n\t.reg .pred p;\n\tsetp.ne.u32 p, %5, 0;\n\t"
        "tcgen05.mma.cta_group::1.kind::f16 [%0], %1, %2, %3, {%4, %4, %4, %4}, p;\n\t}"
        :: "r"(d), "l"(ad), "l"(bd), "r"(idesc), "r"(0u), "r"(en) : "memory");
}
__device__ __forceinline__ void t5_ld32(uint32_t* r, uint32_t taddr) {
    asm volatile(
        "tcgen05.ld.sync.aligned.32x32b.x32.b32 "
        "{%0,%1,%2,%3,%4,%5,%6,%7,%8,%9,%10,%11,%12,%13,%14,%15,"
        "%16,%17,%18,%19,%20,%21,%22,%23,%24,%25,%26,%27,%28,%29,%30,%31}, [%32];"
        : "=r"(r[0]), "=r"(r[1]), "=r"(r[2]), "=r"(r[3]), "=r"(r[4]), "=r"(r[5]),
          "=r"(r[6]), "=r"(r[7]), "=r"(r[8]), "=r"(r[9]), "=r"(r[10]), "=r"(r[11]),
          "=r"(r[12]), "=r"(r[13]), "=r"(r[14]), "=r"(r[15]), "=r"(r[16]), "=r"(r[17]),
          "=r"(r[18]), "=r"(r[19]), "=r"(r[20]), "=r"(r[21]), "=r"(r[22]), "=r"(r[23]),
          "=r"(r[24]), "=r"(r[25]), "=r"(r[26]), "=r"(r[27]), "=r"(r[28]), "=r"(r[29]),
          "=r"(r[30]), "=r"(r[31])
        : "r"(taddr));
}

// idesc kind::f16: dtype=F32, a=BF16 K-major, b=BF16 K-major, N=128, M=128
static constexpr uint32_t T5_IDESC = (1u << 4) | (1u << 7) | (1u << 10) |
                                     ((128u / 8) << 17) | ((128u / 16) << 24);
// SW128 K-major smem descriptor: layout=2, version=1, SBO=64, LBO=1
static constexpr unsigned long long T5_DESC_BASE =
    (2ull << 61) | (1ull << 46) | (64ull << 32) | (1ull << 16);
__device__ __forceinline__ uint64_t make_desc(uint32_t addr) {
    return T5_DESC_BASE | ((uint64_t)(addr >> 4) & 0x3FFFull);
}

#define GSMEM 100352   // tcgen05: ctrl + 3x32KB; fallback: 4x16KB

// ---------------- unified bf16 NT GEMM: C[M,N] = A[M,K] * B[N,K]^T (R12 frozen) ----
template<int BIASMODE, bool ACT_SILU, bool OUTBF>
__global__ __launch_bounds__(256, 2)
void gemm_nt(const bf16* __restrict__ A, const bf16* __restrict__ B,
             void* __restrict__ Cv, const float* __restrict__ bias,
             int M, int N, int K, long long sA_, long long sB_, long long sC_)
{
    extern __shared__ __align__(16) unsigned char smem[];
    const bf16* Az = A + (long long)blockIdx.z * sA_;
    const bf16* Bz = B + (long long)blockIdx.z * sB_;
    const int tid  = threadIdx.x;
    const int row0 = blockIdx.y * 128;
    const int col0 = blockIdx.x * 128;

#if defined(__CUDA_ARCH__) && defined(__CUDA_ARCH_FEAT_SM103_ALL)
    const unsigned u    = (unsigned)__cvta_generic_to_shared(smem);
    const unsigned ctrl = u;
    const unsigned stg  = (u + 2047u) & ~1023u;
    const int warp = tid >> 5, lane = tid & 31;

    if (warp == 0) { t5_alloc(ctrl, 128); t5_relinquish(); }
    if (tid == 0) { mbar_init(ctrl + 16, 1); mbar_init(ctrl + 24, 1); mbar_init(ctrl + 32, 1); }
    __syncthreads();
    uint32_t tmem;
    asm volatile("ld.shared.b32 %0, [%1];" : "=r"(tmem) : "r"(ctrl));

    const int nk = K >> 6;

    auto copyStage = [&](int it, int st) {
        int k0 = it << 6;
        unsigned sA = stg + (unsigned)st * 32768u;
        unsigned sB = sA + 16384u;
        int c = tid & 7, rb = tid >> 3;
#pragma unroll
        for (int i = 0; i < 4; i++) {
            int r = i * 32 + rb;
            unsigned sw = (unsigned)((c ^ (r & 7)) << 4);
            cpasync16(sA + (unsigned)r * 128u + sw,
                      Az + (long long)(row0 + r) * K + k0 + c * 8, row0 + r < M);
            cpasync16(sB + (unsigned)r * 128u + sw,
                      Bz + (long long)(col0 + r) * K + k0 + c * 8, true);
        }
    };

    copyStage(0, 0); cp_commit();
    if (nk > 1) copyStage(1, 1);
    cp_commit();
    if (nk > 2) copyStage(2, 2);
    cp_commit();

    for (int it = 0; it < nk; it++) {
        int st = it % 3;
        cp_wait<1>();
        fence_async_shared();
        __syncthreads();

        if (tid < 32 && elect1()) {
            t5_fence_after();
            unsigned sA = stg + (unsigned)st * 32768u;
            uint64_t ad = make_desc(sA);
            uint64_t bd = make_desc(sA + 16384u);
#pragma unroll
            for (int sub = 0; sub < 4; sub++)
                t5_mma(tmem, ad + 2 * sub, bd + 2 * sub, T5_IDESC, (it | sub) != 0);
            t5_commit(ctrl + 16 + st * 8);
        }
        int prev = it - 1;
        if (prev >= 0 && it + 2 < nk) {
            int pst = prev % 3;
            mbar_wait(ctrl + 16 + pst * 8, (uint32_t)((prev / 3) & 1));
            copyStage(it + 2, pst);
        }
        cp_commit();
    }
    {
        int lastst = (nk - 1) % 3;
        mbar_wait(ctrl + 16 + lastst * 8, (uint32_t)(((nk - 1) / 3) & 1));
    }
    t5_fence_after();
    cp_wait<0>();
    __syncthreads();

    float* tb = (float*)(smem + (stg - u));      // [128][129]
    if (warp < 4) {
        int rloc = warp * 32 + lane;
        float bm = (BIASMODE == 1 && row0 + rloc < M) ? bias[row0 + rloc] : 0.f;
#pragma unroll
        for (int g = 0; g < 4; g++) {
            uint32_t d[32];
            t5_ld32(d, tmem + g * 32);
            t5_waitld();
#pragma unroll
            for (int c2 = 0; c2 < 32; c2++) {
                float v = __uint_as_float(d[c2]);
                if (BIASMODE == 1) v += bm;
                if (BIASMODE == 2) v += bias[col0 + g * 32 + c2];
                if (ACT_SILU) v = siluf(v);
                tb[rloc * 129 + g * 32 + c2] = v;
            }
        }
    }
    __syncthreads();
    if (OUTBF) {
        // paired-column bf16 store: 4B per row per thread, 32 rows per quarter
        bf16* Cz = (bf16*)Cv + (long long)blockIdx.z * sC_;
        int cp2 = (tid & 63) * 2;
        int q = tid >> 6;
        for (int rr = q * 32; rr < q * 32 + 32; rr++) {
            int r = row0 + rr;
            if (r >= M) break;
            float v0 = tb[rr * 129 + cp2];
            float v1 = tb[rr * 129 + cp2 + 1];
            *(unsigned*)(Cz + (long long)r * N + col0 + cp2) = pk2(v0, v1);
        }
    } else {
        float* Cz = (float*)Cv + (long long)blockIdx.z * sC_;
        int colx = tid & 127;
        int half = tid >> 7;
        for (int rr = half * 64; rr < half * 64 + 64; rr++) {
            int r = row0 + rr;
            if (r >= M) break;
            Cz[(long long)r * N + col0 + colx] = tb[rr * 129 + colx];
        }
    }
    __syncthreads();
    if (tid == 0) { mbar_inval(ctrl + 16); mbar_inval(ctrl + 24); mbar_inval(ctrl + 32); }
    __syncthreads();
    if (warp == 0) t5_dealloc(tmem, 128);

#else
    const unsigned sbase = (unsigned)__cvta_generic_to_shared(smem);
    const int lane = tid & 31;
    const int warp = tid >> 5;
    const int wm   = (warp & 3) * 32;
    const int wn   = (warp >> 2) * 64;

    float acc[2][8][4];
#pragma unroll
    for (int i = 0; i < 2; i++)
#pragma unroll
        for (int j = 0; j < 8; j++)
#pragma unroll
            for (int r = 0; r < 4; r++) acc[i][j][r] = 0.f;

    const int nk = K / 32;
    const unsigned STG = 16384u;

    auto copyStage = [&](int kt, int st) {
        int k0 = kt * 32;
        unsigned sA = sbase + (unsigned)st * STG;
        unsigned sB = sA + 8192u;
#pragma unroll
        for (int i = 0; i < 2; i++) {
            int f = tid + (i << 8);
            int row = f >> 2, ch = f & 3;
            unsigned dst = sA + row * 64u + (unsigned)((ch ^ ((row >> 1) & 3)) << 4);
            cpasync16(dst, Az + (long long)(row0 + row) * K + k0 + ch * 8, row0 + row < M);
        }
#pragma unroll
        for (int i = 0; i < 2; i++) {
            int f = tid + (i << 8);
            int n = f >> 2, ch = f & 3;
            unsigned dst = sB + n * 64u + (unsigned)((ch ^ ((n >> 1) & 3)) << 4);
            cpasync16(dst, Bz + (long long)(col0 + n) * K + k0 + ch * 8, true);
        }
    };

    copyStage(0, 0); cp_commit();
    if (nk > 1) copyStage(1, 1);
    cp_commit();
    if (nk > 2) copyStage(2, 2);
    cp_commit();

    for (int kt = 0; kt < nk; kt++) {
        cp_wait<2>();
        __syncthreads();

        int st = kt & 3;
        unsigned sA = sbase + (unsigned)st * STG;
        unsigned sB = sA + 8192u;

#pragma unroll
        for (int kk = 0; kk < 32; kk += 16) {
            unsigned a_fr[2][4];
#pragma unroll
            for (int i = 0; i < 2; i++) {
                int row = wm + 16 * i + (lane & 15);
                int ch  = (kk >> 3) + (lane >> 4);
                ldsm4(a_fr[i], sA + row * 64u + (unsigned)((ch ^ ((row >> 1) & 3)) << 4));
            }
            unsigned b_fr[4][4];
#pragma unroll
            for (int j = 0; j < 4; j++) {
                int row = wn + 16 * j + ((lane >> 4) << 3) + (lane & 7);
                int ch  = (kk >> 3) + ((lane >> 3) & 1);
                ldsm4(b_fr[j], sB + row * 64u + (unsigned)((ch ^ ((row >> 1) & 3)) << 4));
            }
#pragma unroll
            for (int i = 0; i < 2; i++)
#pragma unroll
                for (int j = 0; j < 4; j++) {
                    mma_bf16(acc[i][2 * j],     a_fr[i], b_fr[j][0], b_fr[j][1]);
                    mma_bf16(acc[i][2 * j + 1], a_fr[i], b_fr[j][2], b_fr[j][3]);
                }
        }

        if (kt + 3 < nk) copyStage(kt + 3, (kt + 3) & 3);
        cp_commit();
    }

    const int gid = lane >> 2, tig = lane & 3;
#pragma unroll
    for (int i = 0; i < 2; i++) {
#pragma unroll
        for (int rr = 0; rr < 2; rr++) {
            int r = row0 + wm + i * 16 + gid + rr * 8;
            if (r >= M) continue;
            float bm = (BIASMODE == 1) ? bias[r] : 0.f;
#pragma unroll
            for (int j = 0; j < 8; j++) {
                int cc = col0 + wn + j * 8 + 2 * tig;
                float x0 = acc[i][j][2 * rr + 0];
                float x1 = acc[i][j][2 * rr + 1];
                if (BIASMODE == 1) { x0 += bm; x1 += bm; }
                if (BIASMODE == 2) { x0 += bias[cc]; x1 += bias[cc + 1]; }
                if (ACT_SILU) { x0 = siluf(x0); x1 = siluf(x1); }
                if (OUTBF) {
                    bf16* Cz = (bf16*)Cv + (long long)blockIdx.z * sC_;
                    unsigned p = pk2(x0, x1);
                    *(unsigned*)(Cz + (long long)r * N + cc) = p;
                } else {
                    float* Cz = (float*)Cv + (long long)blockIdx.z * sC_;
                    *(float2*)(Cz + (long long)r * N + cc) = make_float2(x0, x1);
                }
            }
        }
    }
#endif
}

// ---------------- weight conversion (vectorized) ----------------
__global__ void convw4_k(const float* __restrict__ src, bf16* __restrict__ dst, long long n4)
{
    long long i = (long long)blockIdx.x * blockDim.x + threadIdx.x;
    long long stride = (long long)gridDim.x * blockDim.x;
    for (; i < n4; i += stride) {
        float4 v = ((const float4*)src)[i];
        uint2 o;
        o.x = pk2(v.x, v.y);
        o.y = pk2(v.z, v.w);
        ((uint2*)dst)[i] = o;
    }
}

// ---------------- silu + transpose ----------------
__global__ void tsil_k(const float* __restrict__ cond, bf16* __restrict__ condT)
{
    __shared__ float t[32][33];
    int b = blockIdx.z;
    int c0 = blockIdx.x * 32, h0 = blockIdx.y * 32;
#pragma unroll
    for (int i = 0; i < 4; i++) {
        int c = c0 + threadIdx.y + i * 8;
        t[threadIdx.y + i * 8][threadIdx.x] =
            cond[((long long)b * SIXC + c) * HWSZ + h0 + threadIdx.x];
    }
    __syncthreads();
#pragma unroll
    for (int i = 0; i < 4; i++) {
        int h = h0 + threadIdx.y + i * 8;
        condT[((long long)b * HWSZ + h) * SIXC + c0 + threadIdx.x] =
            __float2bfloat16(siluf(t[threadIdx.x][threadIdx.y + i * 8]));
    }
}

// ---------------- LayerNorm partial ----------------
__global__ void ln_partial_k(const float* __restrict__ x,
                             float* __restrict__ psum, float* __restrict__ psumsq)
{
    int b = blockIdx.y;
    const float* xb = x + (long long)b * SN;
    const int chunk = SN / LNB;
    int base = blockIdx.x * chunk;
    float s = 0.f, sq = 0.f;
    for (int i = base + threadIdx.x; i < base + chunk; i += 256) {
        float v = xb[i]; s += v; sq += v * v;
    }
    __shared__ float sh1[256], sh2[256];
    sh1[threadIdx.x] = s; sh2[threadIdx.x] = sq;
    __syncthreads();
    for (int o = 128; o > 0; o >>= 1) {
        if (threadIdx.x < o) {
            sh1[threadIdx.x] += sh1[threadIdx.x + o];
            sh2[threadIdx.x] += sh2[threadIdx.x + o];
        }
        __syncthreads();
    }
    if (threadIdx.x == 0) {
        psum[b * LNB + blockIdx.x] = sh1[0];
        psumsq[b * LNB + blockIdx.x] = sh2[0];
    }
}

__global__ void ln_final_k(const float* __restrict__ psum, const float* __restrict__ psumsq,
                           float* __restrict__ stats)
{
    int b = blockIdx.x;
    float s = 0.f, sq = 0.f;
    for (int i = threadIdx.x; i < LNB; i += 256) { s += psum[b * LNB + i]; sq += psumsq[b * LNB + i]; }
    __shared__ float sh1[256], sh2[256];
    sh1[threadIdx.x] = s; sh2[threadIdx.x] = sq;
    __syncthreads();
    for (int o = 128; o > 0; o >>= 1) {
        if (threadIdx.x < o) {
            sh1[threadIdx.x] += sh1[threadIdx.x + o];
            sh2[threadIdx.x] += sh2[threadIdx.x + o];
        }
        __syncthreads();
    }
    if (threadIdx.x == 0) {
        float mu = sh1[0] / (float)SN;
        float var = sh2[0] / (float)SN - mu * mu;
        stats[b * 2 + 0] = mu;
        stats[b * 2 + 1] = rsqrtf(var + 1e-6f);
    }
}

// ---------------- token init ----------------
__global__ void tokinit_k(const float* __restrict__ gt, const float* __restrict__ tt,
                          bf16* __restrict__ tok)
{
    int gid = blockIdx.x * blockDim.x + threadIdx.x;
    if (gid >= BN * DD) return;
    int b = gid / DD, j = gid % DD;
    tok[((long long)b * SSEQ + 0) * DD + j] = __float2bfloat16(gt[b * DD + j]);
    tok[((long long)b * SSEQ + 1) * DD + j] = __float2bfloat16(tt[b * DD + j]);
}

// ---------------- MSA modulate + segment ----------------
__global__ void msa_seg_k(const float* __restrict__ x, const bf16* __restrict__ ss,
                          const float* __restrict__ stats, bf16* __restrict__ tok)
{
    long long gid = (long long)blockIdx.x * blockDim.x + threadIdx.x;
    if (gid >= (long long)BN * STOK * DD) return;
    int j = (int)(gid % DD);
    int t = (int)((gid / DD) % STOK);
    int b = (int)(gid / ((long long)STOK * DD));
    int c = j >> 2, p1 = (j >> 1) & 1, p2 = j & 1;
    int n1 = t >> 5, n2 = t & 31;
    int hw = ((2 * n1 + p1) << 6) + 2 * n2 + p2;
    float mu = stats[b * 2], rsig = stats[b * 2 + 1];
    float xv = x[((long long)b * CCH + c) * HWSZ + hw];
    float sc = __bfloat162float(ss[((long long)b * SIXC + 288 + c) * HWSZ + hw]);
    float sh = __bfloat162float(ss[((long long)b * SIXC + c) * HWSZ + hw]);
    tok[((long long)b * SSEQ + 2 + t) * DD + j] =
        __float2bfloat16((xv - mu) * rsig * (1.f + sc) + sh);
}

// ---------------- linear attention (bf16 qkv) ----------------
__global__ void attn_k(const bf16* __restrict__ qkv, bf16* __restrict__ attn)
{
    int h = blockIdx.x, b = blockIdx.y;
    int tid = threadIdx.x;
    __shared__ float vk[33 * 32];
    __shared__ float ks[8][32];
    __shared__ float vs[8][33];
    float acc[5] = {0.f, 0.f, 0.f, 0.f, 0.f};
    const bf16* qkvb = qkv + (long long)b * SSEQ * (3 * DD);

    for (int s0 = 0; s0 < SSEQ; s0 += 8) {
        {
            int si = tid >> 5, d = tid & 31;
            int s = s0 + si;
            ks[si][d] = (s < SSEQ)
                ? fmaxf(__bfloat162float(qkvb[(long long)s * (3 * DD) + DD + h * 32 + d]), 0.f) : 0.f;
        }
        for (int idx = tid; idx < 8 * 33; idx += 256) {
            int si = idx / 33, e = idx % 33;
            int s = s0 + si;
            float vv = 0.f;
            if (s < SSEQ)
                vv = (e < 32) ? __bfloat162float(qkvb[(long long)s * (3 * DD) + 2 * DD + h * 32 + e]) : 1.f;
            vs[si][e] = vv;
        }
        __syncthreads();
#pragma unroll
        for (int si = 0; si < 8; si++) {
#pragma unroll
            for (int r = 0; r < 5; r++) {
                int f = tid + (r << 8);
                if (f < 1056) acc[r] += vs[si][f >> 5] * ks[si][f & 31];
            }
        }
        __syncthreads();
    }
#pragma unroll
    for (int r = 0; r < 5; r++) {
        int f = tid + (r << 8);
        if (f < 1056) vk[f] = acc[r];
    }
    __syncthreads();

    for (int s = tid; s < SSEQ; s += 256) {
        float q[32];
        const __nv_bfloat162* qp2 = reinterpret_cast<const __nv_bfloat162*>(
            qkvb + (long long)s * (3 * DD) + h * 32);
#pragma unroll
        for (int d2 = 0; d2 < 16; d2++) {
            float2 f = __bfloat1622float2(qp2[d2]);
            q[2 * d2]     = fmaxf(f.x, 0.f);
            q[2 * d2 + 1] = fmaxf(f.y, 0.f);
        }
        float den = 0.f;
#pragma unroll
        for (int d = 0; d < 32; d++) den += vk[32 * 32 + d] * q[d];
        float inv = 1.0f / (den + 1e-8f);
        if (s >= 2) {
            bf16* op = attn + ((long long)(b * STOK + s - 2)) * DD + h * 32;
            for (int e = 0; e < 32; e++) {
                float num = 0.f;
#pragma unroll
                for (int d = 0; d < 32; d++) num += vk[e * 32 + d] * q[d];
                op[e] = __float2bfloat16(num * inv);
            }
        }
    }
}

// ---------------- fused: x1 = x + comb(a)*g_msa, + LN partials (a bf16) --------
__global__ void comb1_ln_k(const float* __restrict__ x, const bf16* __restrict__ a,
                           const bf16* __restrict__ ss, float* __restrict__ x1,
                           float* __restrict__ psum, float* __restrict__ psumsq)
{
    int b = blockIdx.y;
    const int chunk = SN / LNB;
    int base = blockIdx.x * chunk;
    float s = 0.f, sq = 0.f;
    for (int i = threadIdx.x; i < chunk; i += 256) {
        int loc = base + i;
        int hw = loc & (HWSZ - 1);
        int c  = loc >> 12;
        int hh = hw >> 6, ww = hw & 63;
        int t = ((hh >> 1) << 5) + (ww >> 1);
        int j = (c << 2) + ((hh & 1) << 1) + (ww & 1);
        float g = __bfloat162float(ss[((long long)b * SIXC + 576 + c) * HWSZ + hw]);
        long long gid = (long long)b * SN + loc;
        float av = __bfloat162float(a[((long long)(b * STOK + t)) * DD + j]);
        float v = x[gid] + av * g;
        x1[gid] = v;
        s += v; sq += v * v;
    }
    __shared__ float sh1[256], sh2[256];
    sh1[threadIdx.x] = s; sh2[threadIdx.x] = sq;
    __syncthreads();
    for (int o = 128; o > 0; o >>= 1) {
        if (threadIdx.x < o) {
            sh1[threadIdx.x] += sh1[threadIdx.x + o];
            sh2[threadIdx.x] += sh2[threadIdx.x + o];
        }
        __syncthreads();
    }
    if (threadIdx.x == 0) {
        psum[b * LNB + blockIdx.x] = sh1[0];
        psumsq[b * LNB + blockIdx.x] = sh2[0];
    }
}

// ---------------- MLP modulate + segment ----------------
__global__ void mlp_seg_k(const float* __restrict__ x1, const bf16* __restrict__ ss,
                          const float* __restrict__ stats, bf16* __restrict__ t2)
{
    long long gid = (long long)blockIdx.x * blockDim.x + threadIdx.x;
    if (gid >= (long long)BN * STOK * DD) return;
    int j = (int)(gid % DD);
    int t = (int)((gid / DD) % STOK);
    int b = (int)(gid / ((long long)STOK * DD));
    int c = j >> 2, p1 = (j >> 1) & 1, p2 = j & 1;
    int n1 = t >> 5, n2 = t & 31;
    int hw = ((2 * n1 + p1) << 6) + 2 * n2 + p2;
    float mu = stats[b * 2], rsig = stats[b * 2 + 1];
    float xv = x1[((long long)b * CCH + c) * HWSZ + hw];
    float sc = __bfloat162float(ss[((long long)b * SIXC + 1152 + c) * HWSZ + hw]);
    float sh = __bfloat162float(ss[((long long)b * SIXC + 864 + c) * HWSZ + hw]);
    t2[gid] = __float2bfloat16((xv - mu) * rsig * (1.f + sc) + sh);
}

// ---------------- tiled depthwise 3x3 + GLU (proven R12) ----------------
#define DW_CH 64
__global__ __launch_bounds__(256)
void dwglu_t_k(const bf16* __restrict__ hexp, const float* __restrict__ dw_w,
               const float* __restrict__ dw_b, bf16* __restrict__ hglu)
{
    __shared__ bf16 sm[6][32][2 * DW_CH];
    const int cb = blockIdx.x * DW_CH;
    const int y0 = blockIdx.y * 4;
    const int b  = blockIdx.z;
    const bf16* base = hexp + (long long)b * STOK * HF2;

    for (int idx = threadIdx.x; idx < 6 * 32 * 2; idx += 256) {
        int grp = idx & 1;
        int xx  = (idx >> 1) & 31;
        int yr  = idx >> 6;
        int y   = y0 - 1 + yr;
        uint4* dst = (uint4*)&sm[yr][xx][grp * DW_CH];
        if ((unsigned)y < 32u) {
            const uint4* src = (const uint4*)(base + (long long)((y << 5) + xx) * HF2
                                              + cb + grp * HFF);
#pragma unroll
            for (int q = 0; q < 8; q++) dst[q] = src[q];
        } else {
#pragma unroll
            for (int q = 0; q < 8; q++) dst[q] = make_uint4(0, 0, 0, 0);
        }
    }
    __syncthreads();

    const int chp = threadIdx.x & 31;
    const int ch  = chp * 2;
    float2 wa[9], wg[9];
#pragma unroll
    for (int i = 0; i < 9; i++) {
        wa[i] = make_float2(dw_w[(cb + ch) * 9 + i],      dw_w[(cb + ch + 1) * 9 + i]);
        wg[i] = make_float2(dw_w[(cb + ch + HFF) * 9 + i], dw_w[(cb + ch + 1 + HFF) * 9 + i]);
    }
    float2 ba = make_float2(dw_b[cb + ch], dw_b[cb + ch + 1]);
    float2 bg = make_float2(dw_b[cb + ch + HFF], dw_b[cb + ch + 1 + HFF]);

    for (int pos = threadIdx.x >> 5; pos < 128; pos += 8) {
        int xx = pos & 31, yo = pos >> 5;
        float2 va = ba, vg = bg;
#pragma unroll
        for (int ky = 0; ky < 3; ky++) {
            int yr = yo + ky;
#pragma unroll
            for (int kx = -1; kx <= 1; kx++) {
                int xc = xx + kx;
                if ((unsigned)xc >= 32u) continue;
                int wi = ky * 3 + (kx + 1);
                float2 av = __bfloat1622float2(*(const __nv_bfloat162*)&sm[yr][xc][ch]);
                float2 gv = __bfloat1622float2(*(const __nv_bfloat162*)&sm[yr][xc][ch + DW_CH]);
                va.x += wa[wi].x * av.x; va.y += wa[wi].y * av.y;
                vg.x += wg[wi].x * gv.x; vg.y += wg[wi].y * gv.y;
            }
        }
        int n = ((y0 + yo) << 5) + xx;
        float o0 = va.x * siluf(vg.x);
        float o1 = va.y * siluf(vg.y);
        *(unsigned*)&hglu[((long long)(b * STOK + n)) * HFF + cb + ch] = pk2(o0, o1);
    }
}

// ---------------- comb(m)*g_mlp + residual -> out (m bf16) ----------------
__global__ void comb2_k(const float* __restrict__ x1, const bf16* __restrict__ m,
                        const bf16* __restrict__ ss, float* __restrict__ out)
{
    long long gid = (long long)blockIdx.x * blockDim.x + threadIdx.x;
    if (gid >= (long long)BN * SN) return;
    int hw = (int)(gid % HWSZ);
    int c = (int)((gid / HWSZ) % CCH);
    int b = (int)(gid / SN);
    int hh = hw >> 6, ww = hw & 63;
    int t = ((hh >> 1) << 5) + (ww >> 1);
    int j = (c << 2) + ((hh & 1) << 1) + (ww & 1);
    float g = __bfloat162float(ss[((long long)b * SIXC + 1440 + c) * HWSZ + hw]);
    out[gid] = x1[gid] + __bfloat162float(m[((long long)(b * STOK + t)) * DD + j]) * g;
}

// ---------------- launch ----------------
extern "C" void kernel_launch(void* const* d_in, const int* in_sizes, int n_in,
                              void* d_out, int out_size)
{
    const float* x      = (const float*)d_in[0];
    const float* cond   = (const float*)d_in[1];
    const float* gtok   = (const float*)d_in[2];
    const float* ttok   = (const float*)d_in[3];
    const float* ss_w   = (const float*)d_in[4];
    const float* ss_b   = (const float*)d_in[5];
    const float* qkv_w  = (const float*)d_in[6];
    const float* proj_w = (const float*)d_in[7];
    const float* proj_b = (const float*)d_in[8];
    const float* inv_w  = (const float*)d_in[9];
    const float* inv_b  = (const float*)d_in[10];
    const float* dw_w   = (const float*)d_in[11];
    const float* dw_b   = (const float*)d_in[12];
    const float* pw_w   = (const float*)d_in[13];
    float* out = (float*)d_out;

    float *p_x1, *p_psum, *p_psumsq, *p_stats;
    bf16 *p_ss, *p_condT, *p_tok, *p_qkv, *p_attn, *p_aproj, *p_t2, *p_hexp, *p_hglu, *p_m;
    bf16 *p_ssw, *p_qkvw, *p_projw, *p_invw, *p_pww;
    cudaGetSymbolAddress((void**)&p_ss, g_ss);
    cudaGetSymbolAddress((void**)&p_condT, g_condT);
    cudaGetSymbolAddress((void**)&p_tok, g_tok);
    cudaGetSymbolAddress((void**)&p_qkv, g_qkv);
    cudaGetSymbolAddress((void**)&p_attn, g_attn);
    cudaGetSymbolAddress((void**)&p_aproj, g_aproj);
    cudaGetSymbolAddress((void**)&p_x1, g_x1);
    cudaGetSymbolAddress((void**)&p_t2, g_t2);
    cudaGetSymbolAddress((void**)&p_hexp, g_hexp);
    cudaGetSymbolAddress((void**)&p_hglu, g_hglu);
    cudaGetSymbolAddress((void**)&p_m, g_m);
    cudaGetSymbolAddress((void**)&p_psum, g_psum);
    cudaGetSymbolAddress((void**)&p_psumsq, g_psumsq);
    cudaGetSymbolAddress((void**)&p_stats, g_stats);
    cudaGetSymbolAddress((void**)&p_ssw, g_ssw);
    cudaGetSymbolAddress((void**)&p_qkvw, g_qkvw);
    cudaGetSymbolAddress((void**)&p_projw, g_projw);
    cudaGetSymbolAddress((void**)&p_invw, g_invw);
    cudaGetSymbolAddress((void**)&p_pww, g_pww);

    cudaFuncSetAttribute(gemm_nt<1, false, true>, cudaFuncAttributeMaxDynamicSharedMemorySize, GSMEM);
    cudaFuncSetAttribute(gemm_nt<0, false, true>, cudaFuncAttributeMaxDynamicSharedMemorySize, GSMEM);
    cudaFuncSetAttribute(gemm_nt<2, false, true>, cudaFuncAttributeMaxDynamicSharedMemorySize, GSMEM);
    cudaFuncSetAttribute(gemm_nt<2, true, true>,  cudaFuncAttributeMaxDynamicSharedMemorySize, GSMEM);

    // 0) weight conversion + cond silu-transpose
    convw4_k<<<1024, 256>>>(ss_w, p_ssw, (long long)SIXC * SIXC / 4);
    convw4_k<<<1024, 256>>>(qkv_w, p_qkvw, (long long)3 * DD * DD / 4);
    convw4_k<<<1024, 256>>>(proj_w, p_projw, (long long)DD * DD / 4);
    convw4_k<<<2048, 256>>>(inv_w, p_invw, (long long)HF2 * DD / 4);
    convw4_k<<<1024, 256>>>(pw_w, p_pww, (long long)DD * HFF / 4);
    tsil_k<<<dim3(SIXC / 32, HWSZ / 32, BN), dim3(32, 8)>>>(cond, p_condT);

    // 1) scale_shift (bf16 out)
    gemm_nt<1, false, true><<<dim3(HWSZ / 128, 14, BN), 256, GSMEM>>>(
        p_ssw, p_condT, p_ss, ss_b, SIXC, HWSZ, SIXC,
        0LL, (long long)HWSZ * SIXC, (long long)SIXC * HWSZ);

    // 2) LayerNorm(x)
    ln_partial_k<<<dim3(LNB, BN), 256>>>(x, p_psum, p_psumsq);
    ln_final_k<<<BN, 256>>>(p_psum, p_psumsq, p_stats);

    // 3) tokens (bf16)
    tokinit_k<<<(BN * DD + 255) / 256, 256>>>(gtok, ttok, p_tok);
    msa_seg_k<<<(int)(((long long)BN * STOK * DD + 255) / 256), 256>>>(x, p_ss, p_stats, p_tok);

    // 4) qkv (bf16 out)
    gemm_nt<0, false, true><<<dim3((3 * DD) / 128, 33, 1), 256, GSMEM>>>(
        p_tok, p_qkvw, p_qkv, nullptr, BN * SSEQ, 3 * DD, DD, 0LL, 0LL, 0LL);

    // 5) linear attention (bf16 in/out)
    attn_k<<<dim3(NHEADS, BN), 256>>>(p_qkv, p_attn);

    // 6) proj (bf16 out now)
    gemm_nt<2, false, true><<<dim3(DD / 128, 32, 1), 256, GSMEM>>>(
        p_attn, p_projw, p_aproj, proj_b, BN * STOK, DD, DD, 0LL, 0LL, 0LL);

    // 7+8a) x1 = x + comb(a)*g_msa, fused with LN(x1) partials
    comb1_ln_k<<<dim3(LNB, BN), 256>>>(x, p_aproj, p_ss, p_x1, p_psum, p_psumsq);

    // 8b) LN(x1) finalize
    ln_final_k<<<BN, 256>>>(p_psum, p_psumsq, p_stats);

    // 9) MLP modulate+segment (token-major bf16)
    mlp_seg_k<<<(int)(((long long)BN * STOK * DD + 255) / 256), 256>>>(p_x1, p_ss, p_stats, p_t2);

    // 10) expand (bf16 out)
    gemm_nt<2, true, true><<<dim3(HF2 / 128, STOK / 128, BN), 256, GSMEM>>>(
        p_t2, p_invw, p_hexp, inv_b, STOK, HF2, DD,
        (long long)STOK * DD, 0LL, (long long)STOK * HF2);

    // 11) tiled depthwise 3x3 + GLU
    dwglu_t_k<<<dim3(HFF / DW_CH, 8, BN), 256>>>(p_hexp, dw_w, dw_b, p_hglu);

    // 12) project (bf16 out)
    gemm_nt<0, false, true><<<dim3(DD / 128, STOK / 128, BN), 256, GSMEM>>>(
        p_hglu, p_pww, p_m, nullptr, STOK, DD, HFF,
        (long long)STOK * HFF, 0LL, (long long)STOK * DD);

    // 13) comb2
    comb2_k<<<(int)(((long long)BN * SN + 255) / 256), 256>>>(p_x1, p_m, p_ss, out);
}

// round 16
// speedup vs baseline: 1.2107x; 1.0124x over previous
#include <cuda_runtime.h>
#include <cuda_bf16.h>
#include <cstdint>

// ---------------- problem constants ----------------
#define BN     4
#define CCH    288
#define HWSZ   4096
#define SN     (CCH*HWSZ)
#define DD     1152
#define SIXC   1728
#define STOK   1024
#define SSEQ   1026
#define NHEADS 36
#define HFF    4608
#define HF2    9216
#define LNB    144

typedef __nv_bfloat16 bf16;

// ---------------- scratch (static device memory) ----------------
__device__ bf16  g_ss   [BN*SIXC*HWSZ];
__device__ bf16  g_condT[BN*HWSZ*SIXC];
__device__ bf16  g_tok  [BN*SSEQ*DD];
__device__ bf16  g_qkv  [BN*SSEQ*3*DD];
__device__ bf16  g_attn [BN*STOK*DD];
__device__ bf16  g_aproj[BN*STOK*DD];
__device__ float g_x1   [BN*SN];
__device__ bf16  g_t2   [BN*STOK*DD];
__device__ bf16  g_hexp [BN*STOK*HF2];
__device__ bf16  g_hglu [BN*STOK*HFF];
__device__ bf16  g_m    [BN*STOK*DD];
__device__ float g_psum [BN*LNB];
__device__ float g_psumsq[BN*LNB];
__device__ float g_stats[BN*2];
__device__ bf16  g_ssw  [SIXC*SIXC];
__device__ bf16  g_qkvw [3*DD*DD];
__device__ bf16  g_projw[DD*DD];
__device__ bf16  g_invw [HF2*DD];
__device__ bf16  g_pww  [DD*HFF];

__device__ __forceinline__ float siluf(float v) { return v / (1.0f + __expf(-v)); }

__device__ __forceinline__ unsigned pk2(float x, float y) {
    __nv_bfloat162 h = __floats2bfloat162_rn(x, y);
    return *reinterpret_cast<unsigned*>(&h);
}
__device__ __forceinline__ float2 upk2(const bf16* p) {
    return __bfloat1622float2(*reinterpret_cast<const __nv_bfloat162*>(p));
}

// ---------------- common async-copy primitives ----------------
__device__ __forceinline__ void cpasync16(unsigned dst, const void* src, bool valid) {
    int sz = valid ? 16 : 0;
    asm volatile("cp.async.cg.shared.global [%0], [%1], 16, %2;" :: "r"(dst), "l"(src), "r"(sz));
}
__device__ __forceinline__ void cp_commit() { asm volatile("cp.async.commit_group;"); }
template<int N> __device__ __forceinline__ void cp_wait() {
    asm volatile("cp.async.wait_group %0;" :: "n"(N));
}

// ---------------- legacy mma.sync primitives (fallback path) ----------------
__device__ __forceinline__ void ldsm4(unsigned r[4], unsigned addr) {
    asm volatile("ldmatrix.sync.aligned.m8n8.x4.shared.b16 {%0,%1,%2,%3}, [%4];"
                 : "=r"(r[0]), "=r"(r[1]), "=r"(r[2]), "=r"(r[3]) : "r"(addr));
}
__device__ __forceinline__ void mma_bf16(float c[4], const unsigned a[4], unsigned b0, unsigned b1) {
    asm volatile(
        "mma.sync.aligned.m16n8k16.row.col.f32.bf16.bf16.f32 "
        "{%0,%1,%2,%3}, {%4,%5,%6,%7}, {%8,%9}, {%0,%1,%2,%3};"
        : "+f"(c[0]), "+f"(c[1]), "+f"(c[2]), "+f"(c[3])
        : "r"(a[0]), "r"(a[1]), "r"(a[2]), "r"(a[3]), "r"(b0), "r"(b1));
}

// ---------------- tcgen05 primitives (sm_103a-only path; call sites guarded) ----
__device__ __forceinline__ uint32_t elect1() {
    uint32_t pred;
    asm volatile("{\n\t.reg .pred p;\n\telect.sync _|p, 0xFFFFFFFF;\n\tselp.b32 %0, 1, 0, p;\n\t}"
                 : "=r"(pred));
    return pred;
}
__device__ __forceinline__ void mbar_init(uint32_t a, uint32_t cnt) {
    asm volatile("mbarrier.init.shared.b64 [%0], %1;" :: "r"(a), "r"(cnt) : "memory");
}
__device__ __forceinline__ void mbar_inval(uint32_t a) {
    asm volatile("mbarrier.inval.shared.b64 [%0];" :: "r"(a) : "memory");
}
__device__ __forceinline__ void mbar_wait(uint32_t a, uint32_t parity) {
    asm volatile(
        "{\n\t.reg .pred P;\n\t"
        "W%=:\n\t"
        "mbarrier.try_wait.parity.acquire.cta.shared::cta.b64 P, [%0], %1, 0x989680;\n\t"
        "@P bra.uni D%=;\n\t"
        "bra.uni W%=;\n\t"
        "D%=:\n\t}"
        :: "r"(a), "r"(parity) : "memory");
}
__device__ __forceinline__ void t5_alloc(uint32_t dst, uint32_t n) {
    asm volatile("tcgen05.alloc.cta_group::1.sync.aligned.shared::cta.b32 [%0], %1;"
                 :: "r"(dst), "r"(n) : "memory");
}
__device__ __forceinline__ void t5_relinquish() {
    asm volatile("tcgen05.relinquish_alloc_permit.cta_group::1.sync.aligned;");
}
__device__ __forceinline__ void t5_dealloc(uint32_t t, uint32_t n) {
    asm volatile("tcgen05.dealloc.cta_group::1.sync.aligned.b32 %0, %1;" :: "r"(t), "r"(n));
}
__device__ __forceinline__ void t5_commit(uint32_t mbar) {
    asm volatile("tcgen05.commit.cta_group::1.mbarrier::arrive::one.shared::cluster.b64 [%0];"
                 :: "r"(mbar) : "memory");
}
__device__ __forceinline__ void t5_fence_after() {
    asm volatile("tcgen05.fence::after_thread_sync;" ::: "memory");
}
__device__ __forceinline__ void t5_waitld() {
    asm volatile("tcgen05.wait::ld.sync.aligned;" ::: "memory");
}
__device__ __forceinline__ void fence_async_shared() {
    asm volatile("fence.proxy.async.shared::cta;" ::: "memory");
}
__device__ __forceinline__ void t5_mma(uint32_t d, uint64_t ad, uint64_t bd,
                                       uint32_t idesc, bool acc) {
    uint32_t en = acc ? 1u : 0u;
    asm volatile(
        "{\n\t.reg .pred p;\n\tsetp.ne.u32 p, %5, 0;\n\t"
        "tcgen05.mma.cta_group::1.kind::f16 [%0], %1, %2, %3, {%4, %4, %4, %4}, p;\n\t}"
        :: "r"(d), "l"(ad), "l"(bd), "r"(idesc), "r"(0u), "r"(en) : "memory");
}
__device__ __forceinline__ void t5_ld32(uint32_t* r, uint32_t taddr) {
    asm volatile(
        "tcgen05.ld.sync.aligned.32x32b.x32.b32 "
        "{%0,%1,%2,%3,%4,%5,%6,%7,%8,%9,%10,%11,%12,%13,%14,%15,"
        "%16,%17,%18,%19,%20,%21,%22,%23,%24,%25,%26,%27,%28,%29,%30,%31}, [%32];"
        : "=r"(r[0]), "=r"(r[1]), "=r"(r[2]), "=r"(r[3]), "=r"(r[4]), "=r"(r[5]),
          "=r"(r[6]), "=r"(r[7]), "=r"(r[8]), "=r"(r[9]), "=r"(r[10]), "=r"(r[11]),
          "=r"(r[12]), "=r"(r[13]), "=r"(r[14]), "=r"(r[15]), "=r"(r[16]), "=r"(r[17]),
          "=r"(r[18]), "=r"(r[19]), "=r"(r[20]), "=r"(r[21]), "=r"(r[22]), "=r"(r[23]),
          "=r"(r[24]), "=r"(r[25]), "=r"(r[26]), "=r"(r[27]), "=r"(r[28]), "=r"(r[29]),
          "=r"(r[30]), "=r"(r[31])
        : "r"(taddr));
}

// idesc kind::f16: dtype=F32, a=BF16 K-major, b=BF16 K-major, N=128, M=128
static constexpr uint32_t T5_IDESC = (1u << 4) | (1u << 7) | (1u << 10) |
                                     ((128u / 8) << 17) | ((128u / 16) << 24);
// SW128 K-major smem descriptor: layout=2, version=1, SBO=64, LBO=1
static constexpr unsigned long long T5_DESC_BASE =
    (2ull << 61) | (1ull << 46) | (64ull << 32) | (1ull << 16);
__device__ __forceinline__ uint64_t make_desc(uint32_t addr) {
    return T5_DESC_BASE | ((uint64_t)(addr >> 4) & 0x3FFFull);
}

#define GSMEM 100352   // tcgen05: ctrl + 3x32KB; fallback: 4x16KB

// ---------------- unified bf16 NT GEMM: C[M,N] = A[M,K] * B[N,K]^T (R12 frozen) ----
template<int BIASMODE, bool ACT_SILU, bool OUTBF>
__global__ __launch_bounds__(256, 2)
void gemm_nt(const bf16* __restrict__ A, const bf16* __restrict__ B,
             void* __restrict__ Cv, const float* __restrict__ bias,
             int M, int N, int K, long long sA_, long long sB_, long long sC_)
{
    extern __shared__ __align__(16) unsigned char smem[];
    const bf16* Az = A + (long long)blockIdx.z * sA_;
    const bf16* Bz = B + (long long)blockIdx.z * sB_;
    const int tid  = threadIdx.x;
    const int row0 = blockIdx.y * 128;
    const int col0 = blockIdx.x * 128;

#if defined(__CUDA_ARCH__) && defined(__CUDA_ARCH_FEAT_SM103_ALL)
    const unsigned u    = (unsigned)__cvta_generic_to_shared(smem);
    const unsigned ctrl = u;
    const unsigned stg  = (u + 2047u) & ~1023u;
    const int warp = tid >> 5, lane = tid & 31;

    if (warp == 0) { t5_alloc(ctrl, 128); t5_relinquish(); }
    if (tid == 0) { mbar_init(ctrl + 16, 1); mbar_init(ctrl + 24, 1); mbar_init(ctrl + 32, 1); }
    __syncthreads();
    uint32_t tmem;
    asm volatile("ld.shared.b32 %0, [%1];" : "=r"(tmem) : "r"(ctrl));

    const int nk = K >> 6;

    auto copyStage = [&](int it, int st) {
        int k0 = it << 6;
        unsigned sA = stg + (unsigned)st * 32768u;
        unsigned sB = sA + 16384u;
        int c = tid & 7, rb = tid >> 3;
#pragma unroll
        for (int i = 0; i < 4; i++) {
            int r = i * 32 + rb;
            unsigned sw = (unsigned)((c ^ (r & 7)) << 4);
            cpasync16(sA + (unsigned)r * 128u + sw,
                      Az + (long long)(row0 + r) * K + k0 + c * 8, row0 + r < M);
            cpasync16(sB + (unsigned)r * 128u + sw,
                      Bz + (long long)(col0 + r) * K + k0 + c * 8, true);
        }
    };

    copyStage(0, 0); cp_commit();
    if (nk > 1) copyStage(1, 1);
    cp_commit();
    if (nk > 2) copyStage(2, 2);
    cp_commit();

    for (int it = 0; it < nk; it++) {
        int st = it % 3;
        cp_wait<1>();
        fence_async_shared();
        __syncthreads();

        if (tid < 32 && elect1()) {
            t5_fence_after();
            unsigned sA = stg + (unsigned)st * 32768u;
            uint64_t ad = make_desc(sA);
            uint64_t bd = make_desc(sA + 16384u);
#pragma unroll
            for (int sub = 0; sub < 4; sub++)
                t5_mma(tmem, ad + 2 * sub, bd + 2 * sub, T5_IDESC, (it | sub) != 0);
            t5_commit(ctrl + 16 + st * 8);
        }
        int prev = it - 1;
        if (prev >= 0 && it + 2 < nk) {
            int pst = prev % 3;
            mbar_wait(ctrl + 16 + pst * 8, (uint32_t)((prev / 3) & 1));
            copyStage(it + 2, pst);
        }
        cp_commit();
    }
    {
        int lastst = (nk - 1) % 3;
        mbar_wait(ctrl + 16 + lastst * 8, (uint32_t)(((nk - 1) / 3) & 1));
    }
    t5_fence_after();
    cp_wait<0>();
    __syncthreads();

    float* tb = (float*)(smem + (stg - u));      // [128][129]
    if (warp < 4) {
        int rloc = warp * 32 + lane;
        float bm = (BIASMODE == 1 && row0 + rloc < M) ? bias[row0 + rloc] : 0.f;
#pragma unroll
        for (int g = 0; g < 4; g++) {
            uint32_t d[32];
            t5_ld32(d, tmem + g * 32);
            t5_waitld();
#pragma unroll
            for (int c2 = 0; c2 < 32; c2++) {
                float v = __uint_as_float(d[c2]);
                if (BIASMODE == 1) v += bm;
                if (BIASMODE == 2) v += bias[col0 + g * 32 + c2];
                if (ACT_SILU) v = siluf(v);
                tb[rloc * 129 + g * 32 + c2] = v;
            }
        }
    }
    __syncthreads();
    if (OUTBF) {
        bf16* Cz = (bf16*)Cv + (long long)blockIdx.z * sC_;
        int cp2 = (tid & 63) * 2;
        int q = tid >> 6;
        for (int rr = q * 32; rr < q * 32 + 32; rr++) {
            int r = row0 + rr;
            if (r >= M) break;
            float v0 = tb[rr * 129 + cp2];
            float v1 = tb[rr * 129 + cp2 + 1];
            *(unsigned*)(Cz + (long long)r * N + col0 + cp2) = pk2(v0, v1);
        }
    } else {
        float* Cz = (float*)Cv + (long long)blockIdx.z * sC_;
        int colx = tid & 127;
        int half = tid >> 7;
        for (int rr = half * 64; rr < half * 64 + 64; rr++) {
            int r = row0 + rr;
            if (r >= M) break;
            Cz[(long long)r * N + col0 + colx] = tb[rr * 129 + colx];
        }
    }
    __syncthreads();
    if (tid == 0) { mbar_inval(ctrl + 16); mbar_inval(ctrl + 24); mbar_inval(ctrl + 32); }
    __syncthreads();
    if (warp == 0) t5_dealloc(tmem, 128);

#else
    const unsigned sbase = (unsigned)__cvta_generic_to_shared(smem);
    const int lane = tid & 31;
    const int warp = tid >> 5;
    const int wm   = (warp & 3) * 32;
    const int wn   = (warp >> 2) * 64;

    float acc[2][8][4];
#pragma unroll
    for (int i = 0; i < 2; i++)
#pragma unroll
        for (int j = 0; j < 8; j++)
#pragma unroll
            for (int r = 0; r < 4; r++) acc[i][j][r] = 0.f;

    const int nk = K / 32;
    const unsigned STG = 16384u;

    auto copyStage = [&](int kt, int st) {
        int k0 = kt * 32;
        unsigned sA = sbase + (unsigned)st * STG;
        unsigned sB = sA + 8192u;
#pragma unroll
        for (int i = 0; i < 2; i++) {
            int f = tid + (i << 8);
            int row = f >> 2, ch = f & 3;
            unsigned dst = sA + row * 64u + (unsigned)((ch ^ ((row >> 1) & 3)) << 4);
            cpasync16(dst, Az + (long long)(row0 + row) * K + k0 + ch * 8, row0 + row < M);
        }
#pragma unroll
        for (int i = 0; i < 2; i++) {
            int f = tid + (i << 8);
            int n = f >> 2, ch = f & 3;
            unsigned dst = sB + n * 64u + (unsigned)((ch ^ ((n >> 1) & 3)) << 4);
            cpasync16(dst, Bz + (long long)(col0 + n) * K + k0 + ch * 8, true);
        }
    };

    copyStage(0, 0); cp_commit();
    if (nk > 1) copyStage(1, 1);
    cp_commit();
    if (nk > 2) copyStage(2, 2);
    cp_commit();

    for (int kt = 0; kt < nk; kt++) {
        cp_wait<2>();
        __syncthreads();

        int st = kt & 3;
        unsigned sA = sbase + (unsigned)st * STG;
        unsigned sB = sA + 8192u;

#pragma unroll
        for (int kk = 0; kk < 32; kk += 16) {
            unsigned a_fr[2][4];
#pragma unroll
            for (int i = 0; i < 2; i++) {
                int row = wm + 16 * i + (lane & 15);
                int ch  = (kk >> 3) + (lane >> 4);
                ldsm4(a_fr[i], sA + row * 64u + (unsigned)((ch ^ ((row >> 1) & 3)) << 4));
            }
            unsigned b_fr[4][4];
#pragma unroll
            for (int j = 0; j < 4; j++) {
                int row = wn + 16 * j + ((lane >> 4) << 3) + (lane & 7);
                int ch  = (kk >> 3) + ((lane >> 3) & 1);
                ldsm4(b_fr[j], sB + row * 64u + (unsigned)((ch ^ ((row >> 1) & 3)) << 4));
            }
#pragma unroll
            for (int i = 0; i < 2; i++)
#pragma unroll
                for (int j = 0; j < 4; j++) {
                    mma_bf16(acc[i][2 * j],     a_fr[i], b_fr[j][0], b_fr[j][1]);
                    mma_bf16(acc[i][2 * j + 1], a_fr[i], b_fr[j][2], b_fr[j][3]);
                }
        }

        if (kt + 3 < nk) copyStage(kt + 3, (kt + 3) & 3);
        cp_commit();
    }

    const int gid = lane >> 2, tig = lane & 3;
#pragma unroll
    for (int i = 0; i < 2; i++) {
#pragma unroll
        for (int rr = 0; rr < 2; rr++) {
            int r = row0 + wm + i * 16 + gid + rr * 8;
            if (r >= M) continue;
            float bm = (BIASMODE == 1) ? bias[r] : 0.f;
#pragma unroll
            for (int j = 0; j < 8; j++) {
                int cc = col0 + wn + j * 8 + 2 * tig;
                float x0 = acc[i][j][2 * rr + 0];
                float x1 = acc[i][j][2 * rr + 1];
                if (BIASMODE == 1) { x0 += bm; x1 += bm; }
                if (BIASMODE == 2) { x0 += bias[cc]; x1 += bias[cc + 1]; }
                if (ACT_SILU) { x0 = siluf(x0); x1 = siluf(x1); }
                if (OUTBF) {
                    bf16* Cz = (bf16*)Cv + (long long)blockIdx.z * sC_;
                    unsigned p = pk2(x0, x1);
                    *(unsigned*)(Cz + (long long)r * N + cc) = p;
                } else {
                    float* Cz = (float*)Cv + (long long)blockIdx.z * sC_;
                    *(float2*)(Cz + (long long)r * N + cc) = make_float2(x0, x1);
                }
            }
        }
    }
#endif
}

// ---------------- merged weight conversion (5 ranges, one launch) ----------------
__global__ void convw_all_k(const float* __restrict__ s0, bf16* __restrict__ d0, long long n0,
                            const float* __restrict__ s1, bf16* __restrict__ d1, long long n1,
                            const float* __restrict__ s2, bf16* __restrict__ d2, long long n2,
                            const float* __restrict__ s3, bf16* __restrict__ d3, long long n3,
                            const float* __restrict__ s4, bf16* __restrict__ d4, long long n4)
{
    long long tot = n0 + n1 + n2 + n3 + n4;
    long long stride = (long long)gridDim.x * blockDim.x;
    for (long long i = (long long)blockIdx.x * blockDim.x + threadIdx.x; i < tot; i += stride) {
        const float* s; bf16* d; long long off = i;
        if (off < n0) { s = s0; d = d0; }
        else if ((off -= n0) < n1) { s = s1; d = d1; }
        else if ((off -= n1) < n2) { s = s2; d = d2; }
        else if ((off -= n2) < n3) { s = s3; d = d3; }
        else { off -= n3; s = s4; d = d4; }
        float4 v = ((const float4*)s)[off];
        uint2 o;
        o.x = pk2(v.x, v.y);
        o.y = pk2(v.z, v.w);
        ((uint2*)d)[off] = o;
    }
}

// ---------------- silu + transpose ----------------
__global__ void tsil_k(const float* __restrict__ cond, bf16* __restrict__ condT)
{
    __shared__ float t[32][33];
    int b = blockIdx.z;
    int c0 = blockIdx.x * 32, h0 = blockIdx.y * 32;
#pragma unroll
    for (int i = 0; i < 4; i++) {
        int c = c0 + threadIdx.y + i * 8;
        t[threadIdx.y + i * 8][threadIdx.x] =
            cond[((long long)b * SIXC + c) * HWSZ + h0 + threadIdx.x];
    }
    __syncthreads();
#pragma unroll
    for (int i = 0; i < 4; i++) {
        int h = h0 + threadIdx.y + i * 8;
        condT[((long long)b * HWSZ + h) * SIXC + c0 + threadIdx.x] =
            __float2bfloat16(siluf(t[threadIdx.x][threadIdx.y + i * 8]));
    }
}

// ---------------- LayerNorm partial ----------------
__global__ void ln_partial_k(const float* __restrict__ x,
                             float* __restrict__ psum, float* __restrict__ psumsq)
{
    int b = blockIdx.y;
    const float* xb = x + (long long)b * SN;
    const int chunk = SN / LNB;
    int base = blockIdx.x * chunk;
    float s = 0.f, sq = 0.f;
    for (int i = base + threadIdx.x; i < base + chunk; i += 256) {
        float v = xb[i]; s += v; sq += v * v;
    }
    __shared__ float sh1[256], sh2[256];
    sh1[threadIdx.x] = s; sh2[threadIdx.x] = sq;
    __syncthreads();
    for (int o = 128; o > 0; o >>= 1) {
        if (threadIdx.x < o) {
            sh1[threadIdx.x] += sh1[threadIdx.x + o];
            sh2[threadIdx.x] += sh2[threadIdx.x + o];
        }
        __syncthreads();
    }
    if (threadIdx.x == 0) {
        psum[b * LNB + blockIdx.x] = sh1[0];
        psumsq[b * LNB + blockIdx.x] = sh2[0];
    }
}

__global__ void ln_final_k(const float* __restrict__ psum, const float* __restrict__ psumsq,
                           float* __restrict__ stats)
{
    int b = blockIdx.x;
    float s = 0.f, sq = 0.f;
    for (int i = threadIdx.x; i < LNB; i += 256) { s += psum[b * LNB + i]; sq += psumsq[b * LNB + i]; }
    __shared__ float sh1[256], sh2[256];
    sh1[threadIdx.x] = s; sh2[threadIdx.x] = sq;
    __syncthreads();
    for (int o = 128; o > 0; o >>= 1) {
        if (threadIdx.x < o) {
            sh1[threadIdx.x] += sh1[threadIdx.x + o];
            sh2[threadIdx.x] += sh2[threadIdx.x + o];
        }
        __syncthreads();
    }
    if (threadIdx.x == 0) {
        float mu = sh1[0] / (float)SN;
        float var = sh2[0] / (float)SN - mu * mu;
        stats[b * 2 + 0] = mu;
        stats[b * 2 + 1] = rsqrtf(var + 1e-6f);
    }
}

// ---------------- token init ----------------
__global__ void tokinit_k(const float* __restrict__ gt, const float* __restrict__ tt,
                          bf16* __restrict__ tok)
{
    int gid = blockIdx.x * blockDim.x + threadIdx.x;
    if (gid >= BN * DD) return;
    int b = gid / DD, j = gid % DD;
    tok[((long long)b * SSEQ + 0) * DD + j] = __float2bfloat16(gt[b * DD + j]);
    tok[((long long)b * SSEQ + 1) * DD + j] = __float2bfloat16(tt[b * DD + j]);
}

// ---------------- MSA modulate + segment (pair-vectorized) ----------------
__global__ void msa_seg_k(const float* __restrict__ x, const bf16* __restrict__ ss,
                          const float* __restrict__ stats, bf16* __restrict__ tok)
{
    long long gid = (long long)blockIdx.x * blockDim.x + threadIdx.x;
    if (gid >= (long long)BN * STOK * (DD / 2)) return;
    int j2 = (int)(gid % (DD / 2));
    int t  = (int)((gid / (DD / 2)) % STOK);
    int b  = (int)(gid / ((long long)STOK * (DD / 2)));
    int c = j2 >> 1, p1 = j2 & 1;
    int n1 = t >> 5, n2 = t & 31;
    int hw = ((2 * n1 + p1) << 6) + 2 * n2;
    float mu = stats[b * 2], rsig = stats[b * 2 + 1];
    float2 xv = *(const float2*)&x[((long long)b * CCH + c) * HWSZ + hw];
    float2 sc = upk2(&ss[((long long)b * SIXC + 288 + c) * HWSZ + hw]);
    float2 sh = upk2(&ss[((long long)b * SIXC + c) * HWSZ + hw]);
    float v0 = (xv.x - mu) * rsig * (1.f + sc.x) + sh.x;
    float v1 = (xv.y - mu) * rsig * (1.f + sc.y) + sh.y;
    *(unsigned*)&tok[((long long)b * SSEQ + 2 + t) * DD + 2 * j2] = pk2(v0, v1);
}

// ---------------- linear attention (bf16 qkv) ----------------
__global__ void attn_k(const bf16* __restrict__ qkv, bf16* __restrict__ attn)
{
    int h = blockIdx.x, b = blockIdx.y;
    int tid = threadIdx.x;
    __shared__ float vk[33 * 32];
    __shared__ float ks[8][32];
    __shared__ float vs[8][33];
    float acc[5] = {0.f, 0.f, 0.f, 0.f, 0.f};
    const bf16* qkvb = qkv + (long long)b * SSEQ * (3 * DD);

    for (int s0 = 0; s0 < SSEQ; s0 += 8) {
        {
            int si = tid >> 5, d = tid & 31;
            int s = s0 + si;
            ks[si][d] = (s < SSEQ)
                ? fmaxf(__bfloat162float(qkvb[(long long)s * (3 * DD) + DD + h * 32 + d]), 0.f) : 0.f;
        }
        for (int idx = tid; idx < 8 * 33; idx += 256) {
            int si = idx / 33, e = idx % 33;
            int s = s0 + si;
            float vv = 0.f;
            if (s < SSEQ)
                vv = (e < 32) ? __bfloat162float(qkvb[(long long)s * (3 * DD) + 2 * DD + h * 32 + e]) : 1.f;
            vs[si][e] = vv;
        }
        __syncthreads();
#pragma unroll
        for (int si = 0; si < 8; si++) {
#pragma unroll
            for (int r = 0; r < 5; r++) {
                int f = tid + (r << 8);
                if (f < 1056) acc[r] += vs[si][f >> 5] * ks[si][f & 31];
            }
        }
        __syncthreads();
    }
#pragma unroll
    for (int r = 0; r < 5; r++) {
        int f = tid + (r << 8);
        if (f < 1056) vk[f] = acc[r];
    }
    __syncthreads();

    for (int s = tid; s < SSEQ; s += 256) {
        float q[32];
        const __nv_bfloat162* qp2 = reinterpret_cast<const __nv_bfloat162*>(
            qkvb + (long long)s * (3 * DD) + h * 32);
#pragma unroll
        for (int d2 = 0; d2 < 16; d2++) {
            float2 f = __bfloat1622float2(qp2[d2]);
            q[2 * d2]     = fmaxf(f.x, 0.f);
            q[2 * d2 + 1] = fmaxf(f.y, 0.f);
        }
        float den = 0.f;
#pragma unroll
        for (int d = 0; d < 32; d++) den += vk[32 * 32 + d] * q[d];
        float inv = 1.0f / (den + 1e-8f);
        if (s >= 2) {
            bf16* op = attn + ((long long)(b * STOK + s - 2)) * DD + h * 32;
            for (int e = 0; e < 32; e++) {
                float num = 0.f;
#pragma unroll
                for (int d = 0; d < 32; d++) num += vk[e * 32 + d] * q[d];
                op[e] = __float2bfloat16(num * inv);
            }
        }
    }
}

// ---------------- fused comb1 + LN partials (pair-vectorized, a bf16) ----------
__global__ void comb1_ln_k(const float* __restrict__ x, const bf16* __restrict__ a,
                           const bf16* __restrict__ ss, float* __restrict__ x1,
                           float* __restrict__ psum, float* __restrict__ psumsq)
{
    int b = blockIdx.y;
    const int chunk = SN / LNB;   // 8192
    int base = blockIdx.x * chunk;
    float s = 0.f, sq = 0.f;
    for (int i = threadIdx.x; i < chunk / 2; i += 256) {
        int loc = base + 2 * i;
        int hw = loc & (HWSZ - 1);            // even
        int c  = loc >> 12;
        int hh = hw >> 6, ww = hw & 63;       // ww even
        int t = ((hh >> 1) << 5) + (ww >> 1);
        int j = (c << 2) + ((hh & 1) << 1);   // p2 = 0
        float2 g2 = upk2(&ss[((long long)b * SIXC + 576 + c) * HWSZ + hw]);
        float2 a2 = upk2(&a[((long long)(b * STOK + t)) * DD + j]);
        long long gid = (long long)b * SN + loc;
        float2 x2 = *(const float2*)&x[gid];
        float v0 = x2.x + a2.x * g2.x;
        float v1 = x2.y + a2.y * g2.y;
        *(float2*)&x1[gid] = make_float2(v0, v1);
        s += v0 + v1; sq += v0 * v0 + v1 * v1;
    }
    __shared__ float sh1[256], sh2[256];
    sh1[threadIdx.x] = s; sh2[threadIdx.x] = sq;
    __syncthreads();
    for (int o = 128; o > 0; o >>= 1) {
        if (threadIdx.x < o) {
            sh1[threadIdx.x] += sh1[threadIdx.x + o];
            sh2[threadIdx.x] += sh2[threadIdx.x + o];
        }
        __syncthreads();
    }
    if (threadIdx.x == 0) {
        psum[b * LNB + blockIdx.x] = sh1[0];
        psumsq[b * LNB + blockIdx.x] = sh2[0];
    }
}

// ---------------- MLP modulate + segment (pair-vectorized) ----------------
__global__ void mlp_seg_k(const float* __restrict__ x1, const bf16* __restrict__ ss,
                          const float* __restrict__ stats, bf16* __restrict__ t2)
{
    long long gid = (long long)blockIdx.x * blockDim.x + threadIdx.x;
    if (gid >= (long long)BN * STOK * (DD / 2)) return;
    int j2 = (int)(gid % (DD / 2));
    int t  = (int)((gid / (DD / 2)) % STOK);
    int b  = (int)(gid / ((long long)STOK * (DD / 2)));
    int c = j2 >> 1, p1 = j2 & 1;
    int n1 = t >> 5, n2 = t & 31;
    int hw = ((2 * n1 + p1) << 6) + 2 * n2;
    float mu = stats[b * 2], rsig = stats[b * 2 + 1];
    float2 xv = *(const float2*)&x1[((long long)b * CCH + c) * HWSZ + hw];
    float2 sc = upk2(&ss[((long long)b * SIXC + 1152 + c) * HWSZ + hw]);
    float2 sh = upk2(&ss[((long long)b * SIXC + 864 + c) * HWSZ + hw]);
    float v0 = (xv.x - mu) * rsig * (1.f + sc.x) + sh.x;
    float v1 = (xv.y - mu) * rsig * (1.f + sc.y) + sh.y;
    *(unsigned*)&t2[((long long)b * STOK + t) * DD + 2 * j2] = pk2(v0, v1);
}

// ---------------- tiled depthwise 3x3 + GLU (proven R12) ----------------
#define DW_CH 64
__global__ __launch_bounds__(256)
void dwglu_t_k(const bf16* __restrict__ hexp, const float* __restrict__ dw_w,
               const float* __restrict__ dw_b, bf16* __restrict__ hglu)
{
    __shared__ bf16 sm[6][32][2 * DW_CH];
    const int cb = blockIdx.x * DW_CH;
    const int y0 = blockIdx.y * 4;
    const int b  = blockIdx.z;
    const bf16* base = hexp + (long long)b * STOK * HF2;

    for (int idx = threadIdx.x; idx < 6 * 32 * 2; idx += 256) {
        int grp = idx & 1;
        int xx  = (idx >> 1) & 31;
        int yr  = idx >> 6;
        int y   = y0 - 1 + yr;
        uint4* dst = (uint4*)&sm[yr][xx][grp * DW_CH];
        if ((unsigned)y < 32u) {
            const uint4* src = (const uint4*)(base + (long long)((y << 5) + xx) * HF2
                                              + cb + grp * HFF);
#pragma unroll
            for (int q = 0; q < 8; q++) dst[q] = src[q];
        } else {
#pragma unroll
            for (int q = 0; q < 8; q++) dst[q] = make_uint4(0, 0, 0, 0);
        }
    }
    __syncthreads();

    const int chp = threadIdx.x & 31;
    const int ch  = chp * 2;
    float2 wa[9], wg[9];
#pragma unroll
    for (int i = 0; i < 9; i++) {
        wa[i] = make_float2(dw_w[(cb + ch) * 9 + i],      dw_w[(cb + ch + 1) * 9 + i]);
        wg[i] = make_float2(dw_w[(cb + ch + HFF) * 9 + i], dw_w[(cb + ch + 1 + HFF) * 9 + i]);
    }
    float2 ba = make_float2(dw_b[cb + ch], dw_b[cb + ch + 1]);
    float2 bg = make_float2(dw_b[cb + ch + HFF], dw_b[cb + ch + 1 + HFF]);

    for (int pos = threadIdx.x >> 5; pos < 128; pos += 8) {
        int xx = pos & 31, yo = pos >> 5;
        float2 va = ba, vg = bg;
#pragma unroll
        for (int ky = 0; ky < 3; ky++) {
            int yr = yo + ky;
#pragma unroll
            for (int kx = -1; kx <= 1; kx++) {
                int xc = xx + kx;
                if ((unsigned)xc >= 32u) continue;
                int wi = ky * 3 + (kx + 1);
                float2 av = __bfloat1622float2(*(const __nv_bfloat162*)&sm[yr][xc][ch]);
                float2 gv = __bfloat1622float2(*(const __nv_bfloat162*)&sm[yr][xc][ch + DW_CH]);
                va.x += wa[wi].x * av.x; va.y += wa[wi].y * av.y;
                vg.x += wg[wi].x * gv.x; vg.y += wg[wi].y * gv.y;
            }
        }
        int n = ((y0 + yo) << 5) + xx;
        float o0 = va.x * siluf(vg.x);
        float o1 = va.y * siluf(vg.y);
        *(unsigned*)&hglu[((long long)(b * STOK + n)) * HFF + cb + ch] = pk2(o0, o1);
    }
}

// ---------------- comb2 (pair-vectorized, m bf16) ----------------
__global__ void comb2_k(const float* __restrict__ x1, const bf16* __restrict__ m,
                        const bf16* __restrict__ ss, float* __restrict__ out)
{
    long long gid = (long long)blockIdx.x * blockDim.x + threadIdx.x;
    if (gid >= (long long)BN * SN / 2) return;
    long long loc = 2 * gid;
    int hw = (int)(loc & (HWSZ - 1));           // even
    int c  = (int)((loc >> 12) % CCH);
    int b  = (int)(loc / SN);
    int hh = hw >> 6, ww = hw & 63;             // ww even
    int t = ((hh >> 1) << 5) + (ww >> 1);
    int j = (c << 2) + ((hh & 1) << 1);
    float2 g2 = upk2(&ss[((long long)b * SIXC + 1440 + c) * HWSZ + hw]);
    float2 m2 = upk2(&m[((long long)(b * STOK + t)) * DD + j]);
    float2 x2 = *(const float2*)&x1[loc];
    *(float2*)&out[loc] = make_float2(x2.x + m2.x * g2.x, x2.y + m2.y * g2.y);
}

// ---------------- launch ----------------
extern "C" void kernel_launch(void* const* d_in, const int* in_sizes, int n_in,
                              void* d_out, int out_size)
{
    const float* x      = (const float*)d_in[0];
    const float* cond   = (const float*)d_in[1];
    const float* gtok   = (const float*)d_in[2];
    const float* ttok   = (const float*)d_in[3];
    const float* ss_w   = (const float*)d_in[4];
    const float* ss_b   = (const float*)d_in[5];
    const float* qkv_w  = (const float*)d_in[6];
    const float* proj_w = (const float*)d_in[7];
    const float* proj_b = (const float*)d_in[8];
    const float* inv_w  = (const float*)d_in[9];
    const float* inv_b  = (const float*)d_in[10];
    const float* dw_w   = (const float*)d_in[11];
    const float* dw_b   = (const float*)d_in[12];
    const float* pw_w   = (const float*)d_in[13];
    float* out = (float*)d_out;

    float *p_x1, *p_psum, *p_psumsq, *p_stats;
    bf16 *p_ss, *p_condT, *p_tok, *p_qkv, *p_attn, *p_aproj, *p_t2, *p_hexp, *p_hglu, *p_m;
    bf16 *p_ssw, *p_qkvw, *p_projw, *p_invw, *p_pww;
    cudaGetSymbolAddress((void**)&p_ss, g_ss);
    cudaGetSymbolAddress((void**)&p_condT, g_condT);
    cudaGetSymbolAddress((void**)&p_tok, g_tok);
    cudaGetSymbolAddress((void**)&p_qkv, g_qkv);
    cudaGetSymbolAddress((void**)&p_attn, g_attn);
    cudaGetSymbolAddress((void**)&p_aproj, g_aproj);
    cudaGetSymbolAddress((void**)&p_x1, g_x1);
    cudaGetSymbolAddress((void**)&p_t2, g_t2);
    cudaGetSymbolAddress((void**)&p_hexp, g_hexp);
    cudaGetSymbolAddress((void**)&p_hglu, g_hglu);
    cudaGetSymbolAddress((void**)&p_m, g_m);
    cudaGetSymbolAddress((void**)&p_psum, g_psum);
    cudaGetSymbolAddress((void**)&p_psumsq, g_psumsq);
    cudaGetSymbolAddress((void**)&p_stats, g_stats);
    cudaGetSymbolAddress((void**)&p_ssw, g_ssw);
    cudaGetSymbolAddress((void**)&p_qkvw, g_qkvw);
    cudaGetSymbolAddress((void**)&p_projw, g_projw);
    cudaGetSymbolAddress((void**)&p_invw, g_invw);
    cudaGetSymbolAddress((void**)&p_pww, g_pww);

    cudaFuncSetAttribute(gemm_nt<1, false, true>, cudaFuncAttributeMaxDynamicSharedMemorySize, GSMEM);
    cudaFuncSetAttribute(gemm_nt<0, false, true>, cudaFuncAttributeMaxDynamicSharedMemorySize, GSMEM);
    cudaFuncSetAttribute(gemm_nt<2, false, true>, cudaFuncAttributeMaxDynamicSharedMemorySize, GSMEM);
    cudaFuncSetAttribute(gemm_nt<2, true, true>,  cudaFuncAttributeMaxDynamicSharedMemorySize, GSMEM);

    // 0) merged weight conversion + cond silu-transpose
    convw_all_k<<<2048, 256>>>(
        ss_w,  p_ssw,  (long long)SIXC * SIXC / 4,
        qkv_w, p_qkvw, (long long)3 * DD * DD / 4,
        proj_w, p_projw, (long long)DD * DD / 4,
        inv_w, p_invw, (long long)HF2 * DD / 4,
        pw_w,  p_pww,  (long long)DD * HFF / 4);
    tsil_k<<<dim3(SIXC / 32, HWSZ / 32, BN), dim3(32, 8)>>>(cond, p_condT);

    // 1) scale_shift (bf16 out)
    gemm_nt<1, false, true><<<dim3(HWSZ / 128, 14, BN), 256, GSMEM>>>(
        p_ssw, p_condT, p_ss, ss_b, SIXC, HWSZ, SIXC,
        0LL, (long long)HWSZ * SIXC, (long long)SIXC * HWSZ);

    // 2) LayerNorm(x)
    ln_partial_k<<<dim3(LNB, BN), 256>>>(x, p_psum, p_psumsq);
    ln_final_k<<<BN, 256>>>(p_psum, p_psumsq, p_stats);

    // 3) tokens (bf16)
    tokinit_k<<<(BN * DD + 255) / 256, 256>>>(gtok, ttok, p_tok);
    msa_seg_k<<<(int)(((long long)BN * STOK * (DD / 2) + 255) / 256), 256>>>(x, p_ss, p_stats, p_tok);

    // 4) qkv (bf16 out)
    gemm_nt<0, false, true><<<dim3((3 * DD) / 128, 33, 1), 256, GSMEM>>>(
        p_tok, p_qkvw, p_qkv, nullptr, BN * SSEQ, 3 * DD, DD, 0LL, 0LL, 0LL);

    // 5) linear attention (bf16 in/out)
    attn_k<<<dim3(NHEADS, BN), 256>>>(p_qkv, p_attn);

    // 6) proj (bf16 out)
    gemm_nt<2, false, true><<<dim3(DD / 128, 32, 1), 256, GSMEM>>>(
        p_attn, p_projw, p_aproj, proj_b, BN * STOK, DD, DD, 0LL, 0LL, 0LL);

    // 7+8a) x1 = x + comb(a)*g_msa, fused with LN(x1) partials
    comb1_ln_k<<<dim3(LNB, BN), 256>>>(x, p_aproj, p_ss, p_x1, p_psum, p_psumsq);

    // 8b) LN(x1) finalize
    ln_final_k<<<BN, 256>>>(p_psum, p_psumsq, p_stats);

    // 9) MLP modulate+segment (token-major bf16)
    mlp_seg_k<<<(int)(((long long)BN * STOK * (DD / 2) + 255) / 256), 256>>>(p_x1, p_ss, p_stats, p_t2);

    // 10) expand (bf16 out)
    gemm_nt<2, true, true><<<dim3(HF2 / 128, STOK / 128, BN), 256, GSMEM>>>(
        p_t2, p_invw, p_hexp, inv_b, STOK, HF2, DD,
        (long long)STOK * DD, 0LL, (long long)STOK * HF2);

    // 11) tiled depthwise 3x3 + GLU
    dwglu_t_k<<<dim3(HFF / DW_CH, 8, BN), 256>>>(p_hexp, dw_w, dw_b, p_hglu);

    // 12) project (bf16 out)
    gemm_nt<0, false, true><<<dim3(DD / 128, STOK / 128, BN), 256, GSMEM>>>(
        p_hglu, p_pww, p_m, nullptr, STOK, DD, HFF,
        (long long)STOK * HFF, 0LL, (long long)STOK * DD);

    // 13) comb2 (pair-vectorized)
    comb2_k<<<(int)(((long long)BN * SN / 2 + 255) / 256), 256>>>(p_x1, p_m, p_ss, out);
}

// round 17
// speedup vs baseline: 1.2252x; 1.0120x over previous
#include <cuda_runtime.h>
#include <cuda_bf16.h>
#include <cstdint>

// ---------------- problem constants ----------------
#define BN     4
#define CCH    288
#define HWSZ   4096
#define SN     (CCH*HWSZ)
#define DD     1152
#define SIXC   1728
#define STOK   1024
#define SSEQ   1026
#define NHEADS 36
#define HFF    4608
#define HF2    9216
#define LNB    144

typedef __nv_bfloat16 bf16;

// ---------------- scratch (static device memory) ----------------
__device__ bf16  g_ss   [BN*SIXC*HWSZ];
__device__ bf16  g_condT[BN*HWSZ*SIXC];
__device__ bf16  g_tok  [BN*SSEQ*DD];
__device__ bf16  g_qkv  [BN*SSEQ*3*DD];
__device__ bf16  g_attn [BN*STOK*DD];
__device__ bf16  g_aproj[BN*STOK*DD];
__device__ float g_x1   [BN*SN];
__device__ bf16  g_t2   [BN*STOK*DD];
__device__ bf16  g_hexp [BN*STOK*HF2];
__device__ bf16  g_hglu [BN*STOK*HFF];
__device__ bf16  g_m    [BN*STOK*DD];
__device__ float g_psum [BN*LNB];
__device__ float g_psumsq[BN*LNB];
__device__ float g_stats[BN*2];
__device__ bf16  g_ssw  [SIXC*SIXC];
__device__ bf16  g_qkvw [3*DD*DD];
__device__ bf16  g_projw[DD*DD];
__device__ bf16  g_invw [HF2*DD];
__device__ bf16  g_pww  [DD*HFF];

__device__ __forceinline__ float siluf(float v) { return v / (1.0f + __expf(-v)); }

__device__ __forceinline__ unsigned pk2(float x, float y) {
    __nv_bfloat162 h = __floats2bfloat162_rn(x, y);
    return *reinterpret_cast<unsigned*>(&h);
}
__device__ __forceinline__ float2 upk2(const bf16* p) {
    return __bfloat1622float2(*reinterpret_cast<const __nv_bfloat162*>(p));
}

// ---------------- common async-copy primitives ----------------
__device__ __forceinline__ void cpasync16(unsigned dst, const void* src, bool valid) {
    int sz = valid ? 16 : 0;
    asm volatile("cp.async.cg.shared.global [%0], [%1], 16, %2;" :: "r"(dst), "l"(src), "r"(sz));
}
__device__ __forceinline__ void cp_commit() { asm volatile("cp.async.commit_group;"); }
template<int N> __device__ __forceinline__ void cp_wait() {
    asm volatile("cp.async.wait_group %0;" :: "n"(N));
}

// ---------------- legacy mma.sync primitives (fallback path) ----------------
__device__ __forceinline__ void ldsm4(unsigned r[4], unsigned addr) {
    asm volatile("ldmatrix.sync.aligned.m8n8.x4.shared.b16 {%0,%1,%2,%3}, [%4];"
                 : "=r"(r[0]), "=r"(r[1]), "=r"(r[2]), "=r"(r[3]) : "r"(addr));
}
__device__ __forceinline__ void mma_bf16(float c[4], const unsigned a[4], unsigned b0, unsigned b1) {
    asm volatile(
        "mma.sync.aligned.m16n8k16.row.col.f32.bf16.bf16.f32 "
        "{%0,%1,%2,%3}, {%4,%5,%6,%7}, {%8,%9}, {%0,%1,%2,%3};"
        : "+f"(c[0]), "+f"(c[1]), "+f"(c[2]), "+f"(c[3])
        : "r"(a[0]), "r"(a[1]), "r"(a[2]), "r"(a[3]), "r"(b0), "r"(b1));
}

// ---------------- tcgen05 primitives (sm_103a-only path; call sites guarded) ----
__device__ __forceinline__ uint32_t elect1() {
    uint32_t pred;
    asm volatile("{\n\t.reg .pred p;\n\telect.sync _|p, 0xFFFFFFFF;\n\tselp.b32 %0, 1, 0, p;\n\t}"
                 : "=r"(pred));
    return pred;
}
__device__ __forceinline__ void mbar_init(uint32_t a, uint32_t cnt) {
    asm volatile("mbarrier.init.shared.b64 [%0], %1;" :: "r"(a), "r"(cnt) : "memory");
}
__device__ __forceinline__ void mbar_inval(uint32_t a) {
    asm volatile("mbarrier.inval.shared.b64 [%0];" :: "r"(a) : "memory");
}
__device__ __forceinline__ void mbar_wait(uint32_t a, uint32_t parity) {
    asm volatile(
        "{\n\t.reg .pred P;\n\t"
        "W%=:\n\t"
        "mbarrier.try_wait.parity.acquire.cta.shared::cta.b64 P, [%0], %1, 0x989680;\n\t"
        "@P bra.uni D%=;\n\t"
        "bra.uni W%=;\n\t"
        "D%=:\n\t}"
        :: "r"(a), "r"(parity) : "memory");
}
__device__ __forceinline__ void t5_alloc(uint32_t dst, uint32_t n) {
    asm volatile("tcgen05.alloc.cta_group::1.sync.aligned.shared::cta.b32 [%0], %1;"
                 :: "r"(dst), "r"(n) : "memory");
}
__device__ __forceinline__ void t5_relinquish() {
    asm volatile("tcgen05.relinquish_alloc_permit.cta_group::1.sync.aligned;");
}
__device__ __forceinline__ void t5_dealloc(uint32_t t, uint32_t n) {
    asm volatile("tcgen05.dealloc.cta_group::1.sync.aligned.b32 %0, %1;" :: "r"(t), "r"(n));
}
__device__ __forceinline__ void t5_commit(uint32_t mbar) {
    asm volatile("tcgen05.commit.cta_group::1.mbarrier::arrive::one.shared::cluster.b64 [%0];"
                 :: "r"(mbar) : "memory");
}
__device__ __forceinline__ void t5_fence_after() {
    asm volatile("tcgen05.fence::after_thread_sync;" ::: "memory");
}
__device__ __forceinline__ void t5_waitld() {
    asm volatile("tcgen05.wait::ld.sync.aligned;" ::: "memory");
}
__device__ __forceinline__ void fence_async_shared() {
    asm volatile("fence.proxy.async.shared::cta;" ::: "memory");
}
__device__ __forceinline__ void t5_mma(uint32_t d, uint64_t ad, uint64_t bd,
                                       uint32_t idesc, bool acc) {
    uint32_t en = acc ? 1u : 0u;
    asm volatile(
        "{\n\t.reg .pred p;\n\tsetp.ne.u32 p, %5, 0;\n\t"
        "tcgen05.mma.cta_group::1.kind::f16 [%0], %1, %2, %3, {%4, %4, %4, %4}, p;\n\t}"
        :: "r"(d), "l"(ad), "l"(bd), "r"(idesc), "r"(0u), "r"(en) : "memory");
}
__device__ __forceinline__ void t5_ld32(uint32_t* r, uint32_t taddr) {
    asm volatile(
        "tcgen05.ld.sync.aligned.32x32b.x32.b32 "
        "{%0,%1,%2,%3,%4,%5,%6,%7,%8,%9,%10,%11,%12,%13,%14,%15,"
        "%16,%17,%18,%19,%20,%21,%22,%23,%24,%25,%26,%27,%28,%29,%30,%31}, [%32];"
        : "=r"(r[0]), "=r"(r[1]), "=r"(r[2]), "=r"(r[3]), "=r"(r[4]), "=r"(r[5]),
          "=r"(r[6]), "=r"(r[7]), "=r"(r[8]), "=r"(r[9]), "=r"(r[10]), "=r"(r[11]),
          "=r"(r[12]), "=r"(r[13]), "=r"(r[14]), "=r"(r[15]), "=r"(r[16]), "=r"(r[17]),
          "=r"(r[18]), "=r"(r[19]), "=r"(r[20]), "=r"(r[21]), "=r"(r[22]), "=r"(r[23]),
          "=r"(r[24]), "=r"(r[25]), "=r"(r[26]), "=r"(r[27]), "=r"(r[28]), "=r"(r[29]),
          "=r"(r[30]), "=r"(r[31])
        : "r"(taddr));
}

// idesc kind::f16: dtype=F32, a=BF16 K-major, b=BF16 K-major, N=128, M=128
static constexpr uint32_t T5_IDESC = (1u << 4) | (1u << 7) | (1u << 10) |
                                     ((128u / 8) << 17) | ((128u / 16) << 24);
// SW128 K-major smem descriptor: layout=2, version=1, SBO=64, LBO=1
static constexpr unsigned long long T5_DESC_BASE =
    (2ull << 61) | (1ull << 46) | (64ull << 32) | (1ull << 16);
__device__ __forceinline__ uint64_t make_desc(uint32_t addr) {
    return T5_DESC_BASE | ((uint64_t)(addr >> 4) & 0x3FFFull);
}

#define GSMEM 100352   // tcgen05: ctrl + 3x32KB; fallback: 4x16KB

// ---------------- unified bf16 NT GEMM: C[M,N] = A[M,K] * B[N,K]^T (R12 frozen) ----
template<int BIASMODE, bool ACT_SILU, bool OUTBF>
__global__ __launch_bounds__(256, 2)
void gemm_nt(const bf16* __restrict__ A, const bf16* __restrict__ B,
             void* __restrict__ Cv, const float* __restrict__ bias,
             int M, int N, int K, long long sA_, long long sB_, long long sC_)
{
    extern __shared__ __align__(16) unsigned char smem[];
    const bf16* Az = A + (long long)blockIdx.z * sA_;
    const bf16* Bz = B + (long long)blockIdx.z * sB_;
    const int tid  = threadIdx.x;
    const int row0 = blockIdx.y * 128;
    const int col0 = blockIdx.x * 128;

#if defined(__CUDA_ARCH__) && defined(__CUDA_ARCH_FEAT_SM103_ALL)
    const unsigned u    = (unsigned)__cvta_generic_to_shared(smem);
    const unsigned ctrl = u;
    const unsigned stg  = (u + 2047u) & ~1023u;
    const int warp = tid >> 5, lane = tid & 31;

    if (warp == 0) { t5_alloc(ctrl, 128); t5_relinquish(); }
    if (tid == 0) { mbar_init(ctrl + 16, 1); mbar_init(ctrl + 24, 1); mbar_init(ctrl + 32, 1); }
    __syncthreads();
    uint32_t tmem;
    asm volatile("ld.shared.b32 %0, [%1];" : "=r"(tmem) : "r"(ctrl));

    const int nk = K >> 6;

    auto copyStage = [&](int it, int st) {
        int k0 = it << 6;
        unsigned sA = stg + (unsigned)st * 32768u;
        unsigned sB = sA + 16384u;
        int c = tid & 7, rb = tid >> 3;
#pragma unroll
        for (int i = 0; i < 4; i++) {
            int r = i * 32 + rb;
            unsigned sw = (unsigned)((c ^ (r & 7)) << 4);
            cpasync16(sA + (unsigned)r * 128u + sw,
                      Az + (long long)(row0 + r) * K + k0 + c * 8, row0 + r < M);
            cpasync16(sB + (unsigned)r * 128u + sw,
                      Bz + (long long)(col0 + r) * K + k0 + c * 8, true);
        }
    };

    copyStage(0, 0); cp_commit();
    if (nk > 1) copyStage(1, 1);
    cp_commit();
    if (nk > 2) copyStage(2, 2);
    cp_commit();

    for (int it = 0; it < nk; it++) {
        int st = it % 3;
        cp_wait<1>();
        fence_async_shared();
        __syncthreads();

        if (tid < 32 && elect1()) {
            t5_fence_after();
            unsigned sA = stg + (unsigned)st * 32768u;
            uint64_t ad = make_desc(sA);
            uint64_t bd = make_desc(sA + 16384u);
#pragma unroll
            for (int sub = 0; sub < 4; sub++)
                t5_mma(tmem, ad + 2 * sub, bd + 2 * sub, T5_IDESC, (it | sub) != 0);
            t5_commit(ctrl + 16 + st * 8);
        }
        int prev = it - 1;
        if (prev >= 0 && it + 2 < nk) {
            int pst = prev % 3;
            mbar_wait(ctrl + 16 + pst * 8, (uint32_t)((prev / 3) & 1));
            copyStage(it + 2, pst);
        }
        cp_commit();
    }
    {
        int lastst = (nk - 1) % 3;
        mbar_wait(ctrl + 16 + lastst * 8, (uint32_t)(((nk - 1) / 3) & 1));
    }
    t5_fence_after();
    cp_wait<0>();
    __syncthreads();

    float* tb = (float*)(smem + (stg - u));      // [128][129]
    if (warp < 4) {
        int rloc = warp * 32 + lane;
        float bm = (BIASMODE == 1 && row0 + rloc < M) ? bias[row0 + rloc] : 0.f;
#pragma unroll
        for (int g = 0; g < 4; g++) {
            uint32_t d[32];
            t5_ld32(d, tmem + g * 32);
            t5_waitld();
#pragma unroll
            for (int c2 = 0; c2 < 32; c2++) {
                float v = __uint_as_float(d[c2]);
                if (BIASMODE == 1) v += bm;
                if (BIASMODE == 2) v += bias[col0 + g * 32 + c2];
                if (ACT_SILU) v = siluf(v);
                tb[rloc * 129 + g * 32 + c2] = v;
            }
        }
    }
    __syncthreads();
    if (OUTBF) {
        bf16* Cz = (bf16*)Cv + (long long)blockIdx.z * sC_;
        int cp2 = (tid & 63) * 2;
        int q = tid >> 6;
        for (int rr = q * 32; rr < q * 32 + 32; rr++) {
            int r = row0 + rr;
            if (r >= M) break;
            float v0 = tb[rr * 129 + cp2];
            float v1 = tb[rr * 129 + cp2 + 1];
            *(unsigned*)(Cz + (long long)r * N + col0 + cp2) = pk2(v0, v1);
        }
    } else {
        float* Cz = (float*)Cv + (long long)blockIdx.z * sC_;
        int colx = tid & 127;
        int half = tid >> 7;
        for (int rr = half * 64; rr < half * 64 + 64; rr++) {
            int r = row0 + rr;
            if (r >= M) break;
            Cz[(long long)r * N + col0 + colx] = tb[rr * 129 + colx];
        }
    }
    __syncthreads();
    if (tid == 0) { mbar_inval(ctrl + 16); mbar_inval(ctrl + 24); mbar_inval(ctrl + 32); }
    __syncthreads();
    if (warp == 0) t5_dealloc(tmem, 128);

#else
    const unsigned sbase = (unsigned)__cvta_generic_to_shared(smem);
    const int lane = tid & 31;
    const int warp = tid >> 5;
    const int wm   = (warp & 3) * 32;
    const int wn   = (warp >> 2) * 64;

    float acc[2][8][4];
#pragma unroll
    for (int i = 0; i < 2; i++)
#pragma unroll
        for (int j = 0; j < 8; j++)
#pragma unroll
            for (int r = 0; r < 4; r++) acc[i][j][r] = 0.f;

    const int nk = K / 32;
    const unsigned STG = 16384u;

    auto copyStage = [&](int kt, int st) {
        int k0 = kt * 32;
        unsigned sA = sbase + (unsigned)st * STG;
        unsigned sB = sA + 8192u;
#pragma unroll
        for (int i = 0; i < 2; i++) {
            int f = tid + (i << 8);
            int row = f >> 2, ch = f & 3;
            unsigned dst = sA + row * 64u + (unsigned)((ch ^ ((row >> 1) & 3)) << 4);
            cpasync16(dst, Az + (long long)(row0 + row) * K + k0 + ch * 8, row0 + row < M);
        }
#pragma unroll
        for (int i = 0; i < 2; i++) {
            int f = tid + (i << 8);
            int n = f >> 2, ch = f & 3;
            unsigned dst = sB + n * 64u + (unsigned)((ch ^ ((n >> 1) & 3)) << 4);
            cpasync16(dst, Bz + (long long)(col0 + n) * K + k0 + ch * 8, true);
        }
    };

    copyStage(0, 0); cp_commit();
    if (nk > 1) copyStage(1, 1);
    cp_commit();
    if (nk > 2) copyStage(2, 2);
    cp_commit();

    for (int kt = 0; kt < nk; kt++) {
        cp_wait<2>();
        __syncthreads();

        int st = kt & 3;
        unsigned sA = sbase + (unsigned)st * STG;
        unsigned sB = sA + 8192u;

#pragma unroll
        for (int kk = 0; kk < 32; kk += 16) {
            unsigned a_fr[2][4];
#pragma unroll
            for (int i = 0; i < 2; i++) {
                int row = wm + 16 * i + (lane & 15);
                int ch  = (kk >> 3) + (lane >> 4);
                ldsm4(a_fr[i], sA + row * 64u + (unsigned)((ch ^ ((row >> 1) & 3)) << 4));
            }
            unsigned b_fr[4][4];
#pragma unroll
            for (int j = 0; j < 4; j++) {
                int row = wn + 16 * j + ((lane >> 4) << 3) + (lane & 7);
                int ch  = (kk >> 3) + ((lane >> 3) & 1);
                ldsm4(b_fr[j], sB + row * 64u + (unsigned)((ch ^ ((row >> 1) & 3)) << 4));
            }
#pragma unroll
            for (int i = 0; i < 2; i++)
#pragma unroll
                for (int j = 0; j < 4; j++) {
                    mma_bf16(acc[i][2 * j],     a_fr[i], b_fr[j][0], b_fr[j][1]);
                    mma_bf16(acc[i][2 * j + 1], a_fr[i], b_fr[j][2], b_fr[j][3]);
                }
        }

        if (kt + 3 < nk) copyStage(kt + 3, (kt + 3) & 3);
        cp_commit();
    }

    const int gid = lane >> 2, tig = lane & 3;
#pragma unroll
    for (int i = 0; i < 2; i++) {
#pragma unroll
        for (int rr = 0; rr < 2; rr++) {
            int r = row0 + wm + i * 16 + gid + rr * 8;
            if (r >= M) continue;
            float bm = (BIASMODE == 1) ? bias[r] : 0.f;
#pragma unroll
            for (int j = 0; j < 8; j++) {
                int cc = col0 + wn + j * 8 + 2 * tig;
                float x0 = acc[i][j][2 * rr + 0];
                float x1 = acc[i][j][2 * rr + 1];
                if (BIASMODE == 1) { x0 += bm; x1 += bm; }
                if (BIASMODE == 2) { x0 += bias[cc]; x1 += bias[cc + 1]; }
                if (ACT_SILU) { x0 = siluf(x0); x1 = siluf(x1); }
                if (OUTBF) {
                    bf16* Cz = (bf16*)Cv + (long long)blockIdx.z * sC_;
                    unsigned p = pk2(x0, x1);
                    *(unsigned*)(Cz + (long long)r * N + cc) = p;
                } else {
                    float* Cz = (float*)Cv + (long long)blockIdx.z * sC_;
                    *(float2*)(Cz + (long long)r * N + cc) = make_float2(x0, x1);
                }
            }
        }
    }
#endif
}

// ---------------- merged weight conversion (5 ranges, one launch) ----------------
__global__ void convw_all_k(const float* __restrict__ s0, bf16* __restrict__ d0, long long n0,
                            const float* __restrict__ s1, bf16* __restrict__ d1, long long n1,
                            const float* __restrict__ s2, bf16* __restrict__ d2, long long n2,
                            const float* __restrict__ s3, bf16* __restrict__ d3, long long n3,
                            const float* __restrict__ s4, bf16* __restrict__ d4, long long n4)
{
    long long tot = n0 + n1 + n2 + n3 + n4;
    long long stride = (long long)gridDim.x * blockDim.x;
    for (long long i = (long long)blockIdx.x * blockDim.x + threadIdx.x; i < tot; i += stride) {
        const float* s; bf16* d; long long off = i;
        if (off < n0) { s = s0; d = d0; }
        else if ((off -= n0) < n1) { s = s1; d = d1; }
        else if ((off -= n1) < n2) { s = s2; d = d2; }
        else if ((off -= n2) < n3) { s = s3; d = d3; }
        else { off -= n3; s = s4; d = d4; }
        float4 v = ((const float4*)s)[off];
        uint2 o;
        o.x = pk2(v.x, v.y);
        o.y = pk2(v.z, v.w);
        ((uint2*)d)[off] = o;
    }
}

// ---------------- silu + transpose ----------------
__global__ void tsil_k(const float* __restrict__ cond, bf16* __restrict__ condT)
{
    __shared__ float t[32][33];
    int b = blockIdx.z;
    int c0 = blockIdx.x * 32, h0 = blockIdx.y * 32;
#pragma unroll
    for (int i = 0; i < 4; i++) {
        int c = c0 + threadIdx.y + i * 8;
        t[threadIdx.y + i * 8][threadIdx.x] =
            cond[((long long)b * SIXC + c) * HWSZ + h0 + threadIdx.x];
    }
    __syncthreads();
#pragma unroll
    for (int i = 0; i < 4; i++) {
        int h = h0 + threadIdx.y + i * 8;
        condT[((long long)b * HWSZ + h) * SIXC + c0 + threadIdx.x] =
            __float2bfloat16(siluf(t[threadIdx.x][threadIdx.y + i * 8]));
    }
}

// ---------------- LayerNorm partial (float4) ----------------
__global__ void ln_partial_k(const float* __restrict__ x,
                             float* __restrict__ psum, float* __restrict__ psumsq)
{
    int b = blockIdx.y;
    const float4* xb = (const float4*)(x + (long long)b * SN) + blockIdx.x * (SN / LNB / 4);
    float s = 0.f, sq = 0.f;
#pragma unroll 4
    for (int i = threadIdx.x; i < SN / LNB / 4; i += 256) {
        float4 v = xb[i];
        s  += v.x + v.y + v.z + v.w;
        sq += v.x * v.x + v.y * v.y + v.z * v.z + v.w * v.w;
    }
    __shared__ float sh1[256], sh2[256];
    sh1[threadIdx.x] = s; sh2[threadIdx.x] = sq;
    __syncthreads();
    for (int o = 128; o > 0; o >>= 1) {
        if (threadIdx.x < o) {
            sh1[threadIdx.x] += sh1[threadIdx.x + o];
            sh2[threadIdx.x] += sh2[threadIdx.x + o];
        }
        __syncthreads();
    }
    if (threadIdx.x == 0) {
        psum[b * LNB + blockIdx.x] = sh1[0];
        psumsq[b * LNB + blockIdx.x] = sh2[0];
    }
}

__global__ void ln_final_k(const float* __restrict__ psum, const float* __restrict__ psumsq,
                           float* __restrict__ stats)
{
    int b = blockIdx.x;
    float s = 0.f, sq = 0.f;
    for (int i = threadIdx.x; i < LNB; i += 256) { s += psum[b * LNB + i]; sq += psumsq[b * LNB + i]; }
    __shared__ float sh1[256], sh2[256];
    sh1[threadIdx.x] = s; sh2[threadIdx.x] = sq;
    __syncthreads();
    for (int o = 128; o > 0; o >>= 1) {
        if (threadIdx.x < o) {
            sh1[threadIdx.x] += sh1[threadIdx.x + o];
            sh2[threadIdx.x] += sh2[threadIdx.x + o];
        }
        __syncthreads();
    }
    if (threadIdx.x == 0) {
        float mu = sh1[0] / (float)SN;
        float var = sh2[0] / (float)SN - mu * mu;
        stats[b * 2 + 0] = mu;
        stats[b * 2 + 1] = rsqrtf(var + 1e-6f);
    }
}

// ---------------- token init ----------------
__global__ void tokinit_k(const float* __restrict__ gt, const float* __restrict__ tt,
                          bf16* __restrict__ tok)
{
    int gid = blockIdx.x * blockDim.x + threadIdx.x;
    if (gid >= BN * DD) return;
    int b = gid / DD, j = gid % DD;
    tok[((long long)b * SSEQ + 0) * DD + j] = __float2bfloat16(gt[b * DD + j]);
    tok[((long long)b * SSEQ + 1) * DD + j] = __float2bfloat16(tt[b * DD + j]);
}

// ---------------- MSA modulate + segment (pair-vectorized) ----------------
__global__ void msa_seg_k(const float* __restrict__ x, const bf16* __restrict__ ss,
                          const float* __restrict__ stats, bf16* __restrict__ tok)
{
    long long gid = (long long)blockIdx.x * blockDim.x + threadIdx.x;
    if (gid >= (long long)BN * STOK * (DD / 2)) return;
    int j2 = (int)(gid % (DD / 2));
    int t  = (int)((gid / (DD / 2)) % STOK);
    int b  = (int)(gid / ((long long)STOK * (DD / 2)));
    int c = j2 >> 1, p1 = j2 & 1;
    int n1 = t >> 5, n2 = t & 31;
    int hw = ((2 * n1 + p1) << 6) + 2 * n2;
    float mu = stats[b * 2], rsig = stats[b * 2 + 1];
    float2 xv = *(const float2*)&x[((long long)b * CCH + c) * HWSZ + hw];
    float2 sc = upk2(&ss[((long long)b * SIXC + 288 + c) * HWSZ + hw]);
    float2 sh = upk2(&ss[((long long)b * SIXC + c) * HWSZ + hw]);
    float v0 = (xv.x - mu) * rsig * (1.f + sc.x) + sh.x;
    float v1 = (xv.y - mu) * rsig * (1.f + sc.y) + sh.y;
    *(unsigned*)&tok[((long long)b * SSEQ + 2 + t) * DD + 2 * j2] = pk2(v0, v1);
}

// ---------------- linear attention (bf16 qkv) ----------------
__global__ void attn_k(const bf16* __restrict__ qkv, bf16* __restrict__ attn)
{
    int h = blockIdx.x, b = blockIdx.y;
    int tid = threadIdx.x;
    __shared__ float vk[33 * 32];
    __shared__ float ks[8][32];
    __shared__ float vs[8][33];
    float acc[5] = {0.f, 0.f, 0.f, 0.f, 0.f};
    const bf16* qkvb = qkv + (long long)b * SSEQ * (3 * DD);

    for (int s0 = 0; s0 < SSEQ; s0 += 8) {
        {
            int si = tid >> 5, d = tid & 31;
            int s = s0 + si;
            ks[si][d] = (s < SSEQ)
                ? fmaxf(__bfloat162float(qkvb[(long long)s * (3 * DD) + DD + h * 32 + d]), 0.f) : 0.f;
        }
        for (int idx = tid; idx < 8 * 33; idx += 256) {
            int si = idx / 33, e = idx % 33;
            int s = s0 + si;
            float vv = 0.f;
            if (s < SSEQ)
                vv = (e < 32) ? __bfloat162float(qkvb[(long long)s * (3 * DD) + 2 * DD + h * 32 + e]) : 1.f;
            vs[si][e] = vv;
        }
        __syncthreads();
#pragma unroll
        for (int si = 0; si < 8; si++) {
#pragma unroll
            for (int r = 0; r < 5; r++) {
                int f = tid + (r << 8);
                if (f < 1056) acc[r] += vs[si][f >> 5] * ks[si][f & 31];
            }
        }
        __syncthreads();
    }
#pragma unroll
    for (int r = 0; r < 5; r++) {
        int f = tid + (r << 8);
        if (f < 1056) vk[f] = acc[r];
    }
    __syncthreads();

    for (int s = tid; s < SSEQ; s += 256) {
        float q[32];
        const __nv_bfloat162* qp2 = reinterpret_cast<const __nv_bfloat162*>(
            qkvb + (long long)s * (3 * DD) + h * 32);
#pragma unroll
        for (int d2 = 0; d2 < 16; d2++) {
            float2 f = __bfloat1622float2(qp2[d2]);
            q[2 * d2]     = fmaxf(f.x, 0.f);
            q[2 * d2 + 1] = fmaxf(f.y, 0.f);
        }
        float den = 0.f;
#pragma unroll
        for (int d = 0; d < 32; d++) den += vk[32 * 32 + d] * q[d];
        float inv = 1.0f / (den + 1e-8f);
        if (s >= 2) {
            bf16* op = attn + ((long long)(b * STOK + s - 2)) * DD + h * 32;
            for (int e = 0; e < 32; e++) {
                float num = 0.f;
#pragma unroll
                for (int d = 0; d < 32; d++) num += vk[e * 32 + d] * q[d];
                op[e] = __float2bfloat16(num * inv);
            }
        }
    }
}

// ---------------- fused comb1 + LN partials (quad-vectorized, a bf16) ----------
__global__ void comb1_ln_k(const float* __restrict__ x, const bf16* __restrict__ a,
                           const bf16* __restrict__ ss, float* __restrict__ x1,
                           float* __restrict__ psum, float* __restrict__ psumsq)
{
    int b = blockIdx.y;
    const int chunk = SN / LNB;   // 8192
    int base = blockIdx.x * chunk;
    float s = 0.f, sq = 0.f;
    for (int i = threadIdx.x; i < chunk / 4; i += 256) {
        int loc = base + 4 * i;
        int hw = loc & (HWSZ - 1);            // multiple of 4
        int c  = loc >> 12;
        int hh = hw >> 6, ww = hw & 63;       // ww multiple of 4
        int t = ((hh >> 1) << 5) + (ww >> 1); // tokens t, t+1
        int j = (c << 2) + ((hh & 1) << 1);
        long long abase = ((long long)(b * STOK + t)) * DD + j;
        float2 a0 = upk2(&a[abase]);
        float2 a1 = upk2(&a[abase + DD]);
        const bf16* gp = &ss[((long long)b * SIXC + 576 + c) * HWSZ + hw];
        float2 g0 = upk2(gp);
        float2 g1 = upk2(gp + 2);
        long long gid = (long long)b * SN + loc;
        float4 x4 = *(const float4*)&x[gid];
        float v0 = x4.x + a0.x * g0.x;
        float v1 = x4.y + a0.y * g0.y;
        float v2 = x4.z + a1.x * g1.x;
        float v3 = x4.w + a1.y * g1.y;
        *(float4*)&x1[gid] = make_float4(v0, v1, v2, v3);
        s += (v0 + v1) + (v2 + v3);
        sq += (v0 * v0 + v1 * v1) + (v2 * v2 + v3 * v3);
    }
    __shared__ float sh1[256], sh2[256];
    sh1[threadIdx.x] = s; sh2[threadIdx.x] = sq;
    __syncthreads();
    for (int o = 128; o > 0; o >>= 1) {
        if (threadIdx.x < o) {
            sh1[threadIdx.x] += sh1[threadIdx.x + o];
            sh2[threadIdx.x] += sh2[threadIdx.x + o];
        }
        __syncthreads();
    }
    if (threadIdx.x == 0) {
        psum[b * LNB + blockIdx.x] = sh1[0];
        psumsq[b * LNB + blockIdx.x] = sh2[0];
    }
}

// ---------------- MLP modulate + segment (pair-vectorized) ----------------
__global__ void mlp_seg_k(const float* __restrict__ x1, const bf16* __restrict__ ss,
                          const float* __restrict__ stats, bf16* __restrict__ t2)
{
    long long gid = (long long)blockIdx.x * blockDim.x + threadIdx.x;
    if (gid >= (long long)BN * STOK * (DD / 2)) return;
    int j2 = (int)(gid % (DD / 2));
    int t  = (int)((gid / (DD / 2)) % STOK);
    int b  = (int)(gid / ((long long)STOK * (DD / 2)));
    int c = j2 >> 1, p1 = j2 & 1;
    int n1 = t >> 5, n2 = t & 31;
    int hw = ((2 * n1 + p1) << 6) + 2 * n2;
    float mu = stats[b * 2], rsig = stats[b * 2 + 1];
    float2 xv = *(const float2*)&x1[((long long)b * CCH + c) * HWSZ + hw];
    float2 sc = upk2(&ss[((long long)b * SIXC + 1152 + c) * HWSZ + hw]);
    float2 sh = upk2(&ss[((long long)b * SIXC + 864 + c) * HWSZ + hw]);
    float v0 = (xv.x - mu) * rsig * (1.f + sc.x) + sh.x;
    float v1 = (xv.y - mu) * rsig * (1.f + sc.y) + sh.y;
    *(unsigned*)&t2[((long long)b * STOK + t) * DD + 2 * j2] = pk2(v0, v1);
}

// ---------------- tiled depthwise 3x3 + GLU (proven R12) ----------------
#define DW_CH 64
__global__ __launch_bounds__(256)
void dwglu_t_k(const bf16* __restrict__ hexp, const float* __restrict__ dw_w,
               const float* __restrict__ dw_b, bf16* __restrict__ hglu)
{
    __shared__ bf16 sm[6][32][2 * DW_CH];
    const int cb = blockIdx.x * DW_CH;
    const int y0 = blockIdx.y * 4;
    const int b  = blockIdx.z;
    const bf16* base = hexp + (long long)b * STOK * HF2;

    for (int idx = threadIdx.x; idx < 6 * 32 * 2; idx += 256) {
        int grp = idx & 1;
        int xx  = (idx >> 1) & 31;
        int yr  = idx >> 6;
        int y   = y0 - 1 + yr;
        uint4* dst = (uint4*)&sm[yr][xx][grp * DW_CH];
        if ((unsigned)y < 32u) {
            const uint4* src = (const uint4*)(base + (long long)((y << 5) + xx) * HF2
                                              + cb + grp * HFF);
#pragma unroll
            for (int q = 0; q < 8; q++) dst[q] = src[q];
        } else {
#pragma unroll
            for (int q = 0; q < 8; q++) dst[q] = make_uint4(0, 0, 0, 0);
        }
    }
    __syncthreads();

    const int chp = threadIdx.x & 31;
    const int ch  = chp * 2;
    float2 wa[9], wg[9];
#pragma unroll
    for (int i = 0; i < 9; i++) {
        wa[i] = make_float2(dw_w[(cb + ch) * 9 + i],      dw_w[(cb + ch + 1) * 9 + i]);
        wg[i] = make_float2(dw_w[(cb + ch + HFF) * 9 + i], dw_w[(cb + ch + 1 + HFF) * 9 + i]);
    }
    float2 ba = make_float2(dw_b[cb + ch], dw_b[cb + ch + 1]);
    float2 bg = make_float2(dw_b[cb + ch + HFF], dw_b[cb + ch + 1 + HFF]);

    for (int pos = threadIdx.x >> 5; pos < 128; pos += 8) {
        int xx = pos & 31, yo = pos >> 5;
        float2 va = ba, vg = bg;
#pragma unroll
        for (int ky = 0; ky < 3; ky++) {
            int yr = yo + ky;
#pragma unroll
            for (int kx = -1; kx <= 1; kx++) {
                int xc = xx + kx;
                if ((unsigned)xc >= 32u) continue;
                int wi = ky * 3 + (kx + 1);
                float2 av = __bfloat1622float2(*(const __nv_bfloat162*)&sm[yr][xc][ch]);
                float2 gv = __bfloat1622float2(*(const __nv_bfloat162*)&sm[yr][xc][ch + DW_CH]);
                va.x += wa[wi].x * av.x; va.y += wa[wi].y * av.y;
                vg.x += wg[wi].x * gv.x; vg.y += wg[wi].y * gv.y;
            }
        }
        int n = ((y0 + yo) << 5) + xx;
        float o0 = va.x * siluf(vg.x);
        float o1 = va.y * siluf(vg.y);
        *(unsigned*)&hglu[((long long)(b * STOK + n)) * HFF + cb + ch] = pk2(o0, o1);
    }
}

// ---------------- comb2 (quad-vectorized, m bf16) ----------------
__global__ void comb2_k(const float* __restrict__ x1, const bf16* __restrict__ m,
                        const bf16* __restrict__ ss, float* __restrict__ out)
{
    long long gid = (long long)blockIdx.x * blockDim.x + threadIdx.x;
    if (gid >= (long long)BN * SN / 4) return;
    long long loc = 4 * gid;
    int hw = (int)(loc & (HWSZ - 1));           // multiple of 4
    int c  = (int)((loc >> 12) % CCH);
    int b  = (int)(loc / SN);
    int hh = hw >> 6, ww = hw & 63;             // ww multiple of 4
    int t = ((hh >> 1) << 5) + (ww >> 1);       // tokens t, t+1
    int j = (c << 2) + ((hh & 1) << 1);
    long long mbase = ((long long)(b * STOK + t)) * DD + j;
    float2 m0 = upk2(&m[mbase]);
    float2 m1 = upk2(&m[mbase + DD]);
    const bf16* gp = &ss[((long long)b * SIXC + 1440 + c) * HWSZ + hw];
    float2 g0 = upk2(gp);
    float2 g1 = upk2(gp + 2);
    float4 x4 = *(const float4*)&x1[loc];
    *(float4*)&out[loc] = make_float4(x4.x + m0.x * g0.x, x4.y + m0.y * g0.y,
                                      x4.z + m1.x * g1.x, x4.w + m1.y * g1.y);
}

// ---------------- launch ----------------
extern "C" void kernel_launch(void* const* d_in, const int* in_sizes, int n_in,
                              void* d_out, int out_size)
{
    const float* x      = (const float*)d_in[0];
    const float* cond   = (const float*)d_in[1];
    const float* gtok   = (const float*)d_in[2];
    const float* ttok   = (const float*)d_in[3];
    const float* ss_w   = (const float*)d_in[4];
    const float* ss_b   = (const float*)d_in[5];
    const float* qkv_w  = (const float*)d_in[6];
    const float* proj_w = (const float*)d_in[7];
    const float* proj_b = (const float*)d_in[8];
    const float* inv_w  = (const float*)d_in[9];
    const float* inv_b  = (const float*)d_in[10];
    const float* dw_w   = (const float*)d_in[11];
    const float* dw_b   = (const float*)d_in[12];
    const float* pw_w   = (const float*)d_in[13];
    float* out = (float*)d_out;

    float *p_x1, *p_psum, *p_psumsq, *p_stats;
    bf16 *p_ss, *p_condT, *p_tok, *p_qkv, *p_attn, *p_aproj, *p_t2, *p_hexp, *p_hglu, *p_m;
    bf16 *p_ssw, *p_qkvw, *p_projw, *p_invw, *p_pww;
    cudaGetSymbolAddress((void**)&p_ss, g_ss);
    cudaGetSymbolAddress((void**)&p_condT, g_condT);
    cudaGetSymbolAddress((void**)&p_tok, g_tok);
    cudaGetSymbolAddress((void**)&p_qkv, g_qkv);
    cudaGetSymbolAddress((void**)&p_attn, g_attn);
    cudaGetSymbolAddress((void**)&p_aproj, g_aproj);
    cudaGetSymbolAddress((void**)&p_x1, g_x1);
    cudaGetSymbolAddress((void**)&p_t2, g_t2);
    cudaGetSymbolAddress((void**)&p_hexp, g_hexp);
    cudaGetSymbolAddress((void**)&p_hglu, g_hglu);
    cudaGetSymbolAddress((void**)&p_m, g_m);
    cudaGetSymbolAddress((void**)&p_psum, g_psum);
    cudaGetSymbolAddress((void**)&p_psumsq, g_psumsq);
    cudaGetSymbolAddress((void**)&p_stats, g_stats);
    cudaGetSymbolAddress((void**)&p_ssw, g_ssw);
    cudaGetSymbolAddress((void**)&p_qkvw, g_qkvw);
    cudaGetSymbolAddress((void**)&p_projw, g_projw);
    cudaGetSymbolAddress((void**)&p_invw, g_invw);
    cudaGetSymbolAddress((void**)&p_pww, g_pww);

    cudaFuncSetAttribute(gemm_nt<1, false, true>, cudaFuncAttributeMaxDynamicSharedMemorySize, GSMEM);
    cudaFuncSetAttribute(gemm_nt<0, false, true>, cudaFuncAttributeMaxDynamicSharedMemorySize, GSMEM);
    cudaFuncSetAttribute(gemm_nt<2, false, true>, cudaFuncAttributeMaxDynamicSharedMemorySize, GSMEM);
    cudaFuncSetAttribute(gemm_nt<2, true, true>,  cudaFuncAttributeMaxDynamicSharedMemorySize, GSMEM);

    // 0) merged weight conversion + cond silu-transpose
    convw_all_k<<<2048, 256>>>(
        ss_w,  p_ssw,  (long long)SIXC * SIXC / 4,
        qkv_w, p_qkvw, (long long)3 * DD * DD / 4,
        proj_w, p_projw, (long long)DD * DD / 4,
        inv_w, p_invw, (long long)HF2 * DD / 4,
        pw_w,  p_pww,  (long long)DD * HFF / 4);
    tsil_k<<<dim3(SIXC / 32, HWSZ / 32, BN), dim3(32, 8)>>>(cond, p_condT);

    // 1) scale_shift (bf16 out)
    gemm_nt<1, false, true><<<dim3(HWSZ / 128, 14, BN), 256, GSMEM>>>(
        p_ssw, p_condT, p_ss, ss_b, SIXC, HWSZ, SIXC,
        0LL, (long long)HWSZ * SIXC, (long long)SIXC * HWSZ);

    // 2) LayerNorm(x)
    ln_partial_k<<<dim3(LNB, BN), 256>>>(x, p_psum, p_psumsq);
    ln_final_k<<<BN, 256>>>(p_psum, p_psumsq, p_stats);

    // 3) tokens (bf16)
    tokinit_k<<<(BN * DD + 255) / 256, 256>>>(gtok, ttok, p_tok);
    msa_seg_k<<<(int)(((long long)BN * STOK * (DD / 2) + 255) / 256), 256>>>(x, p_ss, p_stats, p_tok);

    // 4) qkv (bf16 out)
    gemm_nt<0, false, true><<<dim3((3 * DD) / 128, 33, 1), 256, GSMEM>>>(
        p_tok, p_qkvw, p_qkv, nullptr, BN * SSEQ, 3 * DD, DD, 0LL, 0LL, 0LL);

    // 5) linear attention (bf16 in/out)
    attn_k<<<dim3(NHEADS, BN), 256>>>(p_qkv, p_attn);

    // 6) proj (bf16 out)
    gemm_nt<2, false, true><<<dim3(DD / 128, 32, 1), 256, GSMEM>>>(
        p_attn, p_projw, p_aproj, proj_b, BN * STOK, DD, DD, 0LL, 0LL, 0LL);

    // 7+8a) x1 = x + comb(a)*g_msa, fused with LN(x1) partials (quad)
    comb1_ln_k<<<dim3(LNB, BN), 256>>>(x, p_aproj, p_ss, p_x1, p_psum, p_psumsq);

    // 8b) LN(x1) finalize
    ln_final_k<<<BN, 256>>>(p_psum, p_psumsq, p_stats);

    // 9) MLP modulate+segment (token-major bf16)
    mlp_seg_k<<<(int)(((long long)BN * STOK * (DD / 2) + 255) / 256), 256>>>(p_x1, p_ss, p_stats, p_t2);

    // 10) expand (bf16 out)
    gemm_nt<2, true, true><<<dim3(HF2 / 128, STOK / 128, BN), 256, GSMEM>>>(
        p_t2, p_invw, p_hexp, inv_b, STOK, HF2, DD,
        (long long)STOK * DD, 0LL, (long long)STOK * HF2);

    // 11) tiled depthwise 3x3 + GLU
    dwglu_t_k<<<dim3(HFF / DW_CH, 8, BN), 256>>>(p_hexp, dw_w, dw_b, p_hglu);

    // 12) project (bf16 out)
    gemm_nt<0, false, true><<<dim3(DD / 128, STOK / 128, BN), 256, GSMEM>>>(
        p_hglu, p_pww, p_m, nullptr, STOK, DD, HFF,
        (long long)STOK * HFF, 0LL, (long long)STOK * DD);

    // 13) comb2 (quad-vectorized)
    comb2_k<<<(int)(((long long)BN * SN / 4 + 255) / 256), 256>>>(p_x1, p_m, p_ss, out);
}